// round 1
// baseline (speedup 1.0000x reference)
#include <cuda_runtime.h>
#include <math.h>

// Problem constants
#define BSZ   8
#define DIMC  512
#define NTOK  1024      // 32*32 tokens
#define NH    8
#define KD    64
#define VD    64
#define CQKV  640       // 512 Q cols + 64 K + 64 V
#define DOUT  512

// Scratch (static device globals — no allocation in kernel_launch)
__device__ float g_Wc[CQKV * DIMC];            // packed QKV weights  [c][d]
__device__ float g_Q [BSZ * NTOK * 512];       // [b][n][h*64+k]
__device__ float g_K [BSZ * NTOK * 64];        // [b][m][k]
__device__ float g_V [BSZ * NTOK * 64];        // [b][m][v]
__device__ float g_O [BSZ * NTOK * 512];       // [b][n][h*64+v]

// ---------------------------------------------------------------------------
// Kernel 0: pack query_proj / key_proj^T / value_proj^T into one [640][512]
// ---------------------------------------------------------------------------
__global__ void prep_weights(const float* __restrict__ qp,
                             const float* __restrict__ kp,
                             const float* __restrict__ vp) {
    int idx = blockIdx.x * blockDim.x + threadIdx.x;
    if (idx >= CQKV * DIMC) return;
    int c = idx >> 9;         // /512
    int d = idx & 511;
    float w;
    if (c < 512)      w = qp[idx];                    // query_proj[h][k][d] == [c][d]
    else if (c < 576) w = kp[d * 64 + (c - 512)];     // key_proj[d][k] transposed
    else              w = vp[d * 64 + (c - 576)];     // value_proj[d][v] transposed
    g_Wc[idx] = w;
}

// ---------------------------------------------------------------------------
// Kernel 1: fused QKV projection.  Y[b][n][c] = sum_d x[b][d][n] * Wc[c][d]
// Block: 64 n x 64 c tile, 256 threads, 4x4 micro-tile.
// ---------------------------------------------------------------------------
__global__ void __launch_bounds__(256)
qkv_kernel(const float* __restrict__ x) {
    __shared__ float As[16][64];   // [dd][nn]   (x tile)
    __shared__ float Ws[64][17];   // [cc][dd]   (weight tile, padded)

    const int b  = blockIdx.z;
    const int c0 = blockIdx.y * 64;
    const int n0 = blockIdx.x * 64;
    const int tid = threadIdx.x;
    const int tx = tid & 15, ty = tid >> 4;

    const float* xb = x + (size_t)b * DIMC * NTOK;

    float acc[4][4] = {};

    for (int d0 = 0; d0 < DIMC; d0 += 16) {
        #pragma unroll
        for (int r = 0; r < 4; r++) {
            int idx = tid + r * 256;
            int dd = idx >> 6, nn = idx & 63;
            As[dd][nn] = xb[(size_t)(d0 + dd) * NTOK + n0 + nn];
        }
        #pragma unroll
        for (int r = 0; r < 4; r++) {
            int idx = tid + r * 256;
            int dd = idx & 15, cc = idx >> 4;
            Ws[cc][dd] = g_Wc[(size_t)(c0 + cc) * DIMC + d0 + dd];
        }
        __syncthreads();

        #pragma unroll
        for (int dd = 0; dd < 16; dd++) {
            float a[4], w[4];
            #pragma unroll
            for (int i = 0; i < 4; i++) a[i] = As[dd][ty * 4 + i];
            #pragma unroll
            for (int j = 0; j < 4; j++) w[j] = Ws[tx * 4 + j][dd];
            #pragma unroll
            for (int i = 0; i < 4; i++)
                #pragma unroll
                for (int j = 0; j < 4; j++)
                    acc[i][j] += a[i] * w[j];
        }
        __syncthreads();
    }

    #pragma unroll
    for (int i = 0; i < 4; i++) {
        int n = n0 + ty * 4 + i;
        #pragma unroll
        for (int j = 0; j < 4; j++) {
            int c = c0 + tx * 4 + j;
            float v = acc[i][j];
            if (c < 512)
                g_Q[((size_t)b * NTOK + n) * 512 + c] = v;
            else if (c < 576)
                g_K[((size_t)b * NTOK + n) * 64 + (c - 512)] = v;
            else
                g_V[((size_t)b * NTOK + n) * 64 + (c - 576)] = v;
        }
    }
}

// ---------------------------------------------------------------------------
// Kernel 2: flash-style attention per (b, h, 64-row q-tile).
// BLOCK_M = 64 query rows, BLOCK_N = 32 kv cols per iteration.
// Threads (16x16): S micro-tile 4 rows x 2 cols, O micro-tile 4x4.
// Row reductions across the 16 tx lanes via shfl_xor (stays in-warp).
// ---------------------------------------------------------------------------
__global__ void __launch_bounds__(256)
attn_kernel() {
    __shared__ float Qs[64][64];   // [n][k]
    __shared__ float Ks[32][65];   // [m][k] padded
    __shared__ float Ps[64][33];   // [n][m] padded
    __shared__ float Vs[32][64];   // [m][v]

    const int b  = blockIdx.z;
    const int h  = blockIdx.y;
    const int n0 = blockIdx.x * 64;
    const int tid = threadIdx.x;
    const int tx = tid & 15, ty = tid >> 4;
    const float scale = 0.125f;   // 64^-0.5

    const float* Qg = g_Q + ((size_t)b * NTOK + n0) * 512 + h * 64;
    #pragma unroll
    for (int r = 0; r < 16; r++) {
        int idx = tid + r * 256;
        int n = idx >> 6, k = idx & 63;
        Qs[n][k] = Qg[(size_t)n * 512 + k];
    }

    float m_i[4], l_i[4], acc[4][4];
    #pragma unroll
    for (int i = 0; i < 4; i++) {
        m_i[i] = -1e30f; l_i[i] = 0.f;
        #pragma unroll
        for (int j = 0; j < 4; j++) acc[i][j] = 0.f;
    }

    const float* Kg = g_K + (size_t)b * NTOK * 64;
    const float* Vg = g_V + (size_t)b * NTOK * 64;

    for (int m0 = 0; m0 < NTOK; m0 += 32) {
        __syncthreads();   // prev-iter Ps/Vs reads done; Qs visible 1st iter
        #pragma unroll
        for (int r = 0; r < 8; r++) {
            int idx = tid + r * 256;
            int m = idx >> 6, k = idx & 63;
            Ks[m][k] = Kg[(size_t)(m0 + m) * 64 + k];
            Vs[m][k] = Vg[(size_t)(m0 + m) * 64 + k];
        }
        __syncthreads();

        // S tile: rows ty*4+i, cols tx*2+j
        float s[4][2] = {};
        #pragma unroll
        for (int k = 0; k < 64; k++) {
            float q[4], kk[2];
            #pragma unroll
            for (int i = 0; i < 4; i++) q[i] = Qs[ty * 4 + i][k];
            #pragma unroll
            for (int j = 0; j < 2; j++) kk[j] = Ks[tx * 2 + j][k];
            #pragma unroll
            for (int i = 0; i < 4; i++) {
                s[i][0] += q[i] * kk[0];
                s[i][1] += q[i] * kk[1];
            }
        }

        // online softmax per row (width-16 shuffle reductions)
        #pragma unroll
        for (int i = 0; i < 4; i++) {
            float s0 = s[i][0] * scale, s1 = s[i][1] * scale;
            float rmax = fmaxf(s0, s1);
            rmax = fmaxf(rmax, __shfl_xor_sync(0xffffffffu, rmax, 1));
            rmax = fmaxf(rmax, __shfl_xor_sync(0xffffffffu, rmax, 2));
            rmax = fmaxf(rmax, __shfl_xor_sync(0xffffffffu, rmax, 4));
            rmax = fmaxf(rmax, __shfl_xor_sync(0xffffffffu, rmax, 8));
            float mnew = fmaxf(m_i[i], rmax);
            float corr = __expf(m_i[i] - mnew);
            float p0 = __expf(s0 - mnew);
            float p1 = __expf(s1 - mnew);
            Ps[ty * 4 + i][tx * 2 + 0] = p0;
            Ps[ty * 4 + i][tx * 2 + 1] = p1;
            float rs = p0 + p1;
            rs += __shfl_xor_sync(0xffffffffu, rs, 1);
            rs += __shfl_xor_sync(0xffffffffu, rs, 2);
            rs += __shfl_xor_sync(0xffffffffu, rs, 4);
            rs += __shfl_xor_sync(0xffffffffu, rs, 8);
            l_i[i] = l_i[i] * corr + rs;
            m_i[i] = mnew;
            #pragma unroll
            for (int j = 0; j < 4; j++) acc[i][j] *= corr;
        }
        __syncthreads();   // Ps visible to all

        // O += P @ V : rows ty*4+i, cols tx*4+j
        #pragma unroll
        for (int m = 0; m < 32; m++) {
            float p[4], v[4];
            #pragma unroll
            for (int i = 0; i < 4; i++) p[i] = Ps[ty * 4 + i][m];
            #pragma unroll
            for (int j = 0; j < 4; j++) v[j] = Vs[m][tx * 4 + j];
            #pragma unroll
            for (int i = 0; i < 4; i++)
                #pragma unroll
                for (int j = 0; j < 4; j++)
                    acc[i][j] += p[i] * v[j];
        }
    }

    float* Og = g_O + ((size_t)b * NTOK + n0) * 512 + h * 64;
    #pragma unroll
    for (int i = 0; i < 4; i++) {
        float inv = 1.0f / l_i[i];
        #pragma unroll
        for (int j = 0; j < 4; j++)
            Og[(size_t)(ty * 4 + i) * 512 + tx * 4 + j] = acc[i][j] * inv;
    }
}

// ---------------------------------------------------------------------------
// Kernel 3: output projection.
// R[b][dout][n] = sum_c O[b][n][c] * Wout[dout][c]   (c = h*64+v, C = 512)
// ---------------------------------------------------------------------------
__global__ void __launch_bounds__(256)
outproj_kernel(const float* __restrict__ wout, float* __restrict__ out) {
    __shared__ float Os [64][17];   // [nn][cc]
    __shared__ float Wts[64][17];   // [dout][cc]

    const int b  = blockIdx.z;
    const int d0 = blockIdx.y * 64;
    const int n0 = blockIdx.x * 64;
    const int tid = threadIdx.x;
    const int tx = tid & 15, ty = tid >> 4;

    const float* Ob = g_O + ((size_t)b * NTOK + n0) * 512;

    float acc[4][4] = {};

    for (int c0 = 0; c0 < 512; c0 += 16) {
        #pragma unroll
        for (int r = 0; r < 4; r++) {
            int idx = tid + r * 256;
            int cc = idx & 15, rr = idx >> 4;
            Os [rr][cc] = Ob[(size_t)rr * 512 + c0 + cc];
            Wts[rr][cc] = wout[(size_t)(d0 + rr) * 512 + c0 + cc];
        }
        __syncthreads();

        #pragma unroll
        for (int cc = 0; cc < 16; cc++) {
            float w[4], o[4];
            #pragma unroll
            for (int i = 0; i < 4; i++) w[i] = Wts[ty * 4 + i][cc];
            #pragma unroll
            for (int j = 0; j < 4; j++) o[j] = Os[tx * 4 + j][cc];
            #pragma unroll
            for (int i = 0; i < 4; i++)
                #pragma unroll
                for (int j = 0; j < 4; j++)
                    acc[i][j] += w[i] * o[j];
        }
        __syncthreads();
    }

    #pragma unroll
    for (int i = 0; i < 4; i++) {
        int dout = d0 + ty * 4 + i;
        #pragma unroll
        for (int j = 0; j < 4; j++) {
            int n = n0 + tx * 4 + j;
            out[((size_t)b * DOUT + dout) * NTOK + n] = acc[i][j];
        }
    }
}

// ---------------------------------------------------------------------------
extern "C" void kernel_launch(void* const* d_in, const int* in_sizes, int n_in,
                              void* d_out, int out_size) {
    const float* x    = (const float*)d_in[0];  // [8,512,32,32]
    const float* qp   = (const float*)d_in[1];  // [8,64,512]
    const float* kp   = (const float*)d_in[2];  // [512,64]
    const float* vp   = (const float*)d_in[3];  // [512,64]
    const float* wout = (const float*)d_in[4];  // [512,8,64]
    float* out = (float*)d_out;                 // [8,512,32,32]

    // 0) pack weights
    prep_weights<<<(CQKV * DIMC + 255) / 256, 256>>>(qp, kp, vp);

    // 1) fused QKV projection: grid (n-tiles, c-tiles, batch)
    {
        dim3 grid(NTOK / 64, CQKV / 64, BSZ);
        qkv_kernel<<<grid, 256>>>(x);
    }

    // 2) attention: grid (q-tiles, heads, batch)
    {
        dim3 grid(NTOK / 64, NH, BSZ);
        attn_kernel<<<grid, 256>>>();
    }

    // 3) output projection: grid (n-tiles, dout-tiles, batch)
    {
        dim3 grid(NTOK / 64, DOUT / 64, BSZ);
        outproj_kernel<<<grid, 256>>>(wout, out);
    }
}

// round 2
// speedup vs baseline: 1.2290x; 1.2290x over previous
#include <cuda_runtime.h>
#include <math.h>

#define BSZ   8
#define NTOK  1024
#define NH    8

// Intermediates (static device scratch; layouts chosen for coalesced float4)
__device__ float g_Wqkv  [512 * 640];     // [d][c]  (pre-transposed packed weights)
__device__ float g_WoutT [512 * 512];     // [c][dout]
__device__ float g_Q [BSZ * 512 * NTOK];  // [b][h*64+k][n]
__device__ float g_K [BSZ *  64 * NTOK];  // [b][k][m]
__device__ float g_V [BSZ *  64 * NTOK];  // [b][v][m]
__device__ float g_O [BSZ * 512 * NTOK];  // [b][h*64+v][n]

// ---------------------------------------------------------------------------
// prep: pack + transpose weights (tiny)
// ---------------------------------------------------------------------------
__global__ void prep_qkv(const float* __restrict__ qp,
                         const float* __restrict__ kp,
                         const float* __restrict__ vp) {
    int idx = blockIdx.x * 256 + threadIdx.x;
    if (idx >= 512 * 640) return;
    int d = idx / 640, c = idx % 640;
    float w;
    if (c < 512)      w = qp[c * 512 + d];          // qp[h][k][d] -> [c][d]
    else if (c < 576) w = kp[d * 64 + (c - 512)];   // kp[d][k]
    else              w = vp[d * 64 + (c - 576)];   // vp[d][v]
    g_Wqkv[idx] = w;
}

__global__ void prep_out(const float* __restrict__ wout) {
    int idx = blockIdx.x * 256 + threadIdx.x;
    if (idx >= 512 * 512) return;
    int c = idx / 512, dout = idx % 512;
    g_WoutT[idx] = wout[dout * 512 + c];            // wout[dout][c]
}

// ---------------------------------------------------------------------------
// qkv: Y[c][n] = sum_d Wqkv[d][c] * x[d][n]   (per batch)
// 128x128 tile, 256 threads, 8x8 micro (split 64+64), float4 everywhere.
// ---------------------------------------------------------------------------
__global__ void __launch_bounds__(256)
qkv_v2(const float* __restrict__ x) {
    __shared__ float Wsm[16][128];
    __shared__ float Xsm[16][128];

    const int b  = blockIdx.z;
    const int c0 = blockIdx.y * 128;
    const int n0 = blockIdx.x * 128;
    const int tid = threadIdx.x;
    const int tx = tid & 15, ty = tid >> 4;

    const float* xb = x + (size_t)b * 512 * 1024;

    float acc[8][8] = {};

    for (int d0 = 0; d0 < 512; d0 += 16) {
        #pragma unroll
        for (int q = 0; q < 2; q++) {
            int fi = tid + q * 256;
            int dd = fi >> 5, c4 = (fi & 31) * 4;
            *(float4*)&Wsm[dd][c4] = *(const float4*)&g_Wqkv[(size_t)(d0 + dd) * 640 + c0 + c4];
            *(float4*)&Xsm[dd][c4] = *(const float4*)&xb   [(size_t)(d0 + dd) * 1024 + n0 + c4];
        }
        __syncthreads();

        #pragma unroll
        for (int dd = 0; dd < 16; dd++) {
            float4 A0 = *(float4*)&Wsm[dd][ty * 4];
            float4 A1 = *(float4*)&Wsm[dd][64 + ty * 4];
            float4 B0 = *(float4*)&Xsm[dd][tx * 4];
            float4 B1 = *(float4*)&Xsm[dd][64 + tx * 4];
            float a[8] = {A0.x, A0.y, A0.z, A0.w, A1.x, A1.y, A1.z, A1.w};
            float bb[8] = {B0.x, B0.y, B0.z, B0.w, B1.x, B1.y, B1.z, B1.w};
            #pragma unroll
            for (int i = 0; i < 8; i++)
                #pragma unroll
                for (int j = 0; j < 8; j++)
                    acc[i][j] += a[i] * bb[j];
        }
        __syncthreads();
    }

    // store: route rows to Q/K/V (c0==512 tile splits cleanly: half K, half V)
    #pragma unroll
    for (int hi = 0; hi < 2; hi++) {
        #pragma unroll
        for (int i = 0; i < 4; i++) {
            int c = c0 + hi * 64 + ty * 4 + i;
            float* rowp;
            if (c < 512)      rowp = &g_Q[((size_t)b * 512 + c) * 1024];
            else if (c < 576) rowp = &g_K[((size_t)b * 64 + (c - 512)) * 1024];
            else              rowp = &g_V[((size_t)b * 64 + (c - 576)) * 1024];
            #pragma unroll
            for (int hn = 0; hn < 2; hn++) {
                float4 v;
                v.x = acc[hi * 4 + i][hn * 4 + 0];
                v.y = acc[hi * 4 + i][hn * 4 + 1];
                v.z = acc[hi * 4 + i][hn * 4 + 2];
                v.w = acc[hi * 4 + i][hn * 4 + 3];
                *(float4*)&rowp[n0 + hn * 64 + tx * 4] = v;
            }
        }
    }
}

// ---------------------------------------------------------------------------
// attention: per (b, h, 64-row q tile). BLOCK_N = 64 kv per iter.
// S ownership: rows n (ty*4+i), cols m (tx*4+j).
// O ownership: rows v (ty*4+i), cols n (tx*4+j) — transposed accumulate so the
// epilogue store to g_O[c][n] is coalesced. corr/linv cross ownership via smem.
// Dynamic smem layout (floats):
//   Qs [64][64]           @ 0      (Qs[k][n])
//   U  union              @ 4096   (Ks[k][m] stride 64  |  Ps[m][n] stride 68)
//   Vs [64][64]           @ 8448   (Vs[v][m])
//   corr[64]              @ 12544
//   linv[64]              @ 12608     -> total 12672 floats = 50688 B
// ---------------------------------------------------------------------------
#define ATTN_SMEM_BYTES 50688

__global__ void __launch_bounds__(256)
attn_v2() {
    extern __shared__ float sm[];
    float* Qs   = sm;
    float* U    = sm + 4096;
    float* Vs   = sm + 8448;
    float* corr = sm + 12544;
    float* linv = sm + 12608;

    const int b  = blockIdx.z;
    const int h  = blockIdx.y;
    const int n0 = blockIdx.x * 64;
    const int tid = threadIdx.x;
    const int tx = tid & 15, ty = tid >> 4;
    const float scale = 0.125f;

    // load Q tile: Qs[k][n]
    const float* Qg = g_Q + ((size_t)b * 512 + h * 64) * 1024 + n0;
    #pragma unroll
    for (int q = 0; q < 4; q++) {
        int fi = tid + q * 256;
        int k = fi >> 4, n4 = (fi & 15) * 4;
        *(float4*)&Qs[k * 64 + n4] = *(const float4*)&Qg[(size_t)k * 1024 + n4];
    }

    float m_i[4], l_i[4], acc[4][4];
    #pragma unroll
    for (int i = 0; i < 4; i++) {
        m_i[i] = -1e30f; l_i[i] = 0.f;
        #pragma unroll
        for (int j = 0; j < 4; j++) acc[i][j] = 0.f;
    }

    const float* Kg = g_K + (size_t)b * 64 * 1024;
    const float* Vg = g_V + (size_t)b * 64 * 1024;

    for (int m0 = 0; m0 < 1024; m0 += 64) {
        __syncthreads();                       // prev PV done reading U/Vs
        #pragma unroll
        for (int q = 0; q < 4; q++) {
            int fi = tid + q * 256;
            int r = fi >> 4, c4 = (fi & 15) * 4;
            *(float4*)&U [r * 64 + c4] = *(const float4*)&Kg[(size_t)r * 1024 + m0 + c4];
            *(float4*)&Vs[r * 64 + c4] = *(const float4*)&Vg[(size_t)r * 1024 + m0 + c4];
        }
        __syncthreads();

        // S[n][m] = sum_k Q[k][n] K[k][m]
        float s[4][4] = {};
        #pragma unroll 8
        for (int k = 0; k < 64; k++) {
            float4 A = *(float4*)&Qs[k * 64 + ty * 4];
            float4 B = *(float4*)&U [k * 64 + tx * 4];
            float a[4] = {A.x, A.y, A.z, A.w};
            float bb[4] = {B.x, B.y, B.z, B.w};
            #pragma unroll
            for (int i = 0; i < 4; i++)
                #pragma unroll
                for (int j = 0; j < 4; j++)
                    s[i][j] += a[i] * bb[j];
        }
        __syncthreads();                       // Ks reads done; U becomes Ps

        // online softmax per n-row; write P transposed Ps[m][n] (stride 68)
        #pragma unroll
        for (int i = 0; i < 4; i++) {
            float s0 = s[i][0] * scale, s1 = s[i][1] * scale;
            float s2 = s[i][2] * scale, s3 = s[i][3] * scale;
            float mx = fmaxf(fmaxf(s0, s1), fmaxf(s2, s3));
            mx = fmaxf(mx, __shfl_xor_sync(0xffffffffu, mx, 1));
            mx = fmaxf(mx, __shfl_xor_sync(0xffffffffu, mx, 2));
            mx = fmaxf(mx, __shfl_xor_sync(0xffffffffu, mx, 4));
            mx = fmaxf(mx, __shfl_xor_sync(0xffffffffu, mx, 8));
            float mnew = fmaxf(m_i[i], mx);
            float cv = __expf(m_i[i] - mnew);
            float p0 = __expf(s0 - mnew);
            float p1 = __expf(s1 - mnew);
            float p2 = __expf(s2 - mnew);
            float p3 = __expf(s3 - mnew);
            // scatter: column ty*4+i of rows tx*4+j  -> Ps[(tx*4+j)*68 + n]
            U[(tx * 4 + 0) * 68 + ty * 4 + i] = p0;
            U[(tx * 4 + 1) * 68 + ty * 4 + i] = p1;
            U[(tx * 4 + 2) * 68 + ty * 4 + i] = p2;
            U[(tx * 4 + 3) * 68 + ty * 4 + i] = p3;
            float rs = p0 + p1 + p2 + p3;
            rs += __shfl_xor_sync(0xffffffffu, rs, 1);
            rs += __shfl_xor_sync(0xffffffffu, rs, 2);
            rs += __shfl_xor_sync(0xffffffffu, rs, 4);
            rs += __shfl_xor_sync(0xffffffffu, rs, 8);
            l_i[i] = l_i[i] * cv + rs;
            m_i[i] = mnew;
            if (tx == 0) corr[ty * 4 + i] = cv;
        }
        __syncthreads();                       // Ps + corr visible

        // O[v][n] rescale + accumulate P@V
        float4 c4 = *(float4*)&corr[tx * 4];
        float cj[4] = {c4.x, c4.y, c4.z, c4.w};
        #pragma unroll
        for (int i = 0; i < 4; i++)
            #pragma unroll
            for (int j = 0; j < 4; j++)
                acc[i][j] *= cj[j];

        #pragma unroll 8
        for (int m = 0; m < 64; m++) {
            float a0 = Vs[(ty * 4 + 0) * 64 + m];
            float a1 = Vs[(ty * 4 + 1) * 64 + m];
            float a2 = Vs[(ty * 4 + 2) * 64 + m];
            float a3 = Vs[(ty * 4 + 3) * 64 + m];
            float4 B = *(float4*)&U[m * 68 + tx * 4];
            float bb[4] = {B.x, B.y, B.z, B.w};
            float a[4] = {a0, a1, a2, a3};
            #pragma unroll
            for (int i = 0; i < 4; i++)
                #pragma unroll
                for (int j = 0; j < 4; j++)
                    acc[i][j] += a[i] * bb[j];
        }
    }

    __syncthreads();
    if (tx == 0) {
        #pragma unroll
        for (int i = 0; i < 4; i++) linv[ty * 4 + i] = 1.0f / l_i[i];
    }
    __syncthreads();

    float4 lv = *(float4*)&linv[tx * 4];
    float lj[4] = {lv.x, lv.y, lv.z, lv.w};
    #pragma unroll
    for (int i = 0; i < 4; i++) {
        float4 o;
        o.x = acc[i][0] * lj[0];
        o.y = acc[i][1] * lj[1];
        o.z = acc[i][2] * lj[2];
        o.w = acc[i][3] * lj[3];
        *(float4*)&g_O[((size_t)b * 512 + h * 64 + ty * 4 + i) * 1024 + n0 + tx * 4] = o;
    }
}

// ---------------------------------------------------------------------------
// outproj: R[dout][n] = sum_c WoutT[c][dout] * O[c][n]   (per batch)
// Same 128x128 / 8x8 structure as qkv_v2.
// ---------------------------------------------------------------------------
__global__ void __launch_bounds__(256)
outproj_v2(float* __restrict__ out) {
    __shared__ float Wsm[16][128];
    __shared__ float Osm[16][128];

    const int b  = blockIdx.z;
    const int d0 = blockIdx.y * 128;
    const int n0 = blockIdx.x * 128;
    const int tid = threadIdx.x;
    const int tx = tid & 15, ty = tid >> 4;

    const float* Ob = g_O + (size_t)b * 512 * 1024;

    float acc[8][8] = {};

    for (int c0 = 0; c0 < 512; c0 += 16) {
        #pragma unroll
        for (int q = 0; q < 2; q++) {
            int fi = tid + q * 256;
            int cc = fi >> 5, c4 = (fi & 31) * 4;
            *(float4*)&Wsm[cc][c4] = *(const float4*)&g_WoutT[(size_t)(c0 + cc) * 512 + d0 + c4];
            *(float4*)&Osm[cc][c4] = *(const float4*)&Ob     [(size_t)(c0 + cc) * 1024 + n0 + c4];
        }
        __syncthreads();

        #pragma unroll
        for (int cc = 0; cc < 16; cc++) {
            float4 A0 = *(float4*)&Wsm[cc][ty * 4];
            float4 A1 = *(float4*)&Wsm[cc][64 + ty * 4];
            float4 B0 = *(float4*)&Osm[cc][tx * 4];
            float4 B1 = *(float4*)&Osm[cc][64 + tx * 4];
            float a[8] = {A0.x, A0.y, A0.z, A0.w, A1.x, A1.y, A1.z, A1.w};
            float bb[8] = {B0.x, B0.y, B0.z, B0.w, B1.x, B1.y, B1.z, B1.w};
            #pragma unroll
            for (int i = 0; i < 8; i++)
                #pragma unroll
                for (int j = 0; j < 8; j++)
                    acc[i][j] += a[i] * bb[j];
        }
        __syncthreads();
    }

    #pragma unroll
    for (int hi = 0; hi < 2; hi++) {
        #pragma unroll
        for (int i = 0; i < 4; i++) {
            int dout = d0 + hi * 64 + ty * 4 + i;
            #pragma unroll
            for (int hn = 0; hn < 2; hn++) {
                float4 v;
                v.x = acc[hi * 4 + i][hn * 4 + 0];
                v.y = acc[hi * 4 + i][hn * 4 + 1];
                v.z = acc[hi * 4 + i][hn * 4 + 2];
                v.w = acc[hi * 4 + i][hn * 4 + 3];
                *(float4*)&out[((size_t)b * 512 + dout) * 1024 + n0 + hn * 64 + tx * 4] = v;
            }
        }
    }
}

// ---------------------------------------------------------------------------
extern "C" void kernel_launch(void* const* d_in, const int* in_sizes, int n_in,
                              void* d_out, int out_size) {
    const float* x    = (const float*)d_in[0];
    const float* qp   = (const float*)d_in[1];
    const float* kp   = (const float*)d_in[2];
    const float* vp   = (const float*)d_in[3];
    const float* wout = (const float*)d_in[4];
    float* out = (float*)d_out;

    cudaFuncSetAttribute(attn_v2, cudaFuncAttributeMaxDynamicSharedMemorySize,
                         ATTN_SMEM_BYTES);

    prep_qkv<<<(512 * 640 + 255) / 256, 256>>>(qp, kp, vp);
    prep_out<<<(512 * 512 + 255) / 256, 256>>>(wout);

    { dim3 g(1024 / 128, 640 / 128, BSZ); qkv_v2<<<g, 256>>>(x); }
    { dim3 g(1024 / 64, NH, BSZ);         attn_v2<<<g, 256, ATTN_SMEM_BYTES>>>(); }
    { dim3 g(1024 / 128, 512 / 128, BSZ); outproj_v2<<<g, 256>>>(out); }
}

// round 5
// speedup vs baseline: 2.8132x; 2.2890x over previous
#include <cuda_runtime.h>
#include <cuda_bf16.h>
#include <cstdint>
#include <cstddef>
#include <math.h>

#define BSZ 8
#define NTOK 1024
#define NH 8

// ---------------------------------------------------------------------------
// Device scratch
// ---------------------------------------------------------------------------
__device__ __align__(16) __nv_bfloat16 g_rxh[BSZ * NTOK * 512];   // [b][n][d]
__device__ __align__(16) __nv_bfloat16 g_rxl[BSZ * NTOK * 512];
__device__ __align__(16) __nv_bfloat16 g_Wqh[640 * 512];          // [c][d]
__device__ __align__(16) __nv_bfloat16 g_Wql[640 * 512];
__device__ __align__(16) __nv_bfloat16 g_Woh[512 * 512];          // [dout][c]
__device__ __align__(16) __nv_bfloat16 g_Wol[512 * 512];
__device__ __align__(16) float g_Y[BSZ * NTOK * 640];             // [b][n][640]
__device__ __align__(16) __nv_bfloat16 g_Kh[BSZ * NTOK * 64];     // [b][m][kd]
__device__ __align__(16) __nv_bfloat16 g_Kl[BSZ * NTOK * 64];
__device__ __align__(16) __nv_bfloat16 g_Vth[BSZ * 64 * NTOK];    // [b][v][m]
__device__ __align__(16) __nv_bfloat16 g_Vtl[BSZ * 64 * NTOK];
__device__ __align__(16) __nv_bfloat16 g_Ohi[BSZ * NTOK * 512];   // [b][n][c]
__device__ __align__(16) __nv_bfloat16 g_Olo[BSZ * NTOK * 512];

// ---------------------------------------------------------------------------
// helpers
// ---------------------------------------------------------------------------
#define SWZ(x) ((x) ^ (((x) >> 3) & 0x70))

__device__ __forceinline__ uint32_t s2u(const void* p) {
    uint32_t a;
    asm("{ .reg .u64 t; cvta.to.shared.u64 t, %1; cvt.u32.u64 %0, t; }" : "=r"(a) : "l"(p));
    return a;
}
__device__ __forceinline__ void ldsm4(uint32_t& a, uint32_t& b, uint32_t& c, uint32_t& d,
                                      uint32_t addr) {
    asm volatile("ldmatrix.sync.aligned.m8n8.x4.shared.b16 {%0,%1,%2,%3}, [%4];"
                 : "=r"(a), "=r"(b), "=r"(c), "=r"(d) : "r"(addr));
}
__device__ __forceinline__ void mma16816(float* d, const uint32_t* a, const uint32_t* b) {
    asm volatile(
        "mma.sync.aligned.m16n8k16.row.col.f32.bf16.bf16.f32 "
        "{%0,%1,%2,%3}, {%4,%5,%6,%7}, {%8,%9}, {%0,%1,%2,%3};"
        : "+f"(d[0]), "+f"(d[1]), "+f"(d[2]), "+f"(d[3])
        : "r"(a[0]), "r"(a[1]), "r"(a[2]), "r"(a[3]), "r"(b[0]), "r"(b[1]));
}
__device__ __forceinline__ void split2(float v, __nv_bfloat16& h, __nv_bfloat16& l) {
    h = __float2bfloat16(v);
    l = __float2bfloat16(v - __bfloat162float(h));
}
__device__ __forceinline__ uint32_t packbf2(__nv_bfloat16 lo, __nv_bfloat16 hi) {
    __nv_bfloat162 t(lo, hi);
    return *reinterpret_cast<uint32_t*>(&t);
}

// ---------------------------------------------------------------------------
// prep kernels
// ---------------------------------------------------------------------------
__global__ void conv_x(const float* __restrict__ x) {
    __shared__ float t[32][33];
    const int b = blockIdx.z, d0 = blockIdx.y * 32, n0 = blockIdx.x * 32;
    const int txx = threadIdx.x, tyy = threadIdx.y;
    #pragma unroll
    for (int r = 0; r < 4; r++)
        t[tyy + r * 8][txx] = x[((size_t)b * 512 + d0 + tyy + r * 8) * 1024 + n0 + txx];
    __syncthreads();
    #pragma unroll
    for (int r = 0; r < 4; r++) {
        int n = n0 + tyy + r * 8;
        __nv_bfloat16 h, l;
        split2(t[txx][tyy + r * 8], h, l);
        size_t o = ((size_t)b * 1024 + n) * 512 + d0 + txx;
        g_rxh[o] = h; g_rxl[o] = l;
    }
}

__global__ void prep_wqkv(const float* __restrict__ qp, const float* __restrict__ kp,
                          const float* __restrict__ vp) {
    int idx = blockIdx.x * 256 + threadIdx.x;
    if (idx >= 640 * 512) return;
    int c = idx >> 9, d = idx & 511;
    float v;
    if (c < 512)      v = qp[c * 512 + d];
    else if (c < 576) v = kp[d * 64 + (c - 512)];
    else              v = vp[d * 64 + (c - 576)];
    split2(v, g_Wqh[idx], g_Wql[idx]);
}

__global__ void prep_wout(const float* __restrict__ wout) {
    int idx = blockIdx.x * 256 + threadIdx.x;
    if (idx >= 512 * 512) return;
    split2(wout[idx], g_Woh[idx], g_Wol[idx]);
}

__global__ void prep_k() {
    int idx = blockIdx.x * 256 + threadIdx.x;
    if (idx >= BSZ * 1024 * 64) return;
    int k = idx & 63, m = (idx >> 6) & 1023, b = idx >> 16;
    split2(g_Y[((size_t)(b * 1024 + m)) * 640 + 512 + k], g_Kh[idx], g_Kl[idx]);
}

__global__ void prep_vt() {
    __shared__ float t[32][65];
    const int b = blockIdx.z, m0 = blockIdx.x * 32;
    const int txx = threadIdx.x, tyy = threadIdx.y;
    #pragma unroll
    for (int g = 0; g < 8; g++) {
        int m = (g & 3) * 8 + tyy;
        int v = (g >> 2) * 32 + txx;
        t[m][v] = g_Y[((size_t)(b * 1024 + m0 + m)) * 640 + 576 + v];
    }
    __syncthreads();
    #pragma unroll
    for (int g = 0; g < 8; g++) {
        int v = g * 8 + tyy;
        __nv_bfloat16 h, l;
        split2(t[txx][v], h, l);
        size_t o = ((size_t)b * 64 + v) * 1024 + m0 + txx;
        g_Vth[o] = h; g_Vtl[o] = l;
    }
}

// ---------------------------------------------------------------------------
// warp-MMA GEMM: D[M][N] = sum_k A[m][k]B[n][k], 3-term bf16 split.
// CTA 128x128, 8 warps (4m x 2n), warp 32x64, K-chunk 64, SW128 smem.
// ---------------------------------------------------------------------------
#define GEMM_SMEM 65536

__global__ void __launch_bounds__(256)
gemm_mma(const __nv_bfloat16* __restrict__ Ahi, const __nv_bfloat16* __restrict__ Alo,
         size_t sA,
         const __nv_bfloat16* __restrict__ Bhi, const __nv_bfloat16* __restrict__ Blo,
         size_t sB,
         float* __restrict__ D, size_t sD, int ldd, int K) {
    extern __shared__ char sm[];
    const uint32_t sbase = s2u(sm);
    const uint32_t OFF[4] = {0u, 16384u, 32768u, 49152u};   // Ah, Al, Bh, Bl

    const int tid = threadIdx.x, lane = tid & 31, wid = tid >> 5;
    const int b = blockIdx.z, mt = blockIdx.y, nt = blockIdx.x;
    const int wm = (wid >> 1) * 32, wn = (wid & 1) * 64;

    const __nv_bfloat16* src[4] = {
        Ahi + b * sA + (size_t)mt * 128 * K,
        Alo + b * sA + (size_t)mt * 128 * K,
        Bhi + b * sB + (size_t)nt * 128 * K,
        Blo + b * sB + (size_t)nt * 128 * K};

    float acc[2][8][4];
    #pragma unroll
    for (int i = 0; i < 2; i++)
        #pragma unroll
        for (int j = 0; j < 8; j++)
            #pragma unroll
            for (int e = 0; e < 4; e++) acc[i][j][e] = 0.f;

    for (int kc = 0; kc < K; kc += 64) {
        __syncthreads();
        #pragma unroll
        for (int t = 0; t < 4; t++) {
            #pragma unroll
            for (int i = 0; i < 4; i++) {
                int c = tid + i * 256;
                int row = c >> 3, u = c & 7;
                uint4 v = *(const uint4*)(src[t] + (size_t)row * K + kc + u * 8);
                *(uint4*)(sm + OFF[t] + SWZ(row * 128 + u * 16)) = v;
            }
        }
        __syncthreads();

        #pragma unroll
        for (int ks = 0; ks < 4; ks++) {
            uint32_t ah[2][4], al[2][4], bh[8][2], bl[8][2];
            #pragma unroll
            for (int mf = 0; mf < 2; mf++) {
                int row = wm + mf * 16 + (lane & 15);
                int cu = ks * 2 + (lane >> 4);
                uint32_t off = SWZ((uint32_t)(row * 128 + cu * 16));
                ldsm4(ah[mf][0], ah[mf][1], ah[mf][2], ah[mf][3], sbase + OFF[0] + off);
                ldsm4(al[mf][0], al[mf][1], al[mf][2], al[mf][3], sbase + OFF[1] + off);
            }
            #pragma unroll
            for (int nf2 = 0; nf2 < 4; nf2++) {
                int row = wn + nf2 * 16 + (lane & 7) + ((lane >> 4) << 3);
                int cu = ks * 2 + ((lane >> 3) & 1);
                uint32_t off = SWZ((uint32_t)(row * 128 + cu * 16));
                ldsm4(bh[2 * nf2][0], bh[2 * nf2][1], bh[2 * nf2 + 1][0], bh[2 * nf2 + 1][1],
                      sbase + OFF[2] + off);
                ldsm4(bl[2 * nf2][0], bl[2 * nf2][1], bl[2 * nf2 + 1][0], bl[2 * nf2 + 1][1],
                      sbase + OFF[3] + off);
            }
            #pragma unroll
            for (int mf = 0; mf < 2; mf++)
                #pragma unroll
                for (int nf = 0; nf < 8; nf++) {
                    mma16816(acc[mf][nf], ah[mf], bh[nf]);
                    mma16816(acc[mf][nf], ah[mf], bl[nf]);
                    mma16816(acc[mf][nf], al[mf], bh[nf]);
                }
        }
    }

    // epilogue
    #pragma unroll
    for (int mf = 0; mf < 2; mf++) {
        int r0 = mt * 128 + wm + mf * 16 + (lane >> 2);
        #pragma unroll
        for (int nf = 0; nf < 8; nf++) {
            int col = nt * 128 + wn + nf * 8 + 2 * (lane & 3);
            float2 v0 = make_float2(acc[mf][nf][0], acc[mf][nf][1]);
            float2 v1 = make_float2(acc[mf][nf][2], acc[mf][nf][3]);
            *(float2*)(D + b * sD + (size_t)r0 * ldd + col) = v0;
            *(float2*)(D + b * sD + (size_t)(r0 + 8) * ldd + col) = v1;
        }
    }
}

// ---------------------------------------------------------------------------
// HMMA flash attention. CTA = (b, h, 128 q rows); 8 warps, 16 rows each.
// smem: Qh 0 | Ql 16K | Kh 32K | Kl 40K | Vh 48K | Vl 56K  (all SW128)
// ---------------------------------------------------------------------------
#define ATTN_SMEM 65536

__global__ void __launch_bounds__(256)
attn_mma() {
    extern __shared__ char sm[];
    const uint32_t sbase = s2u(sm);
    const uint32_t QH = 0u, QL = 16384u, KH = 32768u, KL = 40960u, VH = 49152u, VL = 57344u;

    const int tid = threadIdx.x, lane = tid & 31, wid = tid >> 5;
    const int b = blockIdx.z, h = blockIdx.y, n0 = blockIdx.x * 128;
    const float* Yb = g_Y + (size_t)b * 1024 * 640;

    // ---- Q fill: 128 rows x 64 k (scale 0.125 folded in, hi/lo split) ----
    #pragma unroll
    for (int i = 0; i < 8; i++) {
        int c = tid + i * 256;          // 2048 float4 units
        int row = c >> 4, u4 = c & 15;  // u4: 4-float unit
        float4 v = *(const float4*)&Yb[(size_t)(n0 + row) * 640 + h * 64 + u4 * 4];
        v.x *= 0.125f; v.y *= 0.125f; v.z *= 0.125f; v.w *= 0.125f;
        __nv_bfloat16 h0, l0, h1, l1, h2, l2, h3, l3;
        split2(v.x, h0, l0); split2(v.y, h1, l1);
        split2(v.z, h2, l2); split2(v.w, h3, l3);
        uint32_t hi01 = packbf2(h0, h1), hi23 = packbf2(h2, h3);
        uint32_t lo01 = packbf2(l0, l1), lo23 = packbf2(l2, l3);
        uint32_t off = SWZ((uint32_t)(row * 128 + u4 * 8));
        *(uint2*)(sm + QH + off) = make_uint2(hi01, hi23);
        *(uint2*)(sm + QL + off) = make_uint2(lo01, lo23);
    }

    float m_i[2], l_i[2], oacc[8][4];
    m_i[0] = m_i[1] = -1e30f;
    l_i[0] = l_i[1] = 0.f;
    #pragma unroll
    for (int nf = 0; nf < 8; nf++)
        #pragma unroll
        for (int e = 0; e < 4; e++) oacc[nf][e] = 0.f;

    const __nv_bfloat16* Khb = g_Kh + (size_t)b * 1024 * 64;
    const __nv_bfloat16* Klb = g_Kl + (size_t)b * 1024 * 64;
    const __nv_bfloat16* Vhb = g_Vth + (size_t)b * 64 * 1024;
    const __nv_bfloat16* Vlb = g_Vtl + (size_t)b * 64 * 1024;

    for (int m0 = 0; m0 < 1024; m0 += 64) {
        __syncthreads();
        // K chunk: 64 rows(m) x 64(kd); V chunk: 64 rows(v) x 64(m)
        #pragma unroll
        for (int i = 0; i < 2; i++) {
            int c = tid + i * 256;       // 512 16B units
            int row = c >> 3, u = c & 7;
            uint32_t off = SWZ((uint32_t)(row * 128 + u * 16));
            *(uint4*)(sm + KH + off) = *(const uint4*)(Khb + (size_t)(m0 + row) * 64 + u * 8);
            *(uint4*)(sm + KL + off) = *(const uint4*)(Klb + (size_t)(m0 + row) * 64 + u * 8);
            *(uint4*)(sm + VH + off) = *(const uint4*)(Vhb + (size_t)row * 1024 + m0 + u * 8);
            *(uint4*)(sm + VL + off) = *(const uint4*)(Vlb + (size_t)row * 1024 + m0 + u * 8);
        }
        __syncthreads();

        // ---- S = Q K^T (warp rows wid*16..+15, cols 0..63) ----
        float sacc[8][4];
        #pragma unroll
        for (int nf = 0; nf < 8; nf++)
            #pragma unroll
            for (int e = 0; e < 4; e++) sacc[nf][e] = 0.f;

        #pragma unroll
        for (int ks = 0; ks < 4; ks++) {
            uint32_t qh[4], ql[4], bh[8][2], bl[8][2];
            {
                int row = wid * 16 + (lane & 15);
                int cu = ks * 2 + (lane >> 4);
                uint32_t off = SWZ((uint32_t)(row * 128 + cu * 16));
                ldsm4(qh[0], qh[1], qh[2], qh[3], sbase + QH + off);
                ldsm4(ql[0], ql[1], ql[2], ql[3], sbase + QL + off);
            }
            #pragma unroll
            for (int nf2 = 0; nf2 < 4; nf2++) {
                int row = nf2 * 16 + (lane & 7) + ((lane >> 4) << 3);
                int cu = ks * 2 + ((lane >> 3) & 1);
                uint32_t off = SWZ((uint32_t)(row * 128 + cu * 16));
                ldsm4(bh[2 * nf2][0], bh[2 * nf2][1], bh[2 * nf2 + 1][0], bh[2 * nf2 + 1][1],
                      sbase + KH + off);
                ldsm4(bl[2 * nf2][0], bl[2 * nf2][1], bl[2 * nf2 + 1][0], bl[2 * nf2 + 1][1],
                      sbase + KL + off);
            }
            #pragma unroll
            for (int nf = 0; nf < 8; nf++) {
                mma16816(sacc[nf], qh, bh[nf]);
                mma16816(sacc[nf], qh, bl[nf]);
                mma16816(sacc[nf], ql, bh[nf]);
            }
        }

        // ---- online softmax (rows lane/4, lane/4+8; all in-warp) ----
        float mx0 = -1e30f, mx1 = -1e30f;
        #pragma unroll
        for (int nf = 0; nf < 8; nf++) {
            mx0 = fmaxf(mx0, fmaxf(sacc[nf][0], sacc[nf][1]));
            mx1 = fmaxf(mx1, fmaxf(sacc[nf][2], sacc[nf][3]));
        }
        mx0 = fmaxf(mx0, __shfl_xor_sync(0xffffffffu, mx0, 1));
        mx0 = fmaxf(mx0, __shfl_xor_sync(0xffffffffu, mx0, 2));
        mx1 = fmaxf(mx1, __shfl_xor_sync(0xffffffffu, mx1, 1));
        mx1 = fmaxf(mx1, __shfl_xor_sync(0xffffffffu, mx1, 2));
        float mn0 = fmaxf(m_i[0], mx0), mn1 = fmaxf(m_i[1], mx1);
        float c0 = __expf(m_i[0] - mn0), c1 = __expf(m_i[1] - mn1);
        float sum0 = 0.f, sum1 = 0.f;
        #pragma unroll
        for (int nf = 0; nf < 8; nf++) {
            sacc[nf][0] = __expf(sacc[nf][0] - mn0);
            sacc[nf][1] = __expf(sacc[nf][1] - mn0);
            sacc[nf][2] = __expf(sacc[nf][2] - mn1);
            sacc[nf][3] = __expf(sacc[nf][3] - mn1);
            sum0 += sacc[nf][0] + sacc[nf][1];
            sum1 += sacc[nf][2] + sacc[nf][3];
        }
        sum0 += __shfl_xor_sync(0xffffffffu, sum0, 1);
        sum0 += __shfl_xor_sync(0xffffffffu, sum0, 2);
        sum1 += __shfl_xor_sync(0xffffffffu, sum1, 1);
        sum1 += __shfl_xor_sync(0xffffffffu, sum1, 2);
        l_i[0] = l_i[0] * c0 + sum0;
        l_i[1] = l_i[1] * c1 + sum1;
        m_i[0] = mn0; m_i[1] = mn1;
        #pragma unroll
        for (int nf = 0; nf < 8; nf++) {
            oacc[nf][0] *= c0; oacc[nf][1] *= c0;
            oacc[nf][2] *= c1; oacc[nf][3] *= c1;
        }

        // ---- O += P V : P stays in registers as A-fragments ----
        #pragma unroll
        for (int ks = 0; ks < 4; ks++) {
            uint32_t pah[4], pal[4];
            {
                const float* f0 = sacc[2 * ks];
                const float* f1 = sacc[2 * ks + 1];
                __nv_bfloat16 h0, l0, h1, l1;
                split2(f0[0], h0, l0); split2(f0[1], h1, l1);
                pah[0] = packbf2(h0, h1); pal[0] = packbf2(l0, l1);
                split2(f0[2], h0, l0); split2(f0[3], h1, l1);
                pah[1] = packbf2(h0, h1); pal[1] = packbf2(l0, l1);
                split2(f1[0], h0, l0); split2(f1[1], h1, l1);
                pah[2] = packbf2(h0, h1); pal[2] = packbf2(l0, l1);
                split2(f1[2], h0, l0); split2(f1[3], h1, l1);
                pah[3] = packbf2(h0, h1); pal[3] = packbf2(l0, l1);
            }
            uint32_t vh[8][2], vl[8][2];
            #pragma unroll
            for (int nf2 = 0; nf2 < 4; nf2++) {
                int row = nf2 * 16 + (lane & 7) + ((lane >> 4) << 3);
                int cu = ks * 2 + ((lane >> 3) & 1);
                uint32_t off = SWZ((uint32_t)(row * 128 + cu * 16));
                ldsm4(vh[2 * nf2][0], vh[2 * nf2][1], vh[2 * nf2 + 1][0], vh[2 * nf2 + 1][1],
                      sbase + VH + off);
                ldsm4(vl[2 * nf2][0], vl[2 * nf2][1], vl[2 * nf2 + 1][0], vl[2 * nf2 + 1][1],
                      sbase + VL + off);
            }
            #pragma unroll
            for (int nf = 0; nf < 8; nf++) {
                mma16816(oacc[nf], pah, vh[nf]);
                mma16816(oacc[nf], pah, vl[nf]);
                mma16816(oacc[nf], pal, vh[nf]);
            }
        }
    }

    // ---- epilogue: normalize, split, write Ohi/Olo ----
    float inv0 = 1.0f / l_i[0], inv1 = 1.0f / l_i[1];
    int nr0 = n0 + wid * 16 + (lane >> 2);
    #pragma unroll
    for (int nf = 0; nf < 8; nf++) {
        int col = h * 64 + nf * 8 + 2 * (lane & 3);
        float o0 = oacc[nf][0] * inv0, o1 = oacc[nf][1] * inv0;
        float o2 = oacc[nf][2] * inv1, o3 = oacc[nf][3] * inv1;
        __nv_bfloat16 h0, l0, h1, l1;
        split2(o0, h0, l0); split2(o1, h1, l1);
        size_t base0 = ((size_t)b * 1024 + nr0) * 512 + col;
        *(uint32_t*)&g_Ohi[base0] = packbf2(h0, h1);
        *(uint32_t*)&g_Olo[base0] = packbf2(l0, l1);
        split2(o2, h0, l0); split2(o3, h1, l1);
        size_t base1 = ((size_t)b * 1024 + nr0 + 8) * 512 + col;
        *(uint32_t*)&g_Ohi[base1] = packbf2(h0, h1);
        *(uint32_t*)&g_Olo[base1] = packbf2(l0, l1);
    }
}

// ---------------------------------------------------------------------------
extern "C" void kernel_launch(void* const* d_in, const int* in_sizes, int n_in,
                              void* d_out, int out_size) {
    const float* x    = (const float*)d_in[0];
    const float* qp   = (const float*)d_in[1];
    const float* kp   = (const float*)d_in[2];
    const float* vp   = (const float*)d_in[3];
    const float* wout = (const float*)d_in[4];
    float* out = (float*)d_out;

    cudaFuncSetAttribute(gemm_mma, cudaFuncAttributeMaxDynamicSharedMemorySize, GEMM_SMEM);
    cudaFuncSetAttribute(attn_mma, cudaFuncAttributeMaxDynamicSharedMemorySize, ATTN_SMEM);

    { dim3 g(32, 16, BSZ); dim3 blk(32, 8); conv_x<<<g, blk>>>(x); }
    prep_wqkv<<<(640 * 512 + 255) / 256, 256>>>(qp, kp, vp);
    prep_wout<<<(512 * 512 + 255) / 256, 256>>>(wout);

    __nv_bfloat16 *rxh, *rxl, *wqh, *wql, *woh, *wol, *ohi, *olo;
    float* yptr;
    cudaGetSymbolAddress((void**)&rxh, g_rxh);
    cudaGetSymbolAddress((void**)&rxl, g_rxl);
    cudaGetSymbolAddress((void**)&wqh, g_Wqh);
    cudaGetSymbolAddress((void**)&wql, g_Wql);
    cudaGetSymbolAddress((void**)&woh, g_Woh);
    cudaGetSymbolAddress((void**)&wol, g_Wol);
    cudaGetSymbolAddress((void**)&ohi, g_Ohi);
    cudaGetSymbolAddress((void**)&olo, g_Olo);
    cudaGetSymbolAddress((void**)&yptr, g_Y);

    // GEMM1: Y[n][c] (M=1024 tokens, N=640, K=512), per batch
    {
        dim3 g(5, 8, BSZ);
        gemm_mma<<<g, 256, GEMM_SMEM>>>(rxh, rxl, (size_t)1024 * 512,
                                        wqh, wql, 0,
                                        yptr, (size_t)1024 * 640, 640, 512);
    }

    prep_k<<<(BSZ * 1024 * 64 + 255) / 256, 256>>>();
    { dim3 g(32, 1, BSZ); dim3 blk(32, 8); prep_vt<<<g, blk>>>(); }

    // attention
    { dim3 g(8, NH, BSZ); attn_mma<<<g, 256, ATTN_SMEM>>>(); }

    // GEMM2: out[dout][n] (M=512, N=1024 tokens, K=512), per batch
    {
        dim3 g(8, 4, BSZ);
        gemm_mma<<<g, 256, GEMM_SMEM>>>(woh, wol, 0,
                                        ohi, olo, (size_t)1024 * 512,
                                        out, (size_t)512 * 1024, 1024, 512);
    }
}

// round 6
// speedup vs baseline: 3.3876x; 1.2042x over previous
#include <cuda_runtime.h>
#include <cuda_bf16.h>
#include <cstdint>
#include <cstddef>
#include <math.h>

#define BSZ 8
#define NTOK 1024
#define NH 8

// ---------------------------------------------------------------------------
// Device scratch
// ---------------------------------------------------------------------------
__device__ __align__(16) __nv_bfloat16 g_rxh[BSZ * NTOK * 512];   // [b][n][d]
__device__ __align__(16) __nv_bfloat16 g_rxl[BSZ * NTOK * 512];
__device__ __align__(16) __nv_bfloat16 g_Wqh[640 * 512];          // [c][d]
__device__ __align__(16) __nv_bfloat16 g_Wql[640 * 512];
__device__ __align__(16) __nv_bfloat16 g_Woh[512 * 512];          // [dout][c]
__device__ __align__(16) __nv_bfloat16 g_Wol[512 * 512];
__device__ __align__(16) float g_Y[BSZ * NTOK * 640];             // [b][n][640]
__device__ __align__(16) __nv_bfloat16 g_Kh[BSZ * NTOK * 64];     // [b][m][kd]
__device__ __align__(16) __nv_bfloat16 g_Kl[BSZ * NTOK * 64];
__device__ __align__(16) __nv_bfloat16 g_Vth[BSZ * 64 * NTOK];    // [b][v][m]
__device__ __align__(16) __nv_bfloat16 g_Vtl[BSZ * 64 * NTOK];
__device__ __align__(16) __nv_bfloat16 g_Ohi[BSZ * NTOK * 512];   // [b][n][c]
__device__ __align__(16) __nv_bfloat16 g_Olo[BSZ * NTOK * 512];

// ---------------------------------------------------------------------------
// helpers
// ---------------------------------------------------------------------------
#define SWZ(x) ((x) ^ (((x) >> 3) & 0x70))

__device__ __forceinline__ uint32_t s2u(const void* p) {
    uint32_t a;
    asm("{ .reg .u64 t; cvta.to.shared.u64 t, %1; cvt.u32.u64 %0, t; }" : "=r"(a) : "l"(p));
    return a;
}
__device__ __forceinline__ void cpasync16(uint32_t dst, const void* src) {
    asm volatile("cp.async.cg.shared.global [%0], [%1], 16;" :: "r"(dst), "l"(src));
}
#define CP_COMMIT() asm volatile("cp.async.commit_group;")
#define CP_WAIT(n)  asm volatile("cp.async.wait_group %0;" :: "n"(n))

__device__ __forceinline__ void ldsm4(uint32_t& a, uint32_t& b, uint32_t& c, uint32_t& d,
                                      uint32_t addr) {
    asm volatile("ldmatrix.sync.aligned.m8n8.x4.shared.b16 {%0,%1,%2,%3}, [%4];"
                 : "=r"(a), "=r"(b), "=r"(c), "=r"(d) : "r"(addr));
}
__device__ __forceinline__ void mma16816(float* d, const uint32_t* a, const uint32_t* b) {
    asm volatile(
        "mma.sync.aligned.m16n8k16.row.col.f32.bf16.bf16.f32 "
        "{%0,%1,%2,%3}, {%4,%5,%6,%7}, {%8,%9}, {%0,%1,%2,%3};"
        : "+f"(d[0]), "+f"(d[1]), "+f"(d[2]), "+f"(d[3])
        : "r"(a[0]), "r"(a[1]), "r"(a[2]), "r"(a[3]), "r"(b[0]), "r"(b[1]));
}
__device__ __forceinline__ void split2(float v, __nv_bfloat16& h, __nv_bfloat16& l) {
    h = __float2bfloat16(v);
    l = __float2bfloat16(v - __bfloat162float(h));
}
__device__ __forceinline__ uint32_t packbf2(__nv_bfloat16 lo, __nv_bfloat16 hi) {
    __nv_bfloat162 t(lo, hi);
    return *reinterpret_cast<uint32_t*>(&t);
}

// ---------------------------------------------------------------------------
// prep kernels
// ---------------------------------------------------------------------------
__global__ void conv_x(const float* __restrict__ x) {
    __shared__ float t[32][33];
    const int b = blockIdx.z, d0 = blockIdx.y * 32, n0 = blockIdx.x * 32;
    const int txx = threadIdx.x, tyy = threadIdx.y;
    #pragma unroll
    for (int r = 0; r < 4; r++)
        t[tyy + r * 8][txx] = x[((size_t)b * 512 + d0 + tyy + r * 8) * 1024 + n0 + txx];
    __syncthreads();
    #pragma unroll
    for (int r = 0; r < 4; r++) {
        int n = n0 + tyy + r * 8;
        __nv_bfloat16 h, l;
        split2(t[txx][tyy + r * 8], h, l);
        size_t o = ((size_t)b * 1024 + n) * 512 + d0 + txx;
        g_rxh[o] = h; g_rxl[o] = l;
    }
}

__global__ void prep_wqkv(const float* __restrict__ qp, const float* __restrict__ kp,
                          const float* __restrict__ vp) {
    int idx = blockIdx.x * 256 + threadIdx.x;
    if (idx >= 640 * 512) return;
    int c = idx >> 9, d = idx & 511;
    float v;
    if (c < 512)      v = qp[c * 512 + d];
    else if (c < 576) v = kp[d * 64 + (c - 512)];
    else              v = vp[d * 64 + (c - 576)];
    split2(v, g_Wqh[idx], g_Wql[idx]);
}

__global__ void prep_wout(const float* __restrict__ wout) {
    int idx = blockIdx.x * 256 + threadIdx.x;
    if (idx >= 512 * 512) return;
    split2(wout[idx], g_Woh[idx], g_Wol[idx]);
}

__global__ void prep_k() {
    int idx = blockIdx.x * 256 + threadIdx.x;
    if (idx >= BSZ * 1024 * 64) return;
    int k = idx & 63, m = (idx >> 6) & 1023, b = idx >> 16;
    split2(g_Y[((size_t)(b * 1024 + m)) * 640 + 512 + k], g_Kh[idx], g_Kl[idx]);
}

__global__ void prep_vt() {
    __shared__ float t[32][65];
    const int b = blockIdx.z, m0 = blockIdx.x * 32;
    const int txx = threadIdx.x, tyy = threadIdx.y;
    #pragma unroll
    for (int g = 0; g < 8; g++) {
        int m = (g & 3) * 8 + tyy;
        int v = (g >> 2) * 32 + txx;
        t[m][v] = g_Y[((size_t)(b * 1024 + m0 + m)) * 640 + 576 + v];
    }
    __syncthreads();
    #pragma unroll
    for (int g = 0; g < 8; g++) {
        int v = g * 8 + tyy;
        __nv_bfloat16 h, l;
        split2(t[txx][v], h, l);
        size_t o = ((size_t)b * 64 + v) * 1024 + m0 + txx;
        g_Vth[o] = h; g_Vtl[o] = l;
    }
}

// ---------------------------------------------------------------------------
// warp-MMA GEMM with cp.async double buffering.
// CTA 128x128, 8 warps (4m x 2n), warp 32x64, K-chunk 64, SW128 smem.
// smem: 2 stages x 64KB; within a stage: Ah 0 | Al 16K | Bh 32K | Bl 48K
// ---------------------------------------------------------------------------
#define GEMM_SMEM (2 * 65536)

__global__ void __launch_bounds__(256)
gemm_mma(const __nv_bfloat16* __restrict__ Ahi, const __nv_bfloat16* __restrict__ Alo,
         size_t sA,
         const __nv_bfloat16* __restrict__ Bhi, const __nv_bfloat16* __restrict__ Blo,
         size_t sB,
         float* __restrict__ D, size_t sD, int ldd, int K) {
    extern __shared__ char sm[];
    const uint32_t sbase = s2u(sm);
    const uint32_t OFF[4] = {0u, 16384u, 32768u, 49152u};

    const int tid = threadIdx.x, lane = tid & 31, wid = tid >> 5;
    const int b = blockIdx.z, mt = blockIdx.y, nt = blockIdx.x;
    const int wm = (wid >> 1) * 32, wn = (wid & 1) * 64;

    const __nv_bfloat16* gsrc[4] = {
        Ahi + b * sA + (size_t)mt * 128 * K,
        Alo + b * sA + (size_t)mt * 128 * K,
        Bhi + b * sB + (size_t)nt * 128 * K,
        Blo + b * sB + (size_t)nt * 128 * K};

    auto load_chunk = [&](int stage, int kc) {
        const uint32_t stbase = sbase + stage * 65536;
        #pragma unroll
        for (int t = 0; t < 4; t++) {
            #pragma unroll
            for (int i = 0; i < 4; i++) {
                int c = tid + i * 256;
                int row = c >> 3, u = c & 7;
                cpasync16(stbase + OFF[t] + SWZ((uint32_t)(row * 128 + u * 16)),
                          gsrc[t] + (size_t)row * K + kc + u * 8);
            }
        }
        CP_COMMIT();
    };

    float acc[2][8][4];
    #pragma unroll
    for (int i = 0; i < 2; i++)
        #pragma unroll
        for (int j = 0; j < 8; j++)
            #pragma unroll
            for (int e = 0; e < 4; e++) acc[i][j][e] = 0.f;

    const int nchunks = K >> 6;
    load_chunk(0, 0);

    for (int c = 0; c < nchunks; c++) {
        if (c + 1 < nchunks) {
            load_chunk((c + 1) & 1, (c + 1) << 6);
            CP_WAIT(1);
        } else {
            CP_WAIT(0);
        }
        __syncthreads();
        const uint32_t stb = sbase + (c & 1) * 65536;

        #pragma unroll
        for (int ks = 0; ks < 4; ks++) {
            uint32_t ah[2][4], al[2][4], bh[8][2], bl[8][2];
            #pragma unroll
            for (int mf = 0; mf < 2; mf++) {
                int row = wm + mf * 16 + (lane & 15);
                int cu = ks * 2 + (lane >> 4);
                uint32_t off = SWZ((uint32_t)(row * 128 + cu * 16));
                ldsm4(ah[mf][0], ah[mf][1], ah[mf][2], ah[mf][3], stb + OFF[0] + off);
                ldsm4(al[mf][0], al[mf][1], al[mf][2], al[mf][3], stb + OFF[1] + off);
            }
            #pragma unroll
            for (int nf2 = 0; nf2 < 4; nf2++) {
                int row = wn + nf2 * 16 + (lane & 7) + ((lane >> 4) << 3);
                int cu = ks * 2 + ((lane >> 3) & 1);
                uint32_t off = SWZ((uint32_t)(row * 128 + cu * 16));
                ldsm4(bh[2 * nf2][0], bh[2 * nf2][1], bh[2 * nf2 + 1][0], bh[2 * nf2 + 1][1],
                      stb + OFF[2] + off);
                ldsm4(bl[2 * nf2][0], bl[2 * nf2][1], bl[2 * nf2 + 1][0], bl[2 * nf2 + 1][1],
                      stb + OFF[3] + off);
            }
            #pragma unroll
            for (int mf = 0; mf < 2; mf++)
                #pragma unroll
                for (int nf = 0; nf < 8; nf++) {
                    mma16816(acc[mf][nf], ah[mf], bh[nf]);
                    mma16816(acc[mf][nf], ah[mf], bl[nf]);
                    mma16816(acc[mf][nf], al[mf], bh[nf]);
                }
        }
        __syncthreads();
    }

    #pragma unroll
    for (int mf = 0; mf < 2; mf++) {
        int r0 = mt * 128 + wm + mf * 16 + (lane >> 2);
        #pragma unroll
        for (int nf = 0; nf < 8; nf++) {
            int col = nt * 128 + wn + nf * 8 + 2 * (lane & 3);
            *(float2*)(D + b * sD + (size_t)r0 * ldd + col) =
                make_float2(acc[mf][nf][0], acc[mf][nf][1]);
            *(float2*)(D + b * sD + (size_t)(r0 + 8) * ldd + col) =
                make_float2(acc[mf][nf][2], acc[mf][nf][3]);
        }
    }
}

// ---------------------------------------------------------------------------
// HMMA flash attention with cp.async double-buffered K/V.
// smem: Qh 0 | Ql 16K | stages at 32K + s*32K: {Kh 0 | Kl 8K | Vh 16K | Vl 24K}
// total 96KB
// ---------------------------------------------------------------------------
#define ATTN_SMEM (98304)

__global__ void __launch_bounds__(256)
attn_mma() {
    extern __shared__ char sm[];
    const uint32_t sbase = s2u(sm);
    const uint32_t QH = 0u, QL = 16384u;
    const uint32_t STG = 32768u;

    const int tid = threadIdx.x, lane = tid & 31, wid = tid >> 5;
    const int b = blockIdx.z, h = blockIdx.y, n0 = blockIdx.x * 128;
    const float* Yb = g_Y + (size_t)b * 1024 * 640;

    const __nv_bfloat16* Khb = g_Kh + (size_t)b * 1024 * 64;
    const __nv_bfloat16* Klb = g_Kl + (size_t)b * 1024 * 64;
    const __nv_bfloat16* Vhb = g_Vth + (size_t)b * 64 * 1024;
    const __nv_bfloat16* Vlb = g_Vtl + (size_t)b * 64 * 1024;

    auto load_kv = [&](int stage, int m0) {
        const uint32_t stb = sbase + STG + stage * 32768u;
        #pragma unroll
        for (int i = 0; i < 2; i++) {
            int c = tid + i * 256;
            int row = c >> 3, u = c & 7;
            uint32_t off = SWZ((uint32_t)(row * 128 + u * 16));
            cpasync16(stb + off,          Khb + (size_t)(m0 + row) * 64 + u * 8);
            cpasync16(stb + 8192u + off,  Klb + (size_t)(m0 + row) * 64 + u * 8);
            cpasync16(stb + 16384u + off, Vhb + (size_t)row * 1024 + m0 + u * 8);
            cpasync16(stb + 24576u + off, Vlb + (size_t)row * 1024 + m0 + u * 8);
        }
        CP_COMMIT();
    };

    load_kv(0, 0);

    // ---- Q fill (overlaps with first K/V load) ----
    #pragma unroll
    for (int i = 0; i < 8; i++) {
        int c = tid + i * 256;
        int row = c >> 4, u4 = c & 15;
        float4 v = *(const float4*)&Yb[(size_t)(n0 + row) * 640 + h * 64 + u4 * 4];
        v.x *= 0.125f; v.y *= 0.125f; v.z *= 0.125f; v.w *= 0.125f;
        __nv_bfloat16 h0, l0, h1, l1, h2, l2, h3, l3;
        split2(v.x, h0, l0); split2(v.y, h1, l1);
        split2(v.z, h2, l2); split2(v.w, h3, l3);
        uint32_t off = SWZ((uint32_t)(row * 128 + u4 * 8));
        *(uint2*)(sm + QH + off) = make_uint2(packbf2(h0, h1), packbf2(h2, h3));
        *(uint2*)(sm + QL + off) = make_uint2(packbf2(l0, l1), packbf2(l2, l3));
    }

    float m_i[2], l_i[2], oacc[8][4];
    m_i[0] = m_i[1] = -1e30f;
    l_i[0] = l_i[1] = 0.f;
    #pragma unroll
    for (int nf = 0; nf < 8; nf++)
        #pragma unroll
        for (int e = 0; e < 4; e++) oacc[nf][e] = 0.f;

    for (int ic = 0; ic < 16; ic++) {
        if (ic + 1 < 16) {
            load_kv((ic + 1) & 1, (ic + 1) * 64);
            CP_WAIT(1);
        } else {
            CP_WAIT(0);
        }
        __syncthreads();
        const uint32_t KHs = STG + (uint32_t)(ic & 1) * 32768u;
        const uint32_t KLs = KHs + 8192u, VHs = KHs + 16384u, VLs = KHs + 24576u;

        // ---- S = Q K^T ----
        float sacc[8][4];
        #pragma unroll
        for (int nf = 0; nf < 8; nf++)
            #pragma unroll
            for (int e = 0; e < 4; e++) sacc[nf][e] = 0.f;

        #pragma unroll
        for (int ks = 0; ks < 4; ks++) {
            uint32_t qh[4], ql[4], bh[8][2], bl[8][2];
            {
                int row = wid * 16 + (lane & 15);
                int cu = ks * 2 + (lane >> 4);
                uint32_t off = SWZ((uint32_t)(row * 128 + cu * 16));
                ldsm4(qh[0], qh[1], qh[2], qh[3], sbase + QH + off);
                ldsm4(ql[0], ql[1], ql[2], ql[3], sbase + QL + off);
            }
            #pragma unroll
            for (int nf2 = 0; nf2 < 4; nf2++) {
                int row = nf2 * 16 + (lane & 7) + ((lane >> 4) << 3);
                int cu = ks * 2 + ((lane >> 3) & 1);
                uint32_t off = SWZ((uint32_t)(row * 128 + cu * 16));
                ldsm4(bh[2 * nf2][0], bh[2 * nf2][1], bh[2 * nf2 + 1][0], bh[2 * nf2 + 1][1],
                      sbase + KHs + off);
                ldsm4(bl[2 * nf2][0], bl[2 * nf2][1], bl[2 * nf2 + 1][0], bl[2 * nf2 + 1][1],
                      sbase + KLs + off);
            }
            #pragma unroll
            for (int nf = 0; nf < 8; nf++) {
                mma16816(sacc[nf], qh, bh[nf]);
                mma16816(sacc[nf], qh, bl[nf]);
                mma16816(sacc[nf], ql, bh[nf]);
            }
        }

        // ---- online softmax ----
        float mx0 = -1e30f, mx1 = -1e30f;
        #pragma unroll
        for (int nf = 0; nf < 8; nf++) {
            mx0 = fmaxf(mx0, fmaxf(sacc[nf][0], sacc[nf][1]));
            mx1 = fmaxf(mx1, fmaxf(sacc[nf][2], sacc[nf][3]));
        }
        mx0 = fmaxf(mx0, __shfl_xor_sync(0xffffffffu, mx0, 1));
        mx0 = fmaxf(mx0, __shfl_xor_sync(0xffffffffu, mx0, 2));
        mx1 = fmaxf(mx1, __shfl_xor_sync(0xffffffffu, mx1, 1));
        mx1 = fmaxf(mx1, __shfl_xor_sync(0xffffffffu, mx1, 2));
        float mn0 = fmaxf(m_i[0], mx0), mn1 = fmaxf(m_i[1], mx1);
        float c0 = __expf(m_i[0] - mn0), c1 = __expf(m_i[1] - mn1);
        float sum0 = 0.f, sum1 = 0.f;
        #pragma unroll
        for (int nf = 0; nf < 8; nf++) {
            sacc[nf][0] = __expf(sacc[nf][0] - mn0);
            sacc[nf][1] = __expf(sacc[nf][1] - mn0);
            sacc[nf][2] = __expf(sacc[nf][2] - mn1);
            sacc[nf][3] = __expf(sacc[nf][3] - mn1);
            sum0 += sacc[nf][0] + sacc[nf][1];
            sum1 += sacc[nf][2] + sacc[nf][3];
        }
        sum0 += __shfl_xor_sync(0xffffffffu, sum0, 1);
        sum0 += __shfl_xor_sync(0xffffffffu, sum0, 2);
        sum1 += __shfl_xor_sync(0xffffffffu, sum1, 1);
        sum1 += __shfl_xor_sync(0xffffffffu, sum1, 2);
        l_i[0] = l_i[0] * c0 + sum0;
        l_i[1] = l_i[1] * c1 + sum1;
        m_i[0] = mn0; m_i[1] = mn1;
        #pragma unroll
        for (int nf = 0; nf < 8; nf++) {
            oacc[nf][0] *= c0; oacc[nf][1] *= c0;
            oacc[nf][2] *= c1; oacc[nf][3] *= c1;
        }

        // ---- O += P V (P in registers) ----
        #pragma unroll
        for (int ks = 0; ks < 4; ks++) {
            uint32_t pah[4], pal[4];
            {
                const float* f0 = sacc[2 * ks];
                const float* f1 = sacc[2 * ks + 1];
                __nv_bfloat16 h0, l0, h1, l1;
                split2(f0[0], h0, l0); split2(f0[1], h1, l1);
                pah[0] = packbf2(h0, h1); pal[0] = packbf2(l0, l1);
                split2(f0[2], h0, l0); split2(f0[3], h1, l1);
                pah[1] = packbf2(h0, h1); pal[1] = packbf2(l0, l1);
                split2(f1[0], h0, l0); split2(f1[1], h1, l1);
                pah[2] = packbf2(h0, h1); pal[2] = packbf2(l0, l1);
                split2(f1[2], h0, l0); split2(f1[3], h1, l1);
                pah[3] = packbf2(h0, h1); pal[3] = packbf2(l0, l1);
            }
            uint32_t vh[8][2], vl[8][2];
            #pragma unroll
            for (int nf2 = 0; nf2 < 4; nf2++) {
                int row = nf2 * 16 + (lane & 7) + ((lane >> 4) << 3);
                int cu = ks * 2 + ((lane >> 3) & 1);
                uint32_t off = SWZ((uint32_t)(row * 128 + cu * 16));
                ldsm4(vh[2 * nf2][0], vh[2 * nf2][1], vh[2 * nf2 + 1][0], vh[2 * nf2 + 1][1],
                      sbase + VHs + off);
                ldsm4(vl[2 * nf2][0], vl[2 * nf2][1], vl[2 * nf2 + 1][0], vl[2 * nf2 + 1][1],
                      sbase + VLs + off);
            }
            #pragma unroll
            for (int nf = 0; nf < 8; nf++) {
                mma16816(oacc[nf], pah, vh[nf]);
                mma16816(oacc[nf], pah, vl[nf]);
                mma16816(oacc[nf], pal, vh[nf]);
            }
        }
        __syncthreads();
    }

    // ---- epilogue ----
    float inv0 = 1.0f / l_i[0], inv1 = 1.0f / l_i[1];
    int nr0 = n0 + wid * 16 + (lane >> 2);
    #pragma unroll
    for (int nf = 0; nf < 8; nf++) {
        int col = h * 64 + nf * 8 + 2 * (lane & 3);
        float o0 = oacc[nf][0] * inv0, o1 = oacc[nf][1] * inv0;
        float o2 = oacc[nf][2] * inv1, o3 = oacc[nf][3] * inv1;
        __nv_bfloat16 h0, l0, h1, l1;
        split2(o0, h0, l0); split2(o1, h1, l1);
        size_t base0 = ((size_t)b * 1024 + nr0) * 512 + col;
        *(uint32_t*)&g_Ohi[base0] = packbf2(h0, h1);
        *(uint32_t*)&g_Olo[base0] = packbf2(l0, l1);
        split2(o2, h0, l0); split2(o3, h1, l1);
        size_t base1 = ((size_t)b * 1024 + nr0 + 8) * 512 + col;
        *(uint32_t*)&g_Ohi[base1] = packbf2(h0, h1);
        *(uint32_t*)&g_Olo[base1] = packbf2(l0, l1);
    }
}

// ---------------------------------------------------------------------------
extern "C" void kernel_launch(void* const* d_in, const int* in_sizes, int n_in,
                              void* d_out, int out_size) {
    const float* x    = (const float*)d_in[0];
    const float* qp   = (const float*)d_in[1];
    const float* kp   = (const float*)d_in[2];
    const float* vp   = (const float*)d_in[3];
    const float* wout = (const float*)d_in[4];
    float* out = (float*)d_out;

    cudaFuncSetAttribute(gemm_mma, cudaFuncAttributeMaxDynamicSharedMemorySize, GEMM_SMEM);
    cudaFuncSetAttribute(attn_mma, cudaFuncAttributeMaxDynamicSharedMemorySize, ATTN_SMEM);

    { dim3 g(32, 16, BSZ); dim3 blk(32, 8); conv_x<<<g, blk>>>(x); }
    prep_wqkv<<<(640 * 512 + 255) / 256, 256>>>(qp, kp, vp);
    prep_wout<<<(512 * 512 + 255) / 256, 256>>>(wout);

    __nv_bfloat16 *rxh, *rxl, *wqh, *wql, *woh, *wol, *ohi, *olo;
    float* yptr;
    cudaGetSymbolAddress((void**)&rxh, g_rxh);
    cudaGetSymbolAddress((void**)&rxl, g_rxl);
    cudaGetSymbolAddress((void**)&wqh, g_Wqh);
    cudaGetSymbolAddress((void**)&wql, g_Wql);
    cudaGetSymbolAddress((void**)&woh, g_Woh);
    cudaGetSymbolAddress((void**)&wol, g_Wol);
    cudaGetSymbolAddress((void**)&ohi, g_Ohi);
    cudaGetSymbolAddress((void**)&olo, g_Olo);
    cudaGetSymbolAddress((void**)&yptr, g_Y);

    // GEMM1: Y[n][c] (M=1024 tokens, N=640, K=512), per batch
    {
        dim3 g(5, 8, BSZ);
        gemm_mma<<<g, 256, GEMM_SMEM>>>(rxh, rxl, (size_t)1024 * 512,
                                        wqh, wql, 0,
                                        yptr, (size_t)1024 * 640, 640, 512);
    }

    prep_k<<<(BSZ * 1024 * 64 + 255) / 256, 256>>>();
    { dim3 g(32, 1, BSZ); dim3 blk(32, 8); prep_vt<<<g, blk>>>(); }

    // attention
    { dim3 g(8, NH, BSZ); attn_mma<<<g, 256, ATTN_SMEM>>>(); }

    // GEMM2: out[dout][n] (M=512, N=1024 tokens, K=512), per batch
    {
        dim3 g(8, 4, BSZ);
        gemm_mma<<<g, 256, GEMM_SMEM>>>(woh, wol, 0,
                                        ohi, olo, (size_t)1024 * 512,
                                        out, (size_t)512 * 1024, 1024, 512);
    }
}

// round 7
// speedup vs baseline: 3.6178x; 1.0679x over previous
#include <cuda_runtime.h>
#include <cuda_bf16.h>
#include <cstdint>
#include <cstddef>
#include <math.h>

#define BSZ 8
#define NTOK 1024
#define NH 8

// ---------------------------------------------------------------------------
// Device scratch
// ---------------------------------------------------------------------------
__device__ __align__(16) __nv_bfloat16 g_rxh[BSZ * NTOK * 512];   // [b][n][d]
__device__ __align__(16) __nv_bfloat16 g_rxl[BSZ * NTOK * 512];
__device__ __align__(16) __nv_bfloat16 g_Wqh[640 * 512];          // [c][d] (Q rows pre-scaled)
__device__ __align__(16) __nv_bfloat16 g_Wql[640 * 512];
__device__ __align__(16) __nv_bfloat16 g_Woh[512 * 512];          // [dout][c]
__device__ __align__(16) __nv_bfloat16 g_Wol[512 * 512];
__device__ __align__(16) __nv_bfloat16 g_Qh[BSZ * NTOK * 512];    // [b][n][hk] scaled
__device__ __align__(16) __nv_bfloat16 g_Ql[BSZ * NTOK * 512];
__device__ __align__(16) __nv_bfloat16 g_Kh[BSZ * NTOK * 64];     // [b][m][kd]
__device__ __align__(16) __nv_bfloat16 g_Kl[BSZ * NTOK * 64];
__device__ __align__(16) __nv_bfloat16 g_Vth[BSZ * 64 * NTOK];    // [b][v][m]
__device__ __align__(16) __nv_bfloat16 g_Vtl[BSZ * 64 * NTOK];
__device__ __align__(16) __nv_bfloat16 g_Ohi[BSZ * NTOK * 512];   // [b][n][c]
__device__ __align__(16) __nv_bfloat16 g_Olo[BSZ * NTOK * 512];

// ---------------------------------------------------------------------------
// helpers
// ---------------------------------------------------------------------------
#define SWZ(x) ((x) ^ (((x) >> 3) & 0x70))

__device__ __forceinline__ uint32_t s2u(const void* p) {
    uint32_t a;
    asm("{ .reg .u64 t; cvta.to.shared.u64 t, %1; cvt.u32.u64 %0, t; }" : "=r"(a) : "l"(p));
    return a;
}
__device__ __forceinline__ void cpasync16(uint32_t dst, const void* src) {
    asm volatile("cp.async.cg.shared.global [%0], [%1], 16;" :: "r"(dst), "l"(src));
}
#define CP_COMMIT() asm volatile("cp.async.commit_group;")
#define CP_WAIT(n)  asm volatile("cp.async.wait_group %0;" :: "n"(n))

__device__ __forceinline__ void ldsm4(uint32_t& a, uint32_t& b, uint32_t& c, uint32_t& d,
                                      uint32_t addr) {
    asm volatile("ldmatrix.sync.aligned.m8n8.x4.shared.b16 {%0,%1,%2,%3}, [%4];"
                 : "=r"(a), "=r"(b), "=r"(c), "=r"(d) : "r"(addr));
}
__device__ __forceinline__ void mma16816(float* d, const uint32_t* a, const uint32_t* b) {
    asm volatile(
        "mma.sync.aligned.m16n8k16.row.col.f32.bf16.bf16.f32 "
        "{%0,%1,%2,%3}, {%4,%5,%6,%7}, {%8,%9}, {%0,%1,%2,%3};"
        : "+f"(d[0]), "+f"(d[1]), "+f"(d[2]), "+f"(d[3])
        : "r"(a[0]), "r"(a[1]), "r"(a[2]), "r"(a[3]), "r"(b[0]), "r"(b[1]));
}
__device__ __forceinline__ void split2(float v, __nv_bfloat16& h, __nv_bfloat16& l) {
    h = __float2bfloat16(v);
    l = __float2bfloat16(v - __bfloat162float(h));
}
__device__ __forceinline__ uint32_t packbf2(__nv_bfloat16 lo, __nv_bfloat16 hi) {
    __nv_bfloat162 t(lo, hi);
    return *reinterpret_cast<uint32_t*>(&t);
}
// pack two floats -> bf16x2 (lo half = f0, hi half = f1)
__device__ __forceinline__ uint32_t cvt2bf(float f0, float f1) {
    uint32_t r;
    asm("cvt.rn.bf16x2.f32 %0, %1, %2;" : "=r"(r) : "f"(f1), "f"(f0));
    return r;
}
// hi/lo split of a float pair using packed cvt
__device__ __forceinline__ void split_pair(float f0, float f1, uint32_t& hp, uint32_t& lp) {
    hp = cvt2bf(f0, f1);
    float h0 = __uint_as_float(hp << 16);
    float h1 = __uint_as_float(hp & 0xffff0000u);
    lp = cvt2bf(f0 - h0, f1 - h1);
}

// ---------------------------------------------------------------------------
// prep kernels
// ---------------------------------------------------------------------------
__global__ void conv_x(const float* __restrict__ x) {
    __shared__ float t[32][33];
    const int b = blockIdx.z, d0 = blockIdx.y * 32, n0 = blockIdx.x * 32;
    const int txx = threadIdx.x, tyy = threadIdx.y;
    #pragma unroll
    for (int r = 0; r < 4; r++)
        t[tyy + r * 8][txx] = x[((size_t)b * 512 + d0 + tyy + r * 8) * 1024 + n0 + txx];
    __syncthreads();
    #pragma unroll
    for (int r = 0; r < 4; r++) {
        int n = n0 + tyy + r * 8;
        __nv_bfloat16 h, l;
        split2(t[txx][tyy + r * 8], h, l);
        size_t o = ((size_t)b * 1024 + n) * 512 + d0 + txx;
        g_rxh[o] = h; g_rxl[o] = l;
    }
}

__global__ void prep_wqkv(const float* __restrict__ qp, const float* __restrict__ kp,
                          const float* __restrict__ vp) {
    int idx = blockIdx.x * 256 + threadIdx.x;
    if (idx >= 640 * 512) return;
    int c = idx >> 9, d = idx & 511;
    float v;
    if (c < 512)      v = qp[c * 512 + d] * 0.125f;   // fold softmax scale into Wq
    else if (c < 576) v = kp[d * 64 + (c - 512)];
    else              v = vp[d * 64 + (c - 576)];
    split2(v, g_Wqh[idx], g_Wql[idx]);
}

__global__ void prep_wout(const float* __restrict__ wout) {
    int idx = blockIdx.x * 256 + threadIdx.x;
    if (idx >= 512 * 512) return;
    split2(wout[idx], g_Woh[idx], g_Wol[idx]);
}

// ---------------------------------------------------------------------------
// GEMM1 (QKV) with fused split epilogue. CTA 128x128, 8 warps, K-chunk 64,
// cp.async double buffer. Writes Qh/Ql, Kh/Kl, Vth/Vtl directly.
// ---------------------------------------------------------------------------
#define GEMM_SMEM (2 * 65536)

__global__ void __launch_bounds__(256)
gemm_qkv() {
    extern __shared__ char sm[];
    const uint32_t sbase = s2u(sm);
    const uint32_t OFF[4] = {0u, 16384u, 32768u, 49152u};

    const int tid = threadIdx.x, lane = tid & 31, wid = tid >> 5;
    const int b = blockIdx.z, mt = blockIdx.y, nt = blockIdx.x;
    const int wm = (wid >> 1) * 32, wn = (wid & 1) * 64;
    const int K = 512;

    const __nv_bfloat16* gsrc[4] = {
        g_rxh + (size_t)b * 1024 * 512 + (size_t)mt * 128 * 512,
        g_rxl + (size_t)b * 1024 * 512 + (size_t)mt * 128 * 512,
        g_Wqh + (size_t)nt * 128 * 512,
        g_Wql + (size_t)nt * 128 * 512};

    auto load_chunk = [&](int stage, int kc) {
        const uint32_t stbase = sbase + stage * 65536;
        #pragma unroll
        for (int t = 0; t < 4; t++) {
            #pragma unroll
            for (int i = 0; i < 4; i++) {
                int c = tid + i * 256;
                int row = c >> 3, u = c & 7;
                cpasync16(stbase + OFF[t] + SWZ((uint32_t)(row * 128 + u * 16)),
                          gsrc[t] + (size_t)row * K + kc + u * 8);
            }
        }
        CP_COMMIT();
    };

    float acc[2][8][4];
    #pragma unroll
    for (int i = 0; i < 2; i++)
        #pragma unroll
        for (int j = 0; j < 8; j++)
            #pragma unroll
            for (int e = 0; e < 4; e++) acc[i][j][e] = 0.f;

    load_chunk(0, 0);
    for (int c = 0; c < 8; c++) {
        if (c + 1 < 8) { load_chunk((c + 1) & 1, (c + 1) << 6); CP_WAIT(1); }
        else           { CP_WAIT(0); }
        __syncthreads();
        const uint32_t stb = sbase + (c & 1) * 65536;

        #pragma unroll
        for (int ks = 0; ks < 4; ks++) {
            uint32_t ah[2][4], al[2][4], bh[8][2], bl[8][2];
            #pragma unroll
            for (int mf = 0; mf < 2; mf++) {
                int row = wm + mf * 16 + (lane & 15);
                int cu = ks * 2 + (lane >> 4);
                uint32_t off = SWZ((uint32_t)(row * 128 + cu * 16));
                ldsm4(ah[mf][0], ah[mf][1], ah[mf][2], ah[mf][3], stb + OFF[0] + off);
                ldsm4(al[mf][0], al[mf][1], al[mf][2], al[mf][3], stb + OFF[1] + off);
            }
            #pragma unroll
            for (int nf2 = 0; nf2 < 4; nf2++) {
                int row = wn + nf2 * 16 + (lane & 7) + ((lane >> 4) << 3);
                int cu = ks * 2 + ((lane >> 3) & 1);
                uint32_t off = SWZ((uint32_t)(row * 128 + cu * 16));
                ldsm4(bh[2 * nf2][0], bh[2 * nf2][1], bh[2 * nf2 + 1][0], bh[2 * nf2 + 1][1],
                      stb + OFF[2] + off);
                ldsm4(bl[2 * nf2][0], bl[2 * nf2][1], bl[2 * nf2 + 1][0], bl[2 * nf2 + 1][1],
                      stb + OFF[3] + off);
            }
            #pragma unroll
            for (int mf = 0; mf < 2; mf++)
                #pragma unroll
                for (int nf = 0; nf < 8; nf++) {
                    mma16816(acc[mf][nf], ah[mf], bh[nf]);
                    mma16816(acc[mf][nf], ah[mf], bl[nf]);
                    mma16816(acc[mf][nf], al[mf], bh[nf]);
                }
        }
        __syncthreads();
    }

    // fused routing epilogue
    #pragma unroll
    for (int mf = 0; mf < 2; mf++) {
        int r0 = mt * 128 + wm + mf * 16 + (lane >> 2);
        #pragma unroll
        for (int nf = 0; nf < 8; nf++) {
            int col = nt * 128 + wn + nf * 8 + 2 * (lane & 3);
            const float* a = acc[mf][nf];
            if (nt < 4) {                       // Q (already scaled via weights)
                uint32_t hp, lp;
                split_pair(a[0], a[1], hp, lp);
                size_t o0 = ((size_t)b * 1024 + r0) * 512 + col;
                *(uint32_t*)&g_Qh[o0] = hp; *(uint32_t*)&g_Ql[o0] = lp;
                split_pair(a[2], a[3], hp, lp);
                size_t o1 = ((size_t)b * 1024 + r0 + 8) * 512 + col;
                *(uint32_t*)&g_Qh[o1] = hp; *(uint32_t*)&g_Ql[o1] = lp;
            } else if (wn == 0) {               // K (cols 512..575)
                int kc = col - 512;
                uint32_t hp, lp;
                split_pair(a[0], a[1], hp, lp);
                size_t o0 = ((size_t)b * 1024 + r0) * 64 + kc;
                *(uint32_t*)&g_Kh[o0] = hp; *(uint32_t*)&g_Kl[o0] = lp;
                split_pair(a[2], a[3], hp, lp);
                size_t o1 = ((size_t)b * 1024 + r0 + 8) * 64 + kc;
                *(uint32_t*)&g_Kh[o1] = hp; *(uint32_t*)&g_Kl[o1] = lp;
            } else {                            // V transposed (cols 576..639)
                int v0 = col - 576;
                #pragma unroll
                for (int e = 0; e < 4; e++) {
                    int vv = v0 + (e & 1);
                    int mm = r0 + (e >> 1) * 8;
                    __nv_bfloat16 h, l;
                    split2(a[e], h, l);
                    size_t o = ((size_t)b * 64 + vv) * 1024 + mm;
                    g_Vth[o] = h; g_Vtl[o] = l;
                }
            }
        }
    }
}

// ---------------------------------------------------------------------------
// generic GEMM (float output) for out-projection
// ---------------------------------------------------------------------------
__global__ void __launch_bounds__(256)
gemm_mma(const __nv_bfloat16* __restrict__ Ahi, const __nv_bfloat16* __restrict__ Alo,
         size_t sA,
         const __nv_bfloat16* __restrict__ Bhi, const __nv_bfloat16* __restrict__ Blo,
         size_t sB,
         float* __restrict__ D, size_t sD, int ldd, int K) {
    extern __shared__ char sm[];
    const uint32_t sbase = s2u(sm);
    const uint32_t OFF[4] = {0u, 16384u, 32768u, 49152u};

    const int tid = threadIdx.x, lane = tid & 31, wid = tid >> 5;
    const int b = blockIdx.z, mt = blockIdx.y, nt = blockIdx.x;
    const int wm = (wid >> 1) * 32, wn = (wid & 1) * 64;

    const __nv_bfloat16* gsrc[4] = {
        Ahi + b * sA + (size_t)mt * 128 * K,
        Alo + b * sA + (size_t)mt * 128 * K,
        Bhi + b * sB + (size_t)nt * 128 * K,
        Blo + b * sB + (size_t)nt * 128 * K};

    auto load_chunk = [&](int stage, int kc) {
        const uint32_t stbase = sbase + stage * 65536;
        #pragma unroll
        for (int t = 0; t < 4; t++) {
            #pragma unroll
            for (int i = 0; i < 4; i++) {
                int c = tid + i * 256;
                int row = c >> 3, u = c & 7;
                cpasync16(stbase + OFF[t] + SWZ((uint32_t)(row * 128 + u * 16)),
                          gsrc[t] + (size_t)row * K + kc + u * 8);
            }
        }
        CP_COMMIT();
    };

    float acc[2][8][4];
    #pragma unroll
    for (int i = 0; i < 2; i++)
        #pragma unroll
        for (int j = 0; j < 8; j++)
            #pragma unroll
            for (int e = 0; e < 4; e++) acc[i][j][e] = 0.f;

    const int nchunks = K >> 6;
    load_chunk(0, 0);
    for (int c = 0; c < nchunks; c++) {
        if (c + 1 < nchunks) { load_chunk((c + 1) & 1, (c + 1) << 6); CP_WAIT(1); }
        else                 { CP_WAIT(0); }
        __syncthreads();
        const uint32_t stb = sbase + (c & 1) * 65536;

        #pragma unroll
        for (int ks = 0; ks < 4; ks++) {
            uint32_t ah[2][4], al[2][4], bh[8][2], bl[8][2];
            #pragma unroll
            for (int mf = 0; mf < 2; mf++) {
                int row = wm + mf * 16 + (lane & 15);
                int cu = ks * 2 + (lane >> 4);
                uint32_t off = SWZ((uint32_t)(row * 128 + cu * 16));
                ldsm4(ah[mf][0], ah[mf][1], ah[mf][2], ah[mf][3], stb + OFF[0] + off);
                ldsm4(al[mf][0], al[mf][1], al[mf][2], al[mf][3], stb + OFF[1] + off);
            }
            #pragma unroll
            for (int nf2 = 0; nf2 < 4; nf2++) {
                int row = wn + nf2 * 16 + (lane & 7) + ((lane >> 4) << 3);
                int cu = ks * 2 + ((lane >> 3) & 1);
                uint32_t off = SWZ((uint32_t)(row * 128 + cu * 16));
                ldsm4(bh[2 * nf2][0], bh[2 * nf2][1], bh[2 * nf2 + 1][0], bh[2 * nf2 + 1][1],
                      stb + OFF[2] + off);
                ldsm4(bl[2 * nf2][0], bl[2 * nf2][1], bl[2 * nf2 + 1][0], bl[2 * nf2 + 1][1],
                      stb + OFF[3] + off);
            }
            #pragma unroll
            for (int mf = 0; mf < 2; mf++)
                #pragma unroll
                for (int nf = 0; nf < 8; nf++) {
                    mma16816(acc[mf][nf], ah[mf], bh[nf]);
                    mma16816(acc[mf][nf], ah[mf], bl[nf]);
                    mma16816(acc[mf][nf], al[mf], bh[nf]);
                }
        }
        __syncthreads();
    }

    #pragma unroll
    for (int mf = 0; mf < 2; mf++) {
        int r0 = mt * 128 + wm + mf * 16 + (lane >> 2);
        #pragma unroll
        for (int nf = 0; nf < 8; nf++) {
            int col = nt * 128 + wn + nf * 8 + 2 * (lane & 3);
            *(float2*)(D + b * sD + (size_t)r0 * ldd + col) =
                make_float2(acc[mf][nf][0], acc[mf][nf][1]);
            *(float2*)(D + b * sD + (size_t)(r0 + 8) * ldd + col) =
                make_float2(acc[mf][nf][2], acc[mf][nf][3]);
        }
    }
}

// ---------------------------------------------------------------------------
// HMMA flash attention; Q loaded pre-split via cp.async.
// smem: Qh 0 | Ql 16K | stages 32K + s*32K: {Kh 0 | Kl 8K | Vh 16K | Vl 24K}
// ---------------------------------------------------------------------------
#define ATTN_SMEM (98304)

__global__ void __launch_bounds__(256)
attn_mma() {
    extern __shared__ char sm[];
    const uint32_t sbase = s2u(sm);
    const uint32_t QH = 0u, QL = 16384u, STG = 32768u;

    const int tid = threadIdx.x, lane = tid & 31, wid = tid >> 5;
    const int b = blockIdx.z, h = blockIdx.y, n0 = blockIdx.x * 128;

    const __nv_bfloat16* Qhb = g_Qh + ((size_t)b * 1024 + n0) * 512 + h * 64;
    const __nv_bfloat16* Qlb = g_Ql + ((size_t)b * 1024 + n0) * 512 + h * 64;
    const __nv_bfloat16* Khb = g_Kh + (size_t)b * 1024 * 64;
    const __nv_bfloat16* Klb = g_Kl + (size_t)b * 1024 * 64;
    const __nv_bfloat16* Vhb = g_Vth + (size_t)b * 64 * 1024;
    const __nv_bfloat16* Vlb = g_Vtl + (size_t)b * 64 * 1024;

    // Q load (group 0)
    #pragma unroll
    for (int i = 0; i < 4; i++) {
        int c = tid + i * 256;          // 1024 16B units
        int row = c >> 3, u = c & 7;
        uint32_t off = SWZ((uint32_t)(row * 128 + u * 16));
        cpasync16(sbase + QH + off, Qhb + (size_t)row * 512 + u * 8);
        cpasync16(sbase + QL + off, Qlb + (size_t)row * 512 + u * 8);
    }
    CP_COMMIT();

    auto load_kv = [&](int stage, int m0) {
        const uint32_t stb = sbase + STG + stage * 32768u;
        #pragma unroll
        for (int i = 0; i < 2; i++) {
            int c = tid + i * 256;
            int row = c >> 3, u = c & 7;
            uint32_t off = SWZ((uint32_t)(row * 128 + u * 16));
            cpasync16(stb + off,          Khb + (size_t)(m0 + row) * 64 + u * 8);
            cpasync16(stb + 8192u + off,  Klb + (size_t)(m0 + row) * 64 + u * 8);
            cpasync16(stb + 16384u + off, Vhb + (size_t)row * 1024 + m0 + u * 8);
            cpasync16(stb + 24576u + off, Vlb + (size_t)row * 1024 + m0 + u * 8);
        }
        CP_COMMIT();
    };

    load_kv(0, 0);

    float m_i[2], l_i[2], oacc[8][4];
    m_i[0] = m_i[1] = -1e30f;
    l_i[0] = l_i[1] = 0.f;
    #pragma unroll
    for (int nf = 0; nf < 8; nf++)
        #pragma unroll
        for (int e = 0; e < 4; e++) oacc[nf][e] = 0.f;

    for (int ic = 0; ic < 16; ic++) {
        if (ic + 1 < 16) { load_kv((ic + 1) & 1, (ic + 1) * 64); CP_WAIT(1); }
        else             { CP_WAIT(0); }
        __syncthreads();
        const uint32_t KHs = STG + (uint32_t)(ic & 1) * 32768u;
        const uint32_t KLs = KHs + 8192u, VHs = KHs + 16384u, VLs = KHs + 24576u;

        // ---- S = Q K^T ----
        float sacc[8][4];
        #pragma unroll
        for (int nf = 0; nf < 8; nf++)
            #pragma unroll
            for (int e = 0; e < 4; e++) sacc[nf][e] = 0.f;

        #pragma unroll
        for (int ks = 0; ks < 4; ks++) {
            uint32_t qh[4], ql[4], bh[8][2], bl[8][2];
            {
                int row = wid * 16 + (lane & 15);
                int cu = ks * 2 + (lane >> 4);
                uint32_t off = SWZ((uint32_t)(row * 128 + cu * 16));
                ldsm4(qh[0], qh[1], qh[2], qh[3], sbase + QH + off);
                ldsm4(ql[0], ql[1], ql[2], ql[3], sbase + QL + off);
            }
            #pragma unroll
            for (int nf2 = 0; nf2 < 4; nf2++) {
                int row = nf2 * 16 + (lane & 7) + ((lane >> 4) << 3);
                int cu = ks * 2 + ((lane >> 3) & 1);
                uint32_t off = SWZ((uint32_t)(row * 128 + cu * 16));
                ldsm4(bh[2 * nf2][0], bh[2 * nf2][1], bh[2 * nf2 + 1][0], bh[2 * nf2 + 1][1],
                      sbase + KHs + off);
                ldsm4(bl[2 * nf2][0], bl[2 * nf2][1], bl[2 * nf2 + 1][0], bl[2 * nf2 + 1][1],
                      sbase + KLs + off);
            }
            #pragma unroll
            for (int nf = 0; nf < 8; nf++) {
                mma16816(sacc[nf], qh, bh[nf]);
                mma16816(sacc[nf], qh, bl[nf]);
                mma16816(sacc[nf], ql, bh[nf]);
            }
        }

        // ---- online softmax ----
        float mx0 = -1e30f, mx1 = -1e30f;
        #pragma unroll
        for (int nf = 0; nf < 8; nf++) {
            mx0 = fmaxf(mx0, fmaxf(sacc[nf][0], sacc[nf][1]));
            mx1 = fmaxf(mx1, fmaxf(sacc[nf][2], sacc[nf][3]));
        }
        mx0 = fmaxf(mx0, __shfl_xor_sync(0xffffffffu, mx0, 1));
        mx0 = fmaxf(mx0, __shfl_xor_sync(0xffffffffu, mx0, 2));
        mx1 = fmaxf(mx1, __shfl_xor_sync(0xffffffffu, mx1, 1));
        mx1 = fmaxf(mx1, __shfl_xor_sync(0xffffffffu, mx1, 2));
        float mn0 = fmaxf(m_i[0], mx0), mn1 = fmaxf(m_i[1], mx1);
        float c0 = __expf(m_i[0] - mn0), c1 = __expf(m_i[1] - mn1);
        float sum0 = 0.f, sum1 = 0.f;
        #pragma unroll
        for (int nf = 0; nf < 8; nf++) {
            sacc[nf][0] = __expf(sacc[nf][0] - mn0);
            sacc[nf][1] = __expf(sacc[nf][1] - mn0);
            sacc[nf][2] = __expf(sacc[nf][2] - mn1);
            sacc[nf][3] = __expf(sacc[nf][3] - mn1);
            sum0 += sacc[nf][0] + sacc[nf][1];
            sum1 += sacc[nf][2] + sacc[nf][3];
        }
        sum0 += __shfl_xor_sync(0xffffffffu, sum0, 1);
        sum0 += __shfl_xor_sync(0xffffffffu, sum0, 2);
        sum1 += __shfl_xor_sync(0xffffffffu, sum1, 1);
        sum1 += __shfl_xor_sync(0xffffffffu, sum1, 2);
        l_i[0] = l_i[0] * c0 + sum0;
        l_i[1] = l_i[1] * c1 + sum1;
        m_i[0] = mn0; m_i[1] = mn1;
        #pragma unroll
        for (int nf = 0; nf < 8; nf++) {
            oacc[nf][0] *= c0; oacc[nf][1] *= c0;
            oacc[nf][2] *= c1; oacc[nf][3] *= c1;
        }

        // ---- O += P V (P split via packed cvt, stays in registers) ----
        #pragma unroll
        for (int ks = 0; ks < 4; ks++) {
            uint32_t pah[4], pal[4];
            {
                const float* f0 = sacc[2 * ks];
                const float* f1 = sacc[2 * ks + 1];
                split_pair(f0[0], f0[1], pah[0], pal[0]);
                split_pair(f0[2], f0[3], pah[1], pal[1]);
                split_pair(f1[0], f1[1], pah[2], pal[2]);
                split_pair(f1[2], f1[3], pah[3], pal[3]);
            }
            uint32_t vh[8][2], vl[8][2];
            #pragma unroll
            for (int nf2 = 0; nf2 < 4; nf2++) {
                int row = nf2 * 16 + (lane & 7) + ((lane >> 4) << 3);
                int cu = ks * 2 + ((lane >> 3) & 1);
                uint32_t off = SWZ((uint32_t)(row * 128 + cu * 16));
                ldsm4(vh[2 * nf2][0], vh[2 * nf2][1], vh[2 * nf2 + 1][0], vh[2 * nf2 + 1][1],
                      sbase + VHs + off);
                ldsm4(vl[2 * nf2][0], vl[2 * nf2][1], vl[2 * nf2 + 1][0], vl[2 * nf2 + 1][1],
                      sbase + VLs + off);
            }
            #pragma unroll
            for (int nf = 0; nf < 8; nf++) {
                mma16816(oacc[nf], pah, vh[nf]);
                mma16816(oacc[nf], pah, vl[nf]);
                mma16816(oacc[nf], pal, vh[nf]);
            }
        }
        __syncthreads();
    }

    // ---- epilogue ----
    float inv0 = 1.0f / l_i[0], inv1 = 1.0f / l_i[1];
    int nr0 = n0 + wid * 16 + (lane >> 2);
    #pragma unroll
    for (int nf = 0; nf < 8; nf++) {
        int col = h * 64 + nf * 8 + 2 * (lane & 3);
        uint32_t hp, lp;
        split_pair(oacc[nf][0] * inv0, oacc[nf][1] * inv0, hp, lp);
        size_t base0 = ((size_t)b * 1024 + nr0) * 512 + col;
        *(uint32_t*)&g_Ohi[base0] = hp;
        *(uint32_t*)&g_Olo[base0] = lp;
        split_pair(oacc[nf][2] * inv1, oacc[nf][3] * inv1, hp, lp);
        size_t base1 = ((size_t)b * 1024 + nr0 + 8) * 512 + col;
        *(uint32_t*)&g_Ohi[base1] = hp;
        *(uint32_t*)&g_Olo[base1] = lp;
    }
}

// ---------------------------------------------------------------------------
extern "C" void kernel_launch(void* const* d_in, const int* in_sizes, int n_in,
                              void* d_out, int out_size) {
    const float* x    = (const float*)d_in[0];
    const float* qp   = (const float*)d_in[1];
    const float* kp   = (const float*)d_in[2];
    const float* vp   = (const float*)d_in[3];
    const float* wout = (const float*)d_in[4];
    float* out = (float*)d_out;

    cudaFuncSetAttribute(gemm_qkv, cudaFuncAttributeMaxDynamicSharedMemorySize, GEMM_SMEM);
    cudaFuncSetAttribute(gemm_mma, cudaFuncAttributeMaxDynamicSharedMemorySize, GEMM_SMEM);
    cudaFuncSetAttribute(attn_mma, cudaFuncAttributeMaxDynamicSharedMemorySize, ATTN_SMEM);

    { dim3 g(32, 16, BSZ); dim3 blk(32, 8); conv_x<<<g, blk>>>(x); }
    prep_wqkv<<<(640 * 512 + 255) / 256, 256>>>(qp, kp, vp);
    prep_wout<<<(512 * 512 + 255) / 256, 256>>>(wout);

    __nv_bfloat16 *woh, *wol, *ohi, *olo;
    cudaGetSymbolAddress((void**)&woh, g_Woh);
    cudaGetSymbolAddress((void**)&wol, g_Wol);
    cudaGetSymbolAddress((void**)&ohi, g_Ohi);
    cudaGetSymbolAddress((void**)&olo, g_Olo);

    // GEMM1 + fused QKV split/routing
    { dim3 g(5, 8, BSZ); gemm_qkv<<<g, 256, GEMM_SMEM>>>(); }

    // attention
    { dim3 g(8, NH, BSZ); attn_mma<<<g, 256, ATTN_SMEM>>>(); }

    // GEMM2: out[dout][n] (M=512, N=1024 tokens, K=512), per batch
    {
        dim3 g(8, 4, BSZ);
        gemm_mma<<<g, 256, GEMM_SMEM>>>(woh, wol, 0,
                                        ohi, olo, (size_t)1024 * 512,
                                        out, (size_t)512 * 1024, 1024, 512);
    }
}

// round 9
// speedup vs baseline: 3.8878x; 1.0746x over previous
#include <cuda_runtime.h>
#include <cuda_bf16.h>
#include <cstdint>
#include <cstddef>
#include <math.h>

#define BSZ 8
#define NTOK 1024
#define NH 8

// ---------------------------------------------------------------------------
// Device scratch
// ---------------------------------------------------------------------------
__device__ __align__(16) __nv_bfloat16 g_rxh[BSZ * NTOK * 512];   // [b][n][d]
__device__ __align__(16) __nv_bfloat16 g_rxl[BSZ * NTOK * 512];
__device__ __align__(16) __nv_bfloat16 g_Wqh[640 * 512];          // [c][d] (Q rows pre-scaled)
__device__ __align__(16) __nv_bfloat16 g_Wql[640 * 512];
__device__ __align__(16) __nv_bfloat16 g_Woh[512 * 512];          // [dout][c]
__device__ __align__(16) __nv_bfloat16 g_Wol[512 * 512];
__device__ __align__(16) __nv_bfloat16 g_Qh[BSZ * NTOK * 512];    // [b][n][hk] scaled
__device__ __align__(16) __nv_bfloat16 g_Ql[BSZ * NTOK * 512];
__device__ __align__(16) __nv_bfloat16 g_Kh[BSZ * NTOK * 64];     // [b][m][kd]
__device__ __align__(16) __nv_bfloat16 g_Kl[BSZ * NTOK * 64];
__device__ __align__(16) __nv_bfloat16 g_Vth[BSZ * 64 * NTOK];    // [b][v][m]
__device__ __align__(16) __nv_bfloat16 g_Vtl[BSZ * 64 * NTOK];
__device__ __align__(16) __nv_bfloat16 g_Ohi[BSZ * NTOK * 512];   // [b][n][c]
__device__ __align__(16) __nv_bfloat16 g_Olo[BSZ * NTOK * 512];

// ---------------------------------------------------------------------------
// helpers
// ---------------------------------------------------------------------------
#define SWZ(x) ((x) ^ (((x) >> 3) & 0x70))

__device__ __forceinline__ uint32_t s2u(const void* p) {
    uint32_t a;
    asm("{ .reg .u64 t; cvta.to.shared.u64 t, %1; cvt.u32.u64 %0, t; }" : "=r"(a) : "l"(p));
    return a;
}
__device__ __forceinline__ void cpasync16(uint32_t dst, const void* src) {
    asm volatile("cp.async.cg.shared.global [%0], [%1], 16;" :: "r"(dst), "l"(src));
}
#define CP_COMMIT() asm volatile("cp.async.commit_group;")
#define CP_WAIT(n)  asm volatile("cp.async.wait_group %0;" :: "n"(n))

__device__ __forceinline__ void ldsm4(uint32_t& a, uint32_t& b, uint32_t& c, uint32_t& d,
                                      uint32_t addr) {
    asm volatile("ldmatrix.sync.aligned.m8n8.x4.shared.b16 {%0,%1,%2,%3}, [%4];"
                 : "=r"(a), "=r"(b), "=r"(c), "=r"(d) : "r"(addr));
}
__device__ __forceinline__ void mma16816(float* d, const uint32_t* a, const uint32_t* b) {
    asm volatile(
        "mma.sync.aligned.m16n8k16.row.col.f32.bf16.bf16.f32 "
        "{%0,%1,%2,%3}, {%4,%5,%6,%7}, {%8,%9}, {%0,%1,%2,%3};"
        : "+f"(d[0]), "+f"(d[1]), "+f"(d[2]), "+f"(d[3])
        : "r"(a[0]), "r"(a[1]), "r"(a[2]), "r"(a[3]), "r"(b[0]), "r"(b[1]));
}
__device__ __forceinline__ void split2(float v, __nv_bfloat16& h, __nv_bfloat16& l) {
    h = __float2bfloat16(v);
    l = __float2bfloat16(v - __bfloat162float(h));
}
__device__ __forceinline__ uint32_t cvt2bf(float f0, float f1) {
    uint32_t r;
    asm("cvt.rn.bf16x2.f32 %0, %1, %2;" : "=r"(r) : "f"(f1), "f"(f0));
    return r;
}
__device__ __forceinline__ void split_pair(float f0, float f1, uint32_t& hp, uint32_t& lp) {
    hp = cvt2bf(f0, f1);
    float h0 = __uint_as_float(hp << 16);
    float h1 = __uint_as_float(hp & 0xffff0000u);
    lp = cvt2bf(f0 - h0, f1 - h1);
}

// ---------------------------------------------------------------------------
// prep kernels
// ---------------------------------------------------------------------------
__global__ void conv_x(const float* __restrict__ x) {
    __shared__ float t[32][33];
    const int b = blockIdx.z, d0 = blockIdx.y * 32, n0 = blockIdx.x * 32;
    const int txx = threadIdx.x, tyy = threadIdx.y;
    #pragma unroll
    for (int r = 0; r < 4; r++)
        t[tyy + r * 8][txx] = x[((size_t)b * 512 + d0 + tyy + r * 8) * 1024 + n0 + txx];
    __syncthreads();
    #pragma unroll
    for (int r = 0; r < 4; r++) {
        int n = n0 + tyy + r * 8;
        __nv_bfloat16 h, l;
        split2(t[txx][tyy + r * 8], h, l);
        size_t o = ((size_t)b * 1024 + n) * 512 + d0 + txx;
        g_rxh[o] = h; g_rxl[o] = l;
    }
}

__global__ void prep_wqkv(const float* __restrict__ qp, const float* __restrict__ kp,
                          const float* __restrict__ vp) {
    int idx = blockIdx.x * 256 + threadIdx.x;
    if (idx >= 640 * 512) return;
    int c = idx >> 9, d = idx & 511;
    float v;
    if (c < 512)      v = qp[c * 512 + d] * 0.125f;
    else if (c < 576) v = kp[d * 64 + (c - 512)];
    else              v = vp[d * 64 + (c - 576)];
    split2(v, g_Wqh[idx], g_Wql[idx]);
}

__global__ void prep_wout(const float* __restrict__ wout) {
    int idx = blockIdx.x * 256 + threadIdx.x;
    if (idx >= 512 * 512) return;
    split2(wout[idx], g_Woh[idx], g_Wol[idx]);
}

// ---------------------------------------------------------------------------
// GEMM core (4-warp CTA, 64x128 tile, 2-stage cp.async, 2 CTAs/SM)
// stage layout: Ah 0 | Al 8K | Bh 16K | Bl 32K   (stage = 48K)
// warps: 2m x 2n -> warp tile 32x64
// ---------------------------------------------------------------------------
#define GEMM_SMEM (2 * 49152)
#define STAGE_SZ  49152u

struct GemmAcc { float a[2][8][4]; };

template <typename Epi>
__device__ __forceinline__ void gemm_core(
    const __nv_bfloat16* Ahi, const __nv_bfloat16* Alo,
    const __nv_bfloat16* Bhi, const __nv_bfloat16* Blo,
    int K, Epi epi) {
    extern __shared__ char sm[];
    const uint32_t sbase = s2u(sm);
    const uint32_t OFF[4] = {0u, 8192u, 16384u, 32768u};

    const int tid = threadIdx.x, lane = tid & 31, wid = tid >> 5;
    const int wm = (wid >> 1) * 32, wn = (wid & 1) * 64;

    const __nv_bfloat16* gsrc[4] = {Ahi, Alo, Bhi, Blo};

    auto load_chunk = [&](int stage, int kc) {
        const uint32_t stbase = sbase + stage * STAGE_SZ;
        #pragma unroll
        for (int t = 0; t < 2; t++) {
            #pragma unroll
            for (int i = 0; i < 4; i++) {
                int c = tid + i * 128;
                int row = c >> 3, u = c & 7;
                cpasync16(stbase + OFF[t] + SWZ((uint32_t)(row * 128 + u * 16)),
                          gsrc[t] + (size_t)row * K + kc + u * 8);
            }
        }
        #pragma unroll
        for (int t = 2; t < 4; t++) {
            #pragma unroll
            for (int i = 0; i < 8; i++) {
                int c = tid + i * 128;
                int row = c >> 3, u = c & 7;
                cpasync16(stbase + OFF[t] + SWZ((uint32_t)(row * 128 + u * 16)),
                          gsrc[t] + (size_t)row * K + kc + u * 8);
            }
        }
        CP_COMMIT();
    };

    GemmAcc acc;
    #pragma unroll
    for (int i = 0; i < 2; i++)
        #pragma unroll
        for (int j = 0; j < 8; j++)
            #pragma unroll
            for (int e = 0; e < 4; e++) acc.a[i][j][e] = 0.f;

    const int nchunks = K >> 6;
    load_chunk(0, 0);
    for (int c = 0; c < nchunks; c++) {
        if (c + 1 < nchunks) { load_chunk((c + 1) & 1, (c + 1) << 6); CP_WAIT(1); }
        else                 { CP_WAIT(0); }
        __syncthreads();
        const uint32_t stb = sbase + (c & 1) * STAGE_SZ;

        #pragma unroll
        for (int ks = 0; ks < 4; ks++) {
            uint32_t ah[2][4], al[2][4], bh[8][2], bl[8][2];
            #pragma unroll
            for (int mf = 0; mf < 2; mf++) {
                int row = wm + mf * 16 + (lane & 15);
                int cu = ks * 2 + (lane >> 4);
                uint32_t off = SWZ((uint32_t)(row * 128 + cu * 16));
                ldsm4(ah[mf][0], ah[mf][1], ah[mf][2], ah[mf][3], stb + OFF[0] + off);
                ldsm4(al[mf][0], al[mf][1], al[mf][2], al[mf][3], stb + OFF[1] + off);
            }
            #pragma unroll
            for (int nf2 = 0; nf2 < 4; nf2++) {
                int row = wn + nf2 * 16 + (lane & 7) + ((lane >> 4) << 3);
                int cu = ks * 2 + ((lane >> 3) & 1);
                uint32_t off = SWZ((uint32_t)(row * 128 + cu * 16));
                ldsm4(bh[2 * nf2][0], bh[2 * nf2][1], bh[2 * nf2 + 1][0], bh[2 * nf2 + 1][1],
                      stb + OFF[2] + off);
                ldsm4(bl[2 * nf2][0], bl[2 * nf2][1], bl[2 * nf2 + 1][0], bl[2 * nf2 + 1][1],
                      stb + OFF[3] + off);
            }
            #pragma unroll
            for (int mf = 0; mf < 2; mf++)
                #pragma unroll
                for (int nf = 0; nf < 8; nf++) {
                    mma16816(acc.a[mf][nf], ah[mf], bh[nf]);
                    mma16816(acc.a[mf][nf], ah[mf], bl[nf]);
                    mma16816(acc.a[mf][nf], al[mf], bh[nf]);
                }
        }
        __syncthreads();
    }
    epi(acc, wm, wn, lane);
}

// epilogue functor: QKV split + routing
struct QkvEpi {
    int b, mt, nt;
    __device__ void operator()(GemmAcc& acc, int wm, int wn, int lane) const {
        #pragma unroll
        for (int mf = 0; mf < 2; mf++) {
            int r0 = mt * 64 + wm + mf * 16 + (lane >> 2);
            #pragma unroll
            for (int nf = 0; nf < 8; nf++) {
                int col = nt * 128 + wn + nf * 8 + 2 * (lane & 3);
                const float* a = acc.a[mf][nf];
                if (nt < 4) {
                    uint32_t hp, lp;
                    split_pair(a[0], a[1], hp, lp);
                    size_t o0 = ((size_t)b * 1024 + r0) * 512 + col;
                    *(uint32_t*)&g_Qh[o0] = hp; *(uint32_t*)&g_Ql[o0] = lp;
                    split_pair(a[2], a[3], hp, lp);
                    size_t o1 = ((size_t)b * 1024 + r0 + 8) * 512 + col;
                    *(uint32_t*)&g_Qh[o1] = hp; *(uint32_t*)&g_Ql[o1] = lp;
                } else if (wn == 0) {
                    int kc = col - 512;
                    uint32_t hp, lp;
                    split_pair(a[0], a[1], hp, lp);
                    size_t o0 = ((size_t)b * 1024 + r0) * 64 + kc;
                    *(uint32_t*)&g_Kh[o0] = hp; *(uint32_t*)&g_Kl[o0] = lp;
                    split_pair(a[2], a[3], hp, lp);
                    size_t o1 = ((size_t)b * 1024 + r0 + 8) * 64 + kc;
                    *(uint32_t*)&g_Kh[o1] = hp; *(uint32_t*)&g_Kl[o1] = lp;
                } else {
                    int v0 = col - 576;
                    #pragma unroll
                    for (int e = 0; e < 4; e++) {
                        int vv = v0 + (e & 1);
                        int mm = r0 + (e >> 1) * 8;
                        __nv_bfloat16 h, l;
                        split2(a[e], h, l);
                        size_t o = ((size_t)b * 64 + vv) * 1024 + mm;
                        g_Vth[o] = h; g_Vtl[o] = l;
                    }
                }
            }
        }
    }
};

// epilogue functor: float output
struct OutEpi {
    int b, mt, nt;
    float* D;
    __device__ void operator()(GemmAcc& acc, int wm, int wn, int lane) const {
        #pragma unroll
        for (int mf = 0; mf < 2; mf++) {
            int r0 = mt * 64 + wm + mf * 16 + (lane >> 2);
            #pragma unroll
            for (int nf = 0; nf < 8; nf++) {
                int col = nt * 128 + wn + nf * 8 + 2 * (lane & 3);
                *(float2*)(D + ((size_t)b * 512 + r0) * 1024 + col) =
                    make_float2(acc.a[mf][nf][0], acc.a[mf][nf][1]);
                *(float2*)(D + ((size_t)b * 512 + r0 + 8) * 1024 + col) =
                    make_float2(acc.a[mf][nf][2], acc.a[mf][nf][3]);
            }
        }
    }
};

// GEMM1: QKV with fused split/routing epilogue
__global__ void __launch_bounds__(128)
gemm_qkv() {
    const int b = blockIdx.z, mt = blockIdx.y, nt = blockIdx.x;
    QkvEpi epi{b, mt, nt};
    gemm_core(
        g_rxh + ((size_t)b * 1024 + mt * 64) * 512,
        g_rxl + ((size_t)b * 1024 + mt * 64) * 512,
        g_Wqh + (size_t)nt * 128 * 512,
        g_Wql + (size_t)nt * 128 * 512,
        512, epi);
}

// GEMM2: out-projection (float output)
__global__ void __launch_bounds__(128)
gemm_out(float* __restrict__ D) {
    const int b = blockIdx.z, mt = blockIdx.y, nt = blockIdx.x;
    OutEpi epi{b, mt, nt, D};
    gemm_core(
        g_Woh + (size_t)mt * 64 * 512,
        g_Wol + (size_t)mt * 64 * 512,
        g_Ohi + ((size_t)b * 1024 + nt * 128) * 512,
        g_Olo + ((size_t)b * 1024 + nt * 128) * 512,
        512, epi);
}

// ---------------------------------------------------------------------------
// HMMA flash attention: 4-warp CTA, 64 q-rows, 2-stage KV, 2 CTAs/SM.
// smem: Qh 0 | Ql 8K | stages 16K + s*32K: {Kh 0 | Kl 8K | Vh 16K | Vl 24K}
// total 80K
// ---------------------------------------------------------------------------
#define ATTN_SMEM 81920

__global__ void __launch_bounds__(128)
attn_mma() {
    extern __shared__ char sm[];
    const uint32_t sbase = s2u(sm);
    const uint32_t QH = 0u, QL = 8192u, STG = 16384u;

    const int tid = threadIdx.x, lane = tid & 31, wid = tid >> 5;
    const int b = blockIdx.z, h = blockIdx.y, n0 = blockIdx.x * 64;

    const __nv_bfloat16* Qhb = g_Qh + ((size_t)b * 1024 + n0) * 512 + h * 64;
    const __nv_bfloat16* Qlb = g_Ql + ((size_t)b * 1024 + n0) * 512 + h * 64;
    const __nv_bfloat16* Khb = g_Kh + (size_t)b * 1024 * 64;
    const __nv_bfloat16* Klb = g_Kl + (size_t)b * 1024 * 64;
    const __nv_bfloat16* Vhb = g_Vth + (size_t)b * 64 * 1024;
    const __nv_bfloat16* Vlb = g_Vtl + (size_t)b * 64 * 1024;

    // Q load: 64 rows x 8 units, hi+lo
    #pragma unroll
    for (int i = 0; i < 4; i++) {
        int c = tid + i * 128;
        int row = c >> 3, u = c & 7;
        uint32_t off = SWZ((uint32_t)(row * 128 + u * 16));
        cpasync16(sbase + QH + off, Qhb + (size_t)row * 512 + u * 8);
        cpasync16(sbase + QL + off, Qlb + (size_t)row * 512 + u * 8);
    }
    CP_COMMIT();

    auto load_kv = [&](int stage, int m0) {
        const uint32_t stb = sbase + STG + stage * 32768u;
        #pragma unroll
        for (int i = 0; i < 4; i++) {
            int c = tid + i * 128;
            int row = c >> 3, u = c & 7;
            uint32_t off = SWZ((uint32_t)(row * 128 + u * 16));
            cpasync16(stb + off,          Khb + (size_t)(m0 + row) * 64 + u * 8);
            cpasync16(stb + 8192u + off,  Klb + (size_t)(m0 + row) * 64 + u * 8);
            cpasync16(stb + 16384u + off, Vhb + (size_t)row * 1024 + m0 + u * 8);
            cpasync16(stb + 24576u + off, Vlb + (size_t)row * 1024 + m0 + u * 8);
        }
        CP_COMMIT();
    };

    load_kv(0, 0);

    float m_i[2], l_i[2], oacc[8][4];
    m_i[0] = m_i[1] = -1e30f;
    l_i[0] = l_i[1] = 0.f;
    #pragma unroll
    for (int nf = 0; nf < 8; nf++)
        #pragma unroll
        for (int e = 0; e < 4; e++) oacc[nf][e] = 0.f;

    for (int ic = 0; ic < 16; ic++) {
        if (ic + 1 < 16) { load_kv((ic + 1) & 1, (ic + 1) * 64); CP_WAIT(1); }
        else             { CP_WAIT(0); }
        __syncthreads();
        const uint32_t KHs = STG + (uint32_t)(ic & 1) * 32768u;
        const uint32_t KLs = KHs + 8192u, VHs = KHs + 16384u, VLs = KHs + 24576u;

        // ---- S = Q K^T ----
        float sacc[8][4];
        #pragma unroll
        for (int nf = 0; nf < 8; nf++)
            #pragma unroll
            for (int e = 0; e < 4; e++) sacc[nf][e] = 0.f;

        #pragma unroll
        for (int ks = 0; ks < 4; ks++) {
            uint32_t qh[4], ql[4], bh[8][2], bl[8][2];
            {
                int row = wid * 16 + (lane & 15);
                int cu = ks * 2 + (lane >> 4);
                uint32_t off = SWZ((uint32_t)(row * 128 + cu * 16));
                ldsm4(qh[0], qh[1], qh[2], qh[3], sbase + QH + off);
                ldsm4(ql[0], ql[1], ql[2], ql[3], sbase + QL + off);
            }
            #pragma unroll
            for (int nf2 = 0; nf2 < 4; nf2++) {
                int row = nf2 * 16 + (lane & 7) + ((lane >> 4) << 3);
                int cu = ks * 2 + ((lane >> 3) & 1);
                uint32_t off = SWZ((uint32_t)(row * 128 + cu * 16));
                ldsm4(bh[2 * nf2][0], bh[2 * nf2][1], bh[2 * nf2 + 1][0], bh[2 * nf2 + 1][1],
                      sbase + KHs + off);
                ldsm4(bl[2 * nf2][0], bl[2 * nf2][1], bl[2 * nf2 + 1][0], bl[2 * nf2 + 1][1],
                      sbase + KLs + off);
            }
            #pragma unroll
            for (int nf = 0; nf < 8; nf++) {
                mma16816(sacc[nf], qh, bh[nf]);
                mma16816(sacc[nf], qh, bl[nf]);
                mma16816(sacc[nf], ql, bh[nf]);
            }
        }

        // ---- online softmax ----
        float mx0 = -1e30f, mx1 = -1e30f;
        #pragma unroll
        for (int nf = 0; nf < 8; nf++) {
            mx0 = fmaxf(mx0, fmaxf(sacc[nf][0], sacc[nf][1]));
            mx1 = fmaxf(mx1, fmaxf(sacc[nf][2], sacc[nf][3]));
        }
        mx0 = fmaxf(mx0, __shfl_xor_sync(0xffffffffu, mx0, 1));
        mx0 = fmaxf(mx0, __shfl_xor_sync(0xffffffffu, mx0, 2));
        mx1 = fmaxf(mx1, __shfl_xor_sync(0xffffffffu, mx1, 1));
        mx1 = fmaxf(mx1, __shfl_xor_sync(0xffffffffu, mx1, 2));
        float mn0 = fmaxf(m_i[0], mx0), mn1 = fmaxf(m_i[1], mx1);
        float c0 = __expf(m_i[0] - mn0), c1 = __expf(m_i[1] - mn1);
        float sum0 = 0.f, sum1 = 0.f;
        #pragma unroll
        for (int nf = 0; nf < 8; nf++) {
            sacc[nf][0] = __expf(sacc[nf][0] - mn0);
            sacc[nf][1] = __expf(sacc[nf][1] - mn0);
            sacc[nf][2] = __expf(sacc[nf][2] - mn1);
            sacc[nf][3] = __expf(sacc[nf][3] - mn1);
            sum0 += sacc[nf][0] + sacc[nf][1];
            sum1 += sacc[nf][2] + sacc[nf][3];
        }
        sum0 += __shfl_xor_sync(0xffffffffu, sum0, 1);
        sum0 += __shfl_xor_sync(0xffffffffu, sum0, 2);
        sum1 += __shfl_xor_sync(0xffffffffu, sum1, 1);
        sum1 += __shfl_xor_sync(0xffffffffu, sum1, 2);
        l_i[0] = l_i[0] * c0 + sum0;
        l_i[1] = l_i[1] * c1 + sum1;
        m_i[0] = mn0; m_i[1] = mn1;
        #pragma unroll
        for (int nf = 0; nf < 8; nf++) {
            oacc[nf][0] *= c0; oacc[nf][1] *= c0;
            oacc[nf][2] *= c1; oacc[nf][3] *= c1;
        }

        // ---- O += P V ----
        #pragma unroll
        for (int ks = 0; ks < 4; ks++) {
            uint32_t pah[4], pal[4];
            {
                const float* f0 = sacc[2 * ks];
                const float* f1 = sacc[2 * ks + 1];
                split_pair(f0[0], f0[1], pah[0], pal[0]);
                split_pair(f0[2], f0[3], pah[1], pal[1]);
                split_pair(f1[0], f1[1], pah[2], pal[2]);
                split_pair(f1[2], f1[3], pah[3], pal[3]);
            }
            uint32_t vh[8][2], vl[8][2];
            #pragma unroll
            for (int nf2 = 0; nf2 < 4; nf2++) {
                int row = nf2 * 16 + (lane & 7) + ((lane >> 4) << 3);
                int cu = ks * 2 + ((lane >> 3) & 1);
                uint32_t off = SWZ((uint32_t)(row * 128 + cu * 16));
                ldsm4(vh[2 * nf2][0], vh[2 * nf2][1], vh[2 * nf2 + 1][0], vh[2 * nf2 + 1][1],
                      sbase + VHs + off);
                ldsm4(vl[2 * nf2][0], vl[2 * nf2][1], vl[2 * nf2 + 1][0], vl[2 * nf2 + 1][1],
                      sbase + VLs + off);
            }
            #pragma unroll
            for (int nf = 0; nf < 8; nf++) {
                mma16816(oacc[nf], pah, vh[nf]);
                mma16816(oacc[nf], pah, vl[nf]);
                mma16816(oacc[nf], pal, vh[nf]);
            }
        }
        __syncthreads();
    }

    // ---- epilogue ----
    float inv0 = 1.0f / l_i[0], inv1 = 1.0f / l_i[1];
    int nr0 = n0 + wid * 16 + (lane >> 2);
    #pragma unroll
    for (int nf = 0; nf < 8; nf++) {
        int col = h * 64 + nf * 8 + 2 * (lane & 3);
        uint32_t hp, lp;
        split_pair(oacc[nf][0] * inv0, oacc[nf][1] * inv0, hp, lp);
        size_t base0 = ((size_t)b * 1024 + nr0) * 512 + col;
        *(uint32_t*)&g_Ohi[base0] = hp;
        *(uint32_t*)&g_Olo[base0] = lp;
        split_pair(oacc[nf][2] * inv1, oacc[nf][3] * inv1, hp, lp);
        size_t base1 = ((size_t)b * 1024 + nr0 + 8) * 512 + col;
        *(uint32_t*)&g_Ohi[base1] = hp;
        *(uint32_t*)&g_Olo[base1] = lp;
    }
}

// ---------------------------------------------------------------------------
extern "C" void kernel_launch(void* const* d_in, const int* in_sizes, int n_in,
                              void* d_out, int out_size) {
    const float* x    = (const float*)d_in[0];
    const float* qp   = (const float*)d_in[1];
    const float* kp   = (const float*)d_in[2];
    const float* vp   = (const float*)d_in[3];
    const float* wout = (const float*)d_in[4];
    float* out = (float*)d_out;

    cudaFuncSetAttribute(gemm_qkv, cudaFuncAttributeMaxDynamicSharedMemorySize, GEMM_SMEM);
    cudaFuncSetAttribute(gemm_out, cudaFuncAttributeMaxDynamicSharedMemorySize, GEMM_SMEM);
    cudaFuncSetAttribute(attn_mma, cudaFuncAttributeMaxDynamicSharedMemorySize, ATTN_SMEM);

    { dim3 g(32, 16, BSZ); dim3 blk(32, 8); conv_x<<<g, blk>>>(x); }
    prep_wqkv<<<(640 * 512 + 255) / 256, 256>>>(qp, kp, vp);
    prep_wout<<<(512 * 512 + 255) / 256, 256>>>(wout);

    // GEMM1 + fused QKV split/routing: M=1024 (16 tiles), N=640 (5 tiles)
    { dim3 g(5, 16, BSZ); gemm_qkv<<<g, 128, GEMM_SMEM>>>(); }

    // attention: 16 q-tiles x 8 heads x 8 batches
    { dim3 g(16, NH, BSZ); attn_mma<<<g, 128, ATTN_SMEM>>>(); }

    // GEMM2: M=512 (8 tiles), N=1024 (8 tiles)
    { dim3 g(8, 8, BSZ); gemm_out<<<g, 128, GEMM_SMEM>>>(out); }
}

// round 10
// speedup vs baseline: 3.9320x; 1.0114x over previous
#include <cuda_runtime.h>
#include <cuda_bf16.h>
#include <cstdint>
#include <cstddef>
#include <math.h>

#define BSZ 8
#define NTOK 1024
#define NH 8

// ---------------------------------------------------------------------------
// Device scratch
// ---------------------------------------------------------------------------
__device__ __align__(16) __nv_bfloat16 g_rxh[BSZ * NTOK * 512];   // [b][n][d]
__device__ __align__(16) __nv_bfloat16 g_rxl[BSZ * NTOK * 512];
__device__ __align__(16) __nv_bfloat16 g_Wqh[640 * 512];          // [c][d] (Q rows pre-scaled)
__device__ __align__(16) __nv_bfloat16 g_Wql[640 * 512];
__device__ __align__(16) __nv_bfloat16 g_Woh[512 * 512];          // [dout][c]
__device__ __align__(16) __nv_bfloat16 g_Wol[512 * 512];
__device__ __align__(16) __nv_bfloat16 g_Qh[BSZ * NTOK * 512];    // [b][n][hk] scaled
__device__ __align__(16) __nv_bfloat16 g_Ql[BSZ * NTOK * 512];
__device__ __align__(16) __nv_bfloat16 g_Kh[BSZ * NTOK * 64];     // [b][m][kd]
__device__ __align__(16) __nv_bfloat16 g_Kl[BSZ * NTOK * 64];
__device__ __align__(16) __nv_bfloat16 g_Vth[BSZ * 64 * NTOK];    // [b][v][m]
__device__ __align__(16) __nv_bfloat16 g_Vtl[BSZ * 64 * NTOK];
__device__ __align__(16) __nv_bfloat16 g_Ohi[BSZ * NTOK * 512];   // [b][n][c]
__device__ __align__(16) __nv_bfloat16 g_Olo[BSZ * NTOK * 512];

// ---------------------------------------------------------------------------
// helpers
// ---------------------------------------------------------------------------
#define SWZ(x) ((x) ^ (((x) >> 3) & 0x70))

__device__ __forceinline__ uint32_t s2u(const void* p) {
    uint32_t a;
    asm("{ .reg .u64 t; cvta.to.shared.u64 t, %1; cvt.u32.u64 %0, t; }" : "=r"(a) : "l"(p));
    return a;
}
__device__ __forceinline__ void cpasync16(uint32_t dst, const void* src) {
    asm volatile("cp.async.cg.shared.global [%0], [%1], 16;" :: "r"(dst), "l"(src));
}
#define CP_COMMIT() asm volatile("cp.async.commit_group;")
#define CP_WAIT(n)  asm volatile("cp.async.wait_group %0;" :: "n"(n))

__device__ __forceinline__ void ldsm4(uint32_t& a, uint32_t& b, uint32_t& c, uint32_t& d,
                                      uint32_t addr) {
    asm volatile("ldmatrix.sync.aligned.m8n8.x4.shared.b16 {%0,%1,%2,%3}, [%4];"
                 : "=r"(a), "=r"(b), "=r"(c), "=r"(d) : "r"(addr));
}
__device__ __forceinline__ void mma16816(float* d, const uint32_t* a, const uint32_t* b) {
    asm volatile(
        "mma.sync.aligned.m16n8k16.row.col.f32.bf16.bf16.f32 "
        "{%0,%1,%2,%3}, {%4,%5,%6,%7}, {%8,%9}, {%0,%1,%2,%3};"
        : "+f"(d[0]), "+f"(d[1]), "+f"(d[2]), "+f"(d[3])
        : "r"(a[0]), "r"(a[1]), "r"(a[2]), "r"(a[3]), "r"(b[0]), "r"(b[1]));
}
__device__ __forceinline__ void split2(float v, __nv_bfloat16& h, __nv_bfloat16& l) {
    h = __float2bfloat16(v);
    l = __float2bfloat16(v - __bfloat162float(h));
}
__device__ __forceinline__ uint32_t cvt2bf(float f0, float f1) {
    uint32_t r;
    asm("cvt.rn.bf16x2.f32 %0, %1, %2;" : "=r"(r) : "f"(f1), "f"(f0));
    return r;
}
__device__ __forceinline__ void split_pair(float f0, float f1, uint32_t& hp, uint32_t& lp) {
    hp = cvt2bf(f0, f1);
    float h0 = __uint_as_float(hp << 16);
    float h1 = __uint_as_float(hp & 0xffff0000u);
    lp = cvt2bf(f0 - h0, f1 - h1);
}

// ---------------------------------------------------------------------------
// prep kernels
// ---------------------------------------------------------------------------
__global__ void conv_x(const float* __restrict__ x) {
    __shared__ float t[32][33];
    const int b = blockIdx.z, d0 = blockIdx.y * 32, n0 = blockIdx.x * 32;
    const int txx = threadIdx.x, tyy = threadIdx.y;
    #pragma unroll
    for (int r = 0; r < 4; r++)
        t[tyy + r * 8][txx] = x[((size_t)b * 512 + d0 + tyy + r * 8) * 1024 + n0 + txx];
    __syncthreads();
    #pragma unroll
    for (int r = 0; r < 4; r++) {
        int n = n0 + tyy + r * 8;
        __nv_bfloat16 h, l;
        split2(t[txx][tyy + r * 8], h, l);
        size_t o = ((size_t)b * 1024 + n) * 512 + d0 + txx;
        g_rxh[o] = h; g_rxl[o] = l;
    }
}

// merged weight prep: [0, 640*512) -> Wqkv, [640*512, +512*512) -> Wout
__global__ void prep_w(const float* __restrict__ qp, const float* __restrict__ kp,
                       const float* __restrict__ vp, const float* __restrict__ wout) {
    int idx = blockIdx.x * 256 + threadIdx.x;
    if (idx < 640 * 512) {
        int c = idx >> 9, d = idx & 511;
        float v;
        if (c < 512)      v = qp[c * 512 + d] * 0.125f;
        else if (c < 576) v = kp[d * 64 + (c - 512)];
        else              v = vp[d * 64 + (c - 576)];
        split2(v, g_Wqh[idx], g_Wql[idx]);
    } else {
        int j = idx - 640 * 512;
        if (j < 512 * 512) split2(wout[j], g_Woh[j], g_Wol[j]);
    }
}

// ---------------------------------------------------------------------------
// GEMM core (4-warp CTA, 64x128 tile, 2-stage cp.async, 2 CTAs/SM)
// stage layout: Ah 0 | Al 8K | Bh 16K | Bl 32K   (stage = 48K)
// ---------------------------------------------------------------------------
#define GEMM_SMEM (2 * 49152)
#define STAGE_SZ  49152u

struct GemmAcc { float a[2][8][4]; };

template <typename Epi>
__device__ __forceinline__ void gemm_core(
    const __nv_bfloat16* Ahi, const __nv_bfloat16* Alo,
    const __nv_bfloat16* Bhi, const __nv_bfloat16* Blo,
    int K, Epi epi) {
    extern __shared__ char sm[];
    const uint32_t sbase = s2u(sm);
    const uint32_t OFF[4] = {0u, 8192u, 16384u, 32768u};

    const int tid = threadIdx.x, lane = tid & 31, wid = tid >> 5;
    const int wm = (wid >> 1) * 32, wn = (wid & 1) * 64;

    const __nv_bfloat16* gsrc[4] = {Ahi, Alo, Bhi, Blo};

    auto load_chunk = [&](int stage, int kc) {
        const uint32_t stbase = sbase + stage * STAGE_SZ;
        #pragma unroll
        for (int t = 0; t < 2; t++) {
            #pragma unroll
            for (int i = 0; i < 4; i++) {
                int c = tid + i * 128;
                int row = c >> 3, u = c & 7;
                cpasync16(stbase + OFF[t] + SWZ((uint32_t)(row * 128 + u * 16)),
                          gsrc[t] + (size_t)row * K + kc + u * 8);
            }
        }
        #pragma unroll
        for (int t = 2; t < 4; t++) {
            #pragma unroll
            for (int i = 0; i < 8; i++) {
                int c = tid + i * 128;
                int row = c >> 3, u = c & 7;
                cpasync16(stbase + OFF[t] + SWZ((uint32_t)(row * 128 + u * 16)),
                          gsrc[t] + (size_t)row * K + kc + u * 8);
            }
        }
        CP_COMMIT();
    };

    GemmAcc acc;
    #pragma unroll
    for (int i = 0; i < 2; i++)
        #pragma unroll
        for (int j = 0; j < 8; j++)
            #pragma unroll
            for (int e = 0; e < 4; e++) acc.a[i][j][e] = 0.f;

    const int nchunks = K >> 6;
    load_chunk(0, 0);
    for (int c = 0; c < nchunks; c++) {
        if (c + 1 < nchunks) { load_chunk((c + 1) & 1, (c + 1) << 6); CP_WAIT(1); }
        else                 { CP_WAIT(0); }
        __syncthreads();
        const uint32_t stb = sbase + (c & 1) * STAGE_SZ;

        #pragma unroll
        for (int ks = 0; ks < 4; ks++) {
            uint32_t ah[2][4], al[2][4], bh[8][2], bl[8][2];
            #pragma unroll
            for (int mf = 0; mf < 2; mf++) {
                int row = wm + mf * 16 + (lane & 15);
                int cu = ks * 2 + (lane >> 4);
                uint32_t off = SWZ((uint32_t)(row * 128 + cu * 16));
                ldsm4(ah[mf][0], ah[mf][1], ah[mf][2], ah[mf][3], stb + OFF[0] + off);
                ldsm4(al[mf][0], al[mf][1], al[mf][2], al[mf][3], stb + OFF[1] + off);
            }
            #pragma unroll
            for (int nf2 = 0; nf2 < 4; nf2++) {
                int row = wn + nf2 * 16 + (lane & 7) + ((lane >> 4) << 3);
                int cu = ks * 2 + ((lane >> 3) & 1);
                uint32_t off = SWZ((uint32_t)(row * 128 + cu * 16));
                ldsm4(bh[2 * nf2][0], bh[2 * nf2][1], bh[2 * nf2 + 1][0], bh[2 * nf2 + 1][1],
                      stb + OFF[2] + off);
                ldsm4(bl[2 * nf2][0], bl[2 * nf2][1], bl[2 * nf2 + 1][0], bl[2 * nf2 + 1][1],
                      stb + OFF[3] + off);
            }
            #pragma unroll
            for (int mf = 0; mf < 2; mf++)
                #pragma unroll
                for (int nf = 0; nf < 8; nf++) {
                    mma16816(acc.a[mf][nf], ah[mf], bh[nf]);
                    mma16816(acc.a[mf][nf], ah[mf], bl[nf]);
                    mma16816(acc.a[mf][nf], al[mf], bh[nf]);
                }
        }
        __syncthreads();
    }
    epi(acc, wm, wn, lane);
}

// epilogue functor: QKV split + routing
struct QkvEpi {
    int b, mt, nt;
    __device__ void operator()(GemmAcc& acc, int wm, int wn, int lane) const {
        #pragma unroll
        for (int mf = 0; mf < 2; mf++) {
            int r0 = mt * 64 + wm + mf * 16 + (lane >> 2);
            #pragma unroll
            for (int nf = 0; nf < 8; nf++) {
                int col = nt * 128 + wn + nf * 8 + 2 * (lane & 3);
                const float* a = acc.a[mf][nf];
                if (nt < 4) {
                    uint32_t hp, lp;
                    split_pair(a[0], a[1], hp, lp);
                    size_t o0 = ((size_t)b * 1024 + r0) * 512 + col;
                    *(uint32_t*)&g_Qh[o0] = hp; *(uint32_t*)&g_Ql[o0] = lp;
                    split_pair(a[2], a[3], hp, lp);
                    size_t o1 = ((size_t)b * 1024 + r0 + 8) * 512 + col;
                    *(uint32_t*)&g_Qh[o1] = hp; *(uint32_t*)&g_Ql[o1] = lp;
                } else if (wn == 0) {
                    int kc = col - 512;
                    uint32_t hp, lp;
                    split_pair(a[0], a[1], hp, lp);
                    size_t o0 = ((size_t)b * 1024 + r0) * 64 + kc;
                    *(uint32_t*)&g_Kh[o0] = hp; *(uint32_t*)&g_Kl[o0] = lp;
                    split_pair(a[2], a[3], hp, lp);
                    size_t o1 = ((size_t)b * 1024 + r0 + 8) * 64 + kc;
                    *(uint32_t*)&g_Kh[o1] = hp; *(uint32_t*)&g_Kl[o1] = lp;
                } else {
                    int v0 = col - 576;
                    #pragma unroll
                    for (int e = 0; e < 4; e++) {
                        int vv = v0 + (e & 1);
                        int mm = r0 + (e >> 1) * 8;
                        __nv_bfloat16 h, l;
                        split2(a[e], h, l);
                        size_t o = ((size_t)b * 64 + vv) * 1024 + mm;
                        g_Vth[o] = h; g_Vtl[o] = l;
                    }
                }
            }
        }
    }
};

// epilogue functor: float output
struct OutEpi {
    int b, mt, nt;
    float* D;
    __device__ void operator()(GemmAcc& acc, int wm, int wn, int lane) const {
        #pragma unroll
        for (int mf = 0; mf < 2; mf++) {
            int r0 = mt * 64 + wm + mf * 16 + (lane >> 2);
            #pragma unroll
            for (int nf = 0; nf < 8; nf++) {
                int col = nt * 128 + wn + nf * 8 + 2 * (lane & 3);
                *(float2*)(D + ((size_t)b * 512 + r0) * 1024 + col) =
                    make_float2(acc.a[mf][nf][0], acc.a[mf][nf][1]);
                *(float2*)(D + ((size_t)b * 512 + r0 + 8) * 1024 + col) =
                    make_float2(acc.a[mf][nf][2], acc.a[mf][nf][3]);
            }
        }
    }
};

__global__ void __launch_bounds__(128)
gemm_qkv() {
    const int b = blockIdx.z, mt = blockIdx.y, nt = blockIdx.x;
    QkvEpi epi{b, mt, nt};
    gemm_core(
        g_rxh + ((size_t)b * 1024 + mt * 64) * 512,
        g_rxl + ((size_t)b * 1024 + mt * 64) * 512,
        g_Wqh + (size_t)nt * 128 * 512,
        g_Wql + (size_t)nt * 128 * 512,
        512, epi);
}

__global__ void __launch_bounds__(128)
gemm_out(float* __restrict__ D) {
    const int b = blockIdx.z, mt = blockIdx.y, nt = blockIdx.x;
    OutEpi epi{b, mt, nt, D};
    gemm_core(
        g_Woh + (size_t)mt * 64 * 512,
        g_Wol + (size_t)mt * 64 * 512,
        g_Ohi + ((size_t)b * 1024 + nt * 128) * 512,
        g_Olo + ((size_t)b * 1024 + nt * 128) * 512,
        512, epi);
}

// ---------------------------------------------------------------------------
// HMMA flash attention: 4-warp CTA, 128 q-rows (2 m-frags/warp), 2-stage KV.
// smem: Qh 0 | Ql 16K | stages 32K + s*32K: {Kh 0 | Kl 8K | Vh 16K | Vl 24K}
// total 96K -> 2 CTAs/SM
// ---------------------------------------------------------------------------
#define ATTN_SMEM 98304

__global__ void __launch_bounds__(128, 2)
attn_mma() {
    extern __shared__ char sm[];
    const uint32_t sbase = s2u(sm);
    const uint32_t QH = 0u, QL = 16384u, STG = 32768u;

    const int tid = threadIdx.x, lane = tid & 31, wid = tid >> 5;
    const int b = blockIdx.z, h = blockIdx.y, n0 = blockIdx.x * 128;

    const __nv_bfloat16* Qhb = g_Qh + ((size_t)b * 1024 + n0) * 512 + h * 64;
    const __nv_bfloat16* Qlb = g_Ql + ((size_t)b * 1024 + n0) * 512 + h * 64;
    const __nv_bfloat16* Khb = g_Kh + (size_t)b * 1024 * 64;
    const __nv_bfloat16* Klb = g_Kl + (size_t)b * 1024 * 64;
    const __nv_bfloat16* Vhb = g_Vth + (size_t)b * 64 * 1024;
    const __nv_bfloat16* Vlb = g_Vtl + (size_t)b * 64 * 1024;

    // Q load: 128 rows x 8 units, hi+lo
    #pragma unroll
    for (int i = 0; i < 8; i++) {
        int c = tid + i * 128;
        int row = c >> 3, u = c & 7;
        uint32_t off = SWZ((uint32_t)(row * 128 + u * 16));
        cpasync16(sbase + QH + off, Qhb + (size_t)row * 512 + u * 8);
        cpasync16(sbase + QL + off, Qlb + (size_t)row * 512 + u * 8);
    }
    CP_COMMIT();

    auto load_kv = [&](int stage, int m0) {
        const uint32_t stb = sbase + STG + stage * 32768u;
        #pragma unroll
        for (int i = 0; i < 4; i++) {
            int c = tid + i * 128;
            int row = c >> 3, u = c & 7;
            uint32_t off = SWZ((uint32_t)(row * 128 + u * 16));
            cpasync16(stb + off,          Khb + (size_t)(m0 + row) * 64 + u * 8);
            cpasync16(stb + 8192u + off,  Klb + (size_t)(m0 + row) * 64 + u * 8);
            cpasync16(stb + 16384u + off, Vhb + (size_t)row * 1024 + m0 + u * 8);
            cpasync16(stb + 24576u + off, Vlb + (size_t)row * 1024 + m0 + u * 8);
        }
        CP_COMMIT();
    };

    load_kv(0, 0);

    float m_i[2][2], l_i[2][2], oacc[2][8][4];
    #pragma unroll
    for (int mf = 0; mf < 2; mf++) {
        m_i[mf][0] = m_i[mf][1] = -1e30f;
        l_i[mf][0] = l_i[mf][1] = 0.f;
        #pragma unroll
        for (int nf = 0; nf < 8; nf++)
            #pragma unroll
            for (int e = 0; e < 4; e++) oacc[mf][nf][e] = 0.f;
    }

    for (int ic = 0; ic < 16; ic++) {
        if (ic + 1 < 16) { load_kv((ic + 1) & 1, (ic + 1) * 64); CP_WAIT(1); }
        else             { CP_WAIT(0); }
        __syncthreads();
        const uint32_t KHs = STG + (uint32_t)(ic & 1) * 32768u;
        const uint32_t KLs = KHs + 8192u, VHs = KHs + 16384u, VLs = KHs + 24576u;

        // ---- S = Q K^T ----
        float sacc[2][8][4];
        #pragma unroll
        for (int mf = 0; mf < 2; mf++)
            #pragma unroll
            for (int nf = 0; nf < 8; nf++)
                #pragma unroll
                for (int e = 0; e < 4; e++) sacc[mf][nf][e] = 0.f;

        #pragma unroll
        for (int ks = 0; ks < 4; ks++) {
            uint32_t qh[2][4], ql[2][4], bh[8][2], bl[8][2];
            #pragma unroll
            for (int mf = 0; mf < 2; mf++) {
                int row = wid * 32 + mf * 16 + (lane & 15);
                int cu = ks * 2 + (lane >> 4);
                uint32_t off = SWZ((uint32_t)(row * 128 + cu * 16));
                ldsm4(qh[mf][0], qh[mf][1], qh[mf][2], qh[mf][3], sbase + QH + off);
                ldsm4(ql[mf][0], ql[mf][1], ql[mf][2], ql[mf][3], sbase + QL + off);
            }
            #pragma unroll
            for (int nf2 = 0; nf2 < 4; nf2++) {
                int row = nf2 * 16 + (lane & 7) + ((lane >> 4) << 3);
                int cu = ks * 2 + ((lane >> 3) & 1);
                uint32_t off = SWZ((uint32_t)(row * 128 + cu * 16));
                ldsm4(bh[2 * nf2][0], bh[2 * nf2][1], bh[2 * nf2 + 1][0], bh[2 * nf2 + 1][1],
                      sbase + KHs + off);
                ldsm4(bl[2 * nf2][0], bl[2 * nf2][1], bl[2 * nf2 + 1][0], bl[2 * nf2 + 1][1],
                      sbase + KLs + off);
            }
            #pragma unroll
            for (int mf = 0; mf < 2; mf++)
                #pragma unroll
                for (int nf = 0; nf < 8; nf++) {
                    mma16816(sacc[mf][nf], qh[mf], bh[nf]);
                    mma16816(sacc[mf][nf], qh[mf], bl[nf]);
                    mma16816(sacc[mf][nf], ql[mf], bh[nf]);
                }
        }

        // ---- online softmax (per m-frag) ----
        #pragma unroll
        for (int mf = 0; mf < 2; mf++) {
            float mx0 = -1e30f, mx1 = -1e30f;
            #pragma unroll
            for (int nf = 0; nf < 8; nf++) {
                mx0 = fmaxf(mx0, fmaxf(sacc[mf][nf][0], sacc[mf][nf][1]));
                mx1 = fmaxf(mx1, fmaxf(sacc[mf][nf][2], sacc[mf][nf][3]));
            }
            mx0 = fmaxf(mx0, __shfl_xor_sync(0xffffffffu, mx0, 1));
            mx0 = fmaxf(mx0, __shfl_xor_sync(0xffffffffu, mx0, 2));
            mx1 = fmaxf(mx1, __shfl_xor_sync(0xffffffffu, mx1, 1));
            mx1 = fmaxf(mx1, __shfl_xor_sync(0xffffffffu, mx1, 2));
            float mn0 = fmaxf(m_i[mf][0], mx0), mn1 = fmaxf(m_i[mf][1], mx1);
            float c0 = __expf(m_i[mf][0] - mn0), c1 = __expf(m_i[mf][1] - mn1);
            float sum0 = 0.f, sum1 = 0.f;
            #pragma unroll
            for (int nf = 0; nf < 8; nf++) {
                sacc[mf][nf][0] = __expf(sacc[mf][nf][0] - mn0);
                sacc[mf][nf][1] = __expf(sacc[mf][nf][1] - mn0);
                sacc[mf][nf][2] = __expf(sacc[mf][nf][2] - mn1);
                sacc[mf][nf][3] = __expf(sacc[mf][nf][3] - mn1);
                sum0 += sacc[mf][nf][0] + sacc[mf][nf][1];
                sum1 += sacc[mf][nf][2] + sacc[mf][nf][3];
            }
            sum0 += __shfl_xor_sync(0xffffffffu, sum0, 1);
            sum0 += __shfl_xor_sync(0xffffffffu, sum0, 2);
            sum1 += __shfl_xor_sync(0xffffffffu, sum1, 1);
            sum1 += __shfl_xor_sync(0xffffffffu, sum1, 2);
            l_i[mf][0] = l_i[mf][0] * c0 + sum0;
            l_i[mf][1] = l_i[mf][1] * c1 + sum1;
            m_i[mf][0] = mn0; m_i[mf][1] = mn1;
            #pragma unroll
            for (int nf = 0; nf < 8; nf++) {
                oacc[mf][nf][0] *= c0; oacc[mf][nf][1] *= c0;
                oacc[mf][nf][2] *= c1; oacc[mf][nf][3] *= c1;
            }
        }

        // ---- O += P V ----
        #pragma unroll
        for (int ks = 0; ks < 4; ks++) {
            uint32_t pah[2][4], pal[2][4];
            #pragma unroll
            for (int mf = 0; mf < 2; mf++) {
                const float* f0 = sacc[mf][2 * ks];
                const float* f1 = sacc[mf][2 * ks + 1];
                split_pair(f0[0], f0[1], pah[mf][0], pal[mf][0]);
                split_pair(f0[2], f0[3], pah[mf][1], pal[mf][1]);
                split_pair(f1[0], f1[1], pah[mf][2], pal[mf][2]);
                split_pair(f1[2], f1[3], pah[mf][3], pal[mf][3]);
            }
            uint32_t vh[8][2], vl[8][2];
            #pragma unroll
            for (int nf2 = 0; nf2 < 4; nf2++) {
                int row = nf2 * 16 + (lane & 7) + ((lane >> 4) << 3);
                int cu = ks * 2 + ((lane >> 3) & 1);
                uint32_t off = SWZ((uint32_t)(row * 128 + cu * 16));
                ldsm4(vh[2 * nf2][0], vh[2 * nf2][1], vh[2 * nf2 + 1][0], vh[2 * nf2 + 1][1],
                      sbase + VHs + off);
                ldsm4(vl[2 * nf2][0], vl[2 * nf2][1], vl[2 * nf2 + 1][0], vl[2 * nf2 + 1][1],
                      sbase + VLs + off);
            }
            #pragma unroll
            for (int mf = 0; mf < 2; mf++)
                #pragma unroll
                for (int nf = 0; nf < 8; nf++) {
                    mma16816(oacc[mf][nf], pah[mf], vh[nf]);
                    mma16816(oacc[mf][nf], pah[mf], vl[nf]);
                    mma16816(oacc[mf][nf], pal[mf], vh[nf]);
                }
        }
        __syncthreads();
    }

    // ---- epilogue ----
    #pragma unroll
    for (int mf = 0; mf < 2; mf++) {
        float inv0 = 1.0f / l_i[mf][0], inv1 = 1.0f / l_i[mf][1];
        int nr0 = n0 + wid * 32 + mf * 16 + (lane >> 2);
        #pragma unroll
        for (int nf = 0; nf < 8; nf++) {
            int col = h * 64 + nf * 8 + 2 * (lane & 3);
            uint32_t hp, lp;
            split_pair(oacc[mf][nf][0] * inv0, oacc[mf][nf][1] * inv0, hp, lp);
            size_t base0 = ((size_t)b * 1024 + nr0) * 512 + col;
            *(uint32_t*)&g_Ohi[base0] = hp;
            *(uint32_t*)&g_Olo[base0] = lp;
            split_pair(oacc[mf][nf][2] * inv1, oacc[mf][nf][3] * inv1, hp, lp);
            size_t base1 = ((size_t)b * 1024 + nr0 + 8) * 512 + col;
            *(uint32_t*)&g_Ohi[base1] = hp;
            *(uint32_t*)&g_Olo[base1] = lp;
        }
    }
}

// ---------------------------------------------------------------------------
extern "C" void kernel_launch(void* const* d_in, const int* in_sizes, int n_in,
                              void* d_out, int out_size) {
    const float* x    = (const float*)d_in[0];
    const float* qp   = (const float*)d_in[1];
    const float* kp   = (const float*)d_in[2];
    const float* vp   = (const float*)d_in[3];
    const float* wout = (const float*)d_in[4];
    float* out = (float*)d_out;

    cudaFuncSetAttribute(gemm_qkv, cudaFuncAttributeMaxDynamicSharedMemorySize, GEMM_SMEM);
    cudaFuncSetAttribute(gemm_out, cudaFuncAttributeMaxDynamicSharedMemorySize, GEMM_SMEM);
    cudaFuncSetAttribute(attn_mma, cudaFuncAttributeMaxDynamicSharedMemorySize, ATTN_SMEM);

    { dim3 g(32, 16, BSZ); dim3 blk(32, 8); conv_x<<<g, blk>>>(x); }
    prep_w<<<(640 * 512 + 512 * 512 + 255) / 256, 256>>>(qp, kp, vp, wout);

    // GEMM1 + fused QKV split/routing: M=1024 (16 tiles), N=640 (5 tiles)
    { dim3 g(5, 16, BSZ); gemm_qkv<<<g, 128, GEMM_SMEM>>>(); }

    // attention: 8 q-tiles (128 rows) x 8 heads x 8 batches
    { dim3 g(8, NH, BSZ); attn_mma<<<g, 128, ATTN_SMEM>>>(); }

    // GEMM2: M=512 (8 tiles), N=1024 (8 tiles)
    { dim3 g(8, 8, BSZ); gemm_out<<<g, 128, GEMM_SMEM>>>(out); }
}

// round 11
// speedup vs baseline: 4.3074x; 1.0955x over previous
#include <cuda_runtime.h>
#include <cuda_bf16.h>
#include <cuda_fp16.h>
#include <cstdint>
#include <cstddef>
#include <math.h>

#define BSZ 8
#define NTOK 1024
#define NH 8

// ---------------------------------------------------------------------------
// Device scratch
// ---------------------------------------------------------------------------
__device__ __align__(16) __nv_bfloat16 g_rxh[BSZ * NTOK * 512];   // [b][n][d]
__device__ __align__(16) __nv_bfloat16 g_rxl[BSZ * NTOK * 512];
__device__ __align__(16) __nv_bfloat16 g_Wqh[640 * 512];          // [c][d] (Q rows pre-scaled)
__device__ __align__(16) __nv_bfloat16 g_Wql[640 * 512];
__device__ __align__(16) __nv_bfloat16 g_Woh[512 * 512];          // [dout][c]
__device__ __align__(16) __nv_bfloat16 g_Wol[512 * 512];
__device__ __align__(16) __nv_bfloat16 g_Qh[BSZ * NTOK * 512];    // [b][n][hk] scaled
__device__ __align__(16) __nv_bfloat16 g_Ql[BSZ * NTOK * 512];
__device__ __align__(16) __nv_bfloat16 g_Kh[BSZ * NTOK * 64];     // [b][m][kd]
__device__ __align__(16) __nv_bfloat16 g_Kl[BSZ * NTOK * 64];
__device__ __align__(16) __half g_Vth[BSZ * 64 * NTOK];           // [b][v][m] fp16 hi
__device__ __align__(16) __half g_Vtl[BSZ * 64 * NTOK];           // fp16 lo
__device__ __align__(16) __nv_bfloat16 g_Ohi[BSZ * NTOK * 512];   // [b][n][c]
__device__ __align__(16) __nv_bfloat16 g_Olo[BSZ * NTOK * 512];

// ---------------------------------------------------------------------------
// helpers
// ---------------------------------------------------------------------------
#define SWZ(x) ((x) ^ (((x) >> 3) & 0x70))

__device__ __forceinline__ uint32_t s2u(const void* p) {
    uint32_t a;
    asm("{ .reg .u64 t; cvta.to.shared.u64 t, %1; cvt.u32.u64 %0, t; }" : "=r"(a) : "l"(p));
    return a;
}
__device__ __forceinline__ void cpasync16(uint32_t dst, const void* src) {
    asm volatile("cp.async.cg.shared.global [%0], [%1], 16;" :: "r"(dst), "l"(src));
}
#define CP_COMMIT() asm volatile("cp.async.commit_group;")
#define CP_WAIT(n)  asm volatile("cp.async.wait_group %0;" :: "n"(n))

__device__ __forceinline__ void ldsm4(uint32_t& a, uint32_t& b, uint32_t& c, uint32_t& d,
                                      uint32_t addr) {
    asm volatile("ldmatrix.sync.aligned.m8n8.x4.shared.b16 {%0,%1,%2,%3}, [%4];"
                 : "=r"(a), "=r"(b), "=r"(c), "=r"(d) : "r"(addr));
}
__device__ __forceinline__ void mma16816(float* d, const uint32_t* a, const uint32_t* b) {
    asm volatile(
        "mma.sync.aligned.m16n8k16.row.col.f32.bf16.bf16.f32 "
        "{%0,%1,%2,%3}, {%4,%5,%6,%7}, {%8,%9}, {%0,%1,%2,%3};"
        : "+f"(d[0]), "+f"(d[1]), "+f"(d[2]), "+f"(d[3])
        : "r"(a[0]), "r"(a[1]), "r"(a[2]), "r"(a[3]), "r"(b[0]), "r"(b[1]));
}
__device__ __forceinline__ void mma16816h(float* d, const uint32_t* a, const uint32_t* b) {
    asm volatile(
        "mma.sync.aligned.m16n8k16.row.col.f32.f16.f16.f32 "
        "{%0,%1,%2,%3}, {%4,%5,%6,%7}, {%8,%9}, {%0,%1,%2,%3};"
        : "+f"(d[0]), "+f"(d[1]), "+f"(d[2]), "+f"(d[3])
        : "r"(a[0]), "r"(a[1]), "r"(a[2]), "r"(a[3]), "r"(b[0]), "r"(b[1]));
}
__device__ __forceinline__ void split2(float v, __nv_bfloat16& h, __nv_bfloat16& l) {
    h = __float2bfloat16(v);
    l = __float2bfloat16(v - __bfloat162float(h));
}
__device__ __forceinline__ uint32_t cvt2bf(float f0, float f1) {
    uint32_t r;
    asm("cvt.rn.bf16x2.f32 %0, %1, %2;" : "=r"(r) : "f"(f1), "f"(f0));
    return r;
}
// pack two floats -> fp16x2 (lo half = f0, hi half = f1)
__device__ __forceinline__ uint32_t cvt2h(float f0, float f1) {
    uint32_t r;
    asm("cvt.rn.f16x2.f32 %0, %1, %2;" : "=r"(r) : "f"(f1), "f"(f0));
    return r;
}
__device__ __forceinline__ void split_pair(float f0, float f1, uint32_t& hp, uint32_t& lp) {
    hp = cvt2bf(f0, f1);
    float h0 = __uint_as_float(hp << 16);
    float h1 = __uint_as_float(hp & 0xffff0000u);
    lp = cvt2bf(f0 - h0, f1 - h1);
}

// ---------------------------------------------------------------------------
// prep kernels
// ---------------------------------------------------------------------------
__global__ void conv_x(const float* __restrict__ x) {
    __shared__ float t[32][33];
    const int b = blockIdx.z, d0 = blockIdx.y * 32, n0 = blockIdx.x * 32;
    const int txx = threadIdx.x, tyy = threadIdx.y;
    #pragma unroll
    for (int r = 0; r < 4; r++)
        t[tyy + r * 8][txx] = x[((size_t)b * 512 + d0 + tyy + r * 8) * 1024 + n0 + txx];
    __syncthreads();
    #pragma unroll
    for (int r = 0; r < 4; r++) {
        int n = n0 + tyy + r * 8;
        __nv_bfloat16 h, l;
        split2(t[txx][tyy + r * 8], h, l);
        size_t o = ((size_t)b * 1024 + n) * 512 + d0 + txx;
        g_rxh[o] = h; g_rxl[o] = l;
    }
}

// merged weight prep
__global__ void prep_w(const float* __restrict__ qp, const float* __restrict__ kp,
                       const float* __restrict__ vp, const float* __restrict__ wout) {
    int idx = blockIdx.x * 256 + threadIdx.x;
    if (idx < 640 * 512) {
        int c = idx >> 9, d = idx & 511;
        float v;
        if (c < 512)      v = qp[c * 512 + d] * 0.125f;
        else if (c < 576) v = kp[d * 64 + (c - 512)];
        else              v = vp[d * 64 + (c - 576)];
        split2(v, g_Wqh[idx], g_Wql[idx]);
    } else {
        int j = idx - 640 * 512;
        if (j < 512 * 512) split2(wout[j], g_Woh[j], g_Wol[j]);
    }
}

// ---------------------------------------------------------------------------
// GEMM core (4-warp CTA, 64x128 tile, 2-stage cp.async, 2 CTAs/SM)
// ---------------------------------------------------------------------------
#define GEMM_SMEM (2 * 49152)
#define STAGE_SZ  49152u

struct GemmAcc { float a[2][8][4]; };

template <typename Epi>
__device__ __forceinline__ void gemm_core(
    const __nv_bfloat16* Ahi, const __nv_bfloat16* Alo,
    const __nv_bfloat16* Bhi, const __nv_bfloat16* Blo,
    int K, Epi epi) {
    extern __shared__ char sm[];
    const uint32_t sbase = s2u(sm);
    const uint32_t OFF[4] = {0u, 8192u, 16384u, 32768u};

    const int tid = threadIdx.x, lane = tid & 31, wid = tid >> 5;
    const int wm = (wid >> 1) * 32, wn = (wid & 1) * 64;

    const __nv_bfloat16* gsrc[4] = {Ahi, Alo, Bhi, Blo};

    auto load_chunk = [&](int stage, int kc) {
        const uint32_t stbase = sbase + stage * STAGE_SZ;
        #pragma unroll
        for (int t = 0; t < 2; t++) {
            #pragma unroll
            for (int i = 0; i < 4; i++) {
                int c = tid + i * 128;
                int row = c >> 3, u = c & 7;
                cpasync16(stbase + OFF[t] + SWZ((uint32_t)(row * 128 + u * 16)),
                          gsrc[t] + (size_t)row * K + kc + u * 8);
            }
        }
        #pragma unroll
        for (int t = 2; t < 4; t++) {
            #pragma unroll
            for (int i = 0; i < 8; i++) {
                int c = tid + i * 128;
                int row = c >> 3, u = c & 7;
                cpasync16(stbase + OFF[t] + SWZ((uint32_t)(row * 128 + u * 16)),
                          gsrc[t] + (size_t)row * K + kc + u * 8);
            }
        }
        CP_COMMIT();
    };

    GemmAcc acc;
    #pragma unroll
    for (int i = 0; i < 2; i++)
        #pragma unroll
        for (int j = 0; j < 8; j++)
            #pragma unroll
            for (int e = 0; e < 4; e++) acc.a[i][j][e] = 0.f;

    const int nchunks = K >> 6;
    load_chunk(0, 0);
    for (int c = 0; c < nchunks; c++) {
        if (c + 1 < nchunks) { load_chunk((c + 1) & 1, (c + 1) << 6); CP_WAIT(1); }
        else                 { CP_WAIT(0); }
        __syncthreads();
        const uint32_t stb = sbase + (c & 1) * STAGE_SZ;

        #pragma unroll
        for (int ks = 0; ks < 4; ks++) {
            uint32_t ah[2][4], al[2][4], bh[8][2], bl[8][2];
            #pragma unroll
            for (int mf = 0; mf < 2; mf++) {
                int row = wm + mf * 16 + (lane & 15);
                int cu = ks * 2 + (lane >> 4);
                uint32_t off = SWZ((uint32_t)(row * 128 + cu * 16));
                ldsm4(ah[mf][0], ah[mf][1], ah[mf][2], ah[mf][3], stb + OFF[0] + off);
                ldsm4(al[mf][0], al[mf][1], al[mf][2], al[mf][3], stb + OFF[1] + off);
            }
            #pragma unroll
            for (int nf2 = 0; nf2 < 4; nf2++) {
                int row = wn + nf2 * 16 + (lane & 7) + ((lane >> 4) << 3);
                int cu = ks * 2 + ((lane >> 3) & 1);
                uint32_t off = SWZ((uint32_t)(row * 128 + cu * 16));
                ldsm4(bh[2 * nf2][0], bh[2 * nf2][1], bh[2 * nf2 + 1][0], bh[2 * nf2 + 1][1],
                      stb + OFF[2] + off);
                ldsm4(bl[2 * nf2][0], bl[2 * nf2][1], bl[2 * nf2 + 1][0], bl[2 * nf2 + 1][1],
                      stb + OFF[3] + off);
            }
            #pragma unroll
            for (int mf = 0; mf < 2; mf++)
                #pragma unroll
                for (int nf = 0; nf < 8; nf++) {
                    mma16816(acc.a[mf][nf], ah[mf], bh[nf]);
                    mma16816(acc.a[mf][nf], ah[mf], bl[nf]);
                    mma16816(acc.a[mf][nf], al[mf], bh[nf]);
                }
        }
        __syncthreads();
    }
    epi(acc, wm, wn, lane);
}

// epilogue functor: QKV split + routing (V -> fp16 hi/lo)
struct QkvEpi {
    int b, mt, nt;
    __device__ void operator()(GemmAcc& acc, int wm, int wn, int lane) const {
        #pragma unroll
        for (int mf = 0; mf < 2; mf++) {
            int r0 = mt * 64 + wm + mf * 16 + (lane >> 2);
            #pragma unroll
            for (int nf = 0; nf < 8; nf++) {
                int col = nt * 128 + wn + nf * 8 + 2 * (lane & 3);
                const float* a = acc.a[mf][nf];
                if (nt < 4) {
                    uint32_t hp, lp;
                    split_pair(a[0], a[1], hp, lp);
                    size_t o0 = ((size_t)b * 1024 + r0) * 512 + col;
                    *(uint32_t*)&g_Qh[o0] = hp; *(uint32_t*)&g_Ql[o0] = lp;
                    split_pair(a[2], a[3], hp, lp);
                    size_t o1 = ((size_t)b * 1024 + r0 + 8) * 512 + col;
                    *(uint32_t*)&g_Qh[o1] = hp; *(uint32_t*)&g_Ql[o1] = lp;
                } else if (wn == 0) {
                    int kc = col - 512;
                    uint32_t hp, lp;
                    split_pair(a[0], a[1], hp, lp);
                    size_t o0 = ((size_t)b * 1024 + r0) * 64 + kc;
                    *(uint32_t*)&g_Kh[o0] = hp; *(uint32_t*)&g_Kl[o0] = lp;
                    split_pair(a[2], a[3], hp, lp);
                    size_t o1 = ((size_t)b * 1024 + r0 + 8) * 64 + kc;
                    *(uint32_t*)&g_Kh[o1] = hp; *(uint32_t*)&g_Kl[o1] = lp;
                } else {
                    int v0 = col - 576;
                    #pragma unroll
                    for (int e = 0; e < 4; e++) {
                        int vv = v0 + (e & 1);
                        int mm = r0 + (e >> 1) * 8;
                        __half h = __float2half(a[e]);
                        __half l = __float2half(a[e] - __half2float(h));
                        size_t o = ((size_t)b * 64 + vv) * 1024 + mm;
                        g_Vth[o] = h; g_Vtl[o] = l;
                    }
                }
            }
        }
    }
};

// epilogue functor: float output
struct OutEpi {
    int b, mt, nt;
    float* D;
    __device__ void operator()(GemmAcc& acc, int wm, int wn, int lane) const {
        #pragma unroll
        for (int mf = 0; mf < 2; mf++) {
            int r0 = mt * 64 + wm + mf * 16 + (lane >> 2);
            #pragma unroll
            for (int nf = 0; nf < 8; nf++) {
                int col = nt * 128 + wn + nf * 8 + 2 * (lane & 3);
                *(float2*)(D + ((size_t)b * 512 + r0) * 1024 + col) =
                    make_float2(acc.a[mf][nf][0], acc.a[mf][nf][1]);
                *(float2*)(D + ((size_t)b * 512 + r0 + 8) * 1024 + col) =
                    make_float2(acc.a[mf][nf][2], acc.a[mf][nf][3]);
            }
        }
    }
};

__global__ void __launch_bounds__(128)
gemm_qkv() {
    const int b = blockIdx.z, mt = blockIdx.y, nt = blockIdx.x;
    QkvEpi epi{b, mt, nt};
    gemm_core(
        g_rxh + ((size_t)b * 1024 + mt * 64) * 512,
        g_rxl + ((size_t)b * 1024 + mt * 64) * 512,
        g_Wqh + (size_t)nt * 128 * 512,
        g_Wql + (size_t)nt * 128 * 512,
        512, epi);
}

__global__ void __launch_bounds__(128)
gemm_out(float* __restrict__ D) {
    const int b = blockIdx.z, mt = blockIdx.y, nt = blockIdx.x;
    OutEpi epi{b, mt, nt, D};
    gemm_core(
        g_Woh + (size_t)mt * 64 * 512,
        g_Wol + (size_t)mt * 64 * 512,
        g_Ohi + ((size_t)b * 1024 + nt * 128) * 512,
        g_Olo + ((size_t)b * 1024 + nt * 128) * 512,
        512, epi);
}

// ---------------------------------------------------------------------------
// HMMA flash attention: 4-warp CTA, 128 q-rows, 2-stage KV, 2 CTAs/SM.
// S = 3-term bf16 split; PV = fp16 P (single) x fp16 V (hi+lo) = 2 terms.
// smem: Qh 0 | Ql 16K | stages 32K + s*32K: {Kh 0 | Kl 8K | Vh 16K | Vl 24K}
// ---------------------------------------------------------------------------
#define ATTN_SMEM 98304

__global__ void __launch_bounds__(128, 2)
attn_mma() {
    extern __shared__ char sm[];
    const uint32_t sbase = s2u(sm);
    const uint32_t QH = 0u, QL = 16384u, STG = 32768u;

    const int tid = threadIdx.x, lane = tid & 31, wid = tid >> 5;
    const int b = blockIdx.z, h = blockIdx.y, n0 = blockIdx.x * 128;

    const __nv_bfloat16* Qhb = g_Qh + ((size_t)b * 1024 + n0) * 512 + h * 64;
    const __nv_bfloat16* Qlb = g_Ql + ((size_t)b * 1024 + n0) * 512 + h * 64;
    const __nv_bfloat16* Khb = g_Kh + (size_t)b * 1024 * 64;
    const __nv_bfloat16* Klb = g_Kl + (size_t)b * 1024 * 64;
    const __half* Vhb = g_Vth + (size_t)b * 64 * 1024;
    const __half* Vlb = g_Vtl + (size_t)b * 64 * 1024;

    // Q load
    #pragma unroll
    for (int i = 0; i < 8; i++) {
        int c = tid + i * 128;
        int row = c >> 3, u = c & 7;
        uint32_t off = SWZ((uint32_t)(row * 128 + u * 16));
        cpasync16(sbase + QH + off, Qhb + (size_t)row * 512 + u * 8);
        cpasync16(sbase + QL + off, Qlb + (size_t)row * 512 + u * 8);
    }
    CP_COMMIT();

    auto load_kv = [&](int stage, int m0) {
        const uint32_t stb = sbase + STG + stage * 32768u;
        #pragma unroll
        for (int i = 0; i < 4; i++) {
            int c = tid + i * 128;
            int row = c >> 3, u = c & 7;
            uint32_t off = SWZ((uint32_t)(row * 128 + u * 16));
            cpasync16(stb + off,          Khb + (size_t)(m0 + row) * 64 + u * 8);
            cpasync16(stb + 8192u + off,  Klb + (size_t)(m0 + row) * 64 + u * 8);
            cpasync16(stb + 16384u + off, Vhb + (size_t)row * 1024 + m0 + u * 8);
            cpasync16(stb + 24576u + off, Vlb + (size_t)row * 1024 + m0 + u * 8);
        }
        CP_COMMIT();
    };

    load_kv(0, 0);

    float m_i[2][2], l_i[2][2], oacc[2][8][4];
    #pragma unroll
    for (int mf = 0; mf < 2; mf++) {
        m_i[mf][0] = m_i[mf][1] = -1e30f;
        l_i[mf][0] = l_i[mf][1] = 0.f;
        #pragma unroll
        for (int nf = 0; nf < 8; nf++)
            #pragma unroll
            for (int e = 0; e < 4; e++) oacc[mf][nf][e] = 0.f;
    }

    for (int ic = 0; ic < 16; ic++) {
        if (ic + 1 < 16) { load_kv((ic + 1) & 1, (ic + 1) * 64); CP_WAIT(1); }
        else             { CP_WAIT(0); }
        __syncthreads();
        const uint32_t KHs = STG + (uint32_t)(ic & 1) * 32768u;
        const uint32_t KLs = KHs + 8192u, VHs = KHs + 16384u, VLs = KHs + 24576u;

        // ---- S = Q K^T (3-term bf16) ----
        float sacc[2][8][4];
        #pragma unroll
        for (int mf = 0; mf < 2; mf++)
            #pragma unroll
            for (int nf = 0; nf < 8; nf++)
                #pragma unroll
                for (int e = 0; e < 4; e++) sacc[mf][nf][e] = 0.f;

        #pragma unroll
        for (int ks = 0; ks < 4; ks++) {
            uint32_t qh[2][4], ql[2][4], bh[8][2], bl[8][2];
            #pragma unroll
            for (int mf = 0; mf < 2; mf++) {
                int row = wid * 32 + mf * 16 + (lane & 15);
                int cu = ks * 2 + (lane >> 4);
                uint32_t off = SWZ((uint32_t)(row * 128 + cu * 16));
                ldsm4(qh[mf][0], qh[mf][1], qh[mf][2], qh[mf][3], sbase + QH + off);
                ldsm4(ql[mf][0], ql[mf][1], ql[mf][2], ql[mf][3], sbase + QL + off);
            }
            #pragma unroll
            for (int nf2 = 0; nf2 < 4; nf2++) {
                int row = nf2 * 16 + (lane & 7) + ((lane >> 4) << 3);
                int cu = ks * 2 + ((lane >> 3) & 1);
                uint32_t off = SWZ((uint32_t)(row * 128 + cu * 16));
                ldsm4(bh[2 * nf2][0], bh[2 * nf2][1], bh[2 * nf2 + 1][0], bh[2 * nf2 + 1][1],
                      sbase + KHs + off);
                ldsm4(bl[2 * nf2][0], bl[2 * nf2][1], bl[2 * nf2 + 1][0], bl[2 * nf2 + 1][1],
                      sbase + KLs + off);
            }
            #pragma unroll
            for (int mf = 0; mf < 2; mf++)
                #pragma unroll
                for (int nf = 0; nf < 8; nf++) {
                    mma16816(sacc[mf][nf], qh[mf], bh[nf]);
                    mma16816(sacc[mf][nf], qh[mf], bl[nf]);
                    mma16816(sacc[mf][nf], ql[mf], bh[nf]);
                }
        }

        // ---- online softmax ----
        #pragma unroll
        for (int mf = 0; mf < 2; mf++) {
            float mx0 = -1e30f, mx1 = -1e30f;
            #pragma unroll
            for (int nf = 0; nf < 8; nf++) {
                mx0 = fmaxf(mx0, fmaxf(sacc[mf][nf][0], sacc[mf][nf][1]));
                mx1 = fmaxf(mx1, fmaxf(sacc[mf][nf][2], sacc[mf][nf][3]));
            }
            mx0 = fmaxf(mx0, __shfl_xor_sync(0xffffffffu, mx0, 1));
            mx0 = fmaxf(mx0, __shfl_xor_sync(0xffffffffu, mx0, 2));
            mx1 = fmaxf(mx1, __shfl_xor_sync(0xffffffffu, mx1, 1));
            mx1 = fmaxf(mx1, __shfl_xor_sync(0xffffffffu, mx1, 2));
            float mn0 = fmaxf(m_i[mf][0], mx0), mn1 = fmaxf(m_i[mf][1], mx1);
            float c0 = __expf(m_i[mf][0] - mn0), c1 = __expf(m_i[mf][1] - mn1);
            float sum0 = 0.f, sum1 = 0.f;
            #pragma unroll
            for (int nf = 0; nf < 8; nf++) {
                sacc[mf][nf][0] = __expf(sacc[mf][nf][0] - mn0);
                sacc[mf][nf][1] = __expf(sacc[mf][nf][1] - mn0);
                sacc[mf][nf][2] = __expf(sacc[mf][nf][2] - mn1);
                sacc[mf][nf][3] = __expf(sacc[mf][nf][3] - mn1);
                sum0 += sacc[mf][nf][0] + sacc[mf][nf][1];
                sum1 += sacc[mf][nf][2] + sacc[mf][nf][3];
            }
            sum0 += __shfl_xor_sync(0xffffffffu, sum0, 1);
            sum0 += __shfl_xor_sync(0xffffffffu, sum0, 2);
            sum1 += __shfl_xor_sync(0xffffffffu, sum1, 1);
            sum1 += __shfl_xor_sync(0xffffffffu, sum1, 2);
            l_i[mf][0] = l_i[mf][0] * c0 + sum0;
            l_i[mf][1] = l_i[mf][1] * c1 + sum1;
            m_i[mf][0] = mn0; m_i[mf][1] = mn1;
            #pragma unroll
            for (int nf = 0; nf < 8; nf++) {
                oacc[mf][nf][0] *= c0; oacc[mf][nf][1] *= c0;
                oacc[mf][nf][2] *= c1; oacc[mf][nf][3] *= c1;
            }
        }

        // ---- O += P V  (fp16 P single-term x fp16 V hi/lo) ----
        #pragma unroll
        for (int ks = 0; ks < 4; ks++) {
            uint32_t pa[2][4];
            #pragma unroll
            for (int mf = 0; mf < 2; mf++) {
                const float* f0 = sacc[mf][2 * ks];
                const float* f1 = sacc[mf][2 * ks + 1];
                pa[mf][0] = cvt2h(f0[0], f0[1]);
                pa[mf][1] = cvt2h(f0[2], f0[3]);
                pa[mf][2] = cvt2h(f1[0], f1[1]);
                pa[mf][3] = cvt2h(f1[2], f1[3]);
            }
            uint32_t vh[8][2], vl[8][2];
            #pragma unroll
            for (int nf2 = 0; nf2 < 4; nf2++) {
                int row = nf2 * 16 + (lane & 7) + ((lane >> 4) << 3);
                int cu = ks * 2 + ((lane >> 3) & 1);
                uint32_t off = SWZ((uint32_t)(row * 128 + cu * 16));
                ldsm4(vh[2 * nf2][0], vh[2 * nf2][1], vh[2 * nf2 + 1][0], vh[2 * nf2 + 1][1],
                      sbase + VHs + off);
                ldsm4(vl[2 * nf2][0], vl[2 * nf2][1], vl[2 * nf2 + 1][0], vl[2 * nf2 + 1][1],
                      sbase + VLs + off);
            }
            #pragma unroll
            for (int mf = 0; mf < 2; mf++)
                #pragma unroll
                for (int nf = 0; nf < 8; nf++) {
                    mma16816h(oacc[mf][nf], pa[mf], vh[nf]);
                    mma16816h(oacc[mf][nf], pa[mf], vl[nf]);
                }
        }
        __syncthreads();
    }

    // ---- epilogue ----
    #pragma unroll
    for (int mf = 0; mf < 2; mf++) {
        float inv0 = 1.0f / l_i[mf][0], inv1 = 1.0f / l_i[mf][1];
        int nr0 = n0 + wid * 32 + mf * 16 + (lane >> 2);
        #pragma unroll
        for (int nf = 0; nf < 8; nf++) {
            int col = h * 64 + nf * 8 + 2 * (lane & 3);
            uint32_t hp, lp;
            split_pair(oacc[mf][nf][0] * inv0, oacc[mf][nf][1] * inv0, hp, lp);
            size_t base0 = ((size_t)b * 1024 + nr0) * 512 + col;
            *(uint32_t*)&g_Ohi[base0] = hp;
            *(uint32_t*)&g_Olo[base0] = lp;
            split_pair(oacc[mf][nf][2] * inv1, oacc[mf][nf][3] * inv1, hp, lp);
            size_t base1 = ((size_t)b * 1024 + nr0 + 8) * 512 + col;
            *(uint32_t*)&g_Ohi[base1] = hp;
            *(uint32_t*)&g_Olo[base1] = lp;
        }
    }
}

// ---------------------------------------------------------------------------
extern "C" void kernel_launch(void* const* d_in, const int* in_sizes, int n_in,
                              void* d_out, int out_size) {
    const float* x    = (const float*)d_in[0];
    const float* qp   = (const float*)d_in[1];
    const float* kp   = (const float*)d_in[2];
    const float* vp   = (const float*)d_in[3];
    const float* wout = (const float*)d_in[4];
    float* out = (float*)d_out;

    cudaFuncSetAttribute(gemm_qkv, cudaFuncAttributeMaxDynamicSharedMemorySize, GEMM_SMEM);
    cudaFuncSetAttribute(gemm_out, cudaFuncAttributeMaxDynamicSharedMemorySize, GEMM_SMEM);
    cudaFuncSetAttribute(attn_mma, cudaFuncAttributeMaxDynamicSharedMemorySize, ATTN_SMEM);

    { dim3 g(32, 16, BSZ); dim3 blk(32, 8); conv_x<<<g, blk>>>(x); }
    prep_w<<<(640 * 512 + 512 * 512 + 255) / 256, 256>>>(qp, kp, vp, wout);

    { dim3 g(5, 16, BSZ); gemm_qkv<<<g, 128, GEMM_SMEM>>>(); }
    { dim3 g(8, NH, BSZ); attn_mma<<<g, 128, ATTN_SMEM>>>(); }
    { dim3 g(8, 8, BSZ); gemm_out<<<g, 128, GEMM_SMEM>>>(out); }
}

// round 12
// speedup vs baseline: 4.3158x; 1.0020x over previous
#include <cuda_runtime.h>
#include <cuda_bf16.h>
#include <cuda_fp16.h>
#include <cstdint>
#include <cstddef>
#include <math.h>

#define BSZ 8
#define NTOK 1024
#define NH 8

// ---------------------------------------------------------------------------
// Device scratch
// ---------------------------------------------------------------------------
__device__ __align__(16) __nv_bfloat16 g_rxh[BSZ * NTOK * 512];   // [b][n][d]
__device__ __align__(16) __nv_bfloat16 g_rxl[BSZ * NTOK * 512];
__device__ __align__(16) __nv_bfloat16 g_Wqh[640 * 512];          // [c][d] (Q rows pre-scaled by 0.125*log2e)
__device__ __align__(16) __nv_bfloat16 g_Wql[640 * 512];
__device__ __align__(16) __nv_bfloat16 g_Woh[512 * 512];          // [dout][c]
__device__ __align__(16) __nv_bfloat16 g_Wol[512 * 512];
__device__ __align__(16) __nv_bfloat16 g_Qh[BSZ * NTOK * 512];    // [b][n][hk] scaled
__device__ __align__(16) __nv_bfloat16 g_Ql[BSZ * NTOK * 512];
__device__ __align__(16) __nv_bfloat16 g_Kh[BSZ * NTOK * 64];     // [b][m][kd]
__device__ __align__(16) __nv_bfloat16 g_Kl[BSZ * NTOK * 64];
__device__ __align__(16) __half g_Vth[BSZ * 64 * NTOK];           // [b][v][m] fp16 hi
__device__ __align__(16) __half g_Vtl[BSZ * 64 * NTOK];           // fp16 lo
__device__ __align__(16) __nv_bfloat16 g_Ohi[BSZ * NTOK * 512];   // [b][n][c]
__device__ __align__(16) __nv_bfloat16 g_Olo[BSZ * NTOK * 512];

// ---------------------------------------------------------------------------
// helpers
// ---------------------------------------------------------------------------
#define SWZ(x) ((x) ^ (((x) >> 3) & 0x70))

__device__ __forceinline__ uint32_t s2u(const void* p) {
    uint32_t a;
    asm("{ .reg .u64 t; cvta.to.shared.u64 t, %1; cvt.u32.u64 %0, t; }" : "=r"(a) : "l"(p));
    return a;
}
__device__ __forceinline__ void cpasync16(uint32_t dst, const void* src) {
    asm volatile("cp.async.cg.shared.global [%0], [%1], 16;" :: "r"(dst), "l"(src));
}
#define CP_COMMIT() asm volatile("cp.async.commit_group;")
#define CP_WAIT(n)  asm volatile("cp.async.wait_group %0;" :: "n"(n))

__device__ __forceinline__ void ldsm4(uint32_t& a, uint32_t& b, uint32_t& c, uint32_t& d,
                                      uint32_t addr) {
    asm volatile("ldmatrix.sync.aligned.m8n8.x4.shared.b16 {%0,%1,%2,%3}, [%4];"
                 : "=r"(a), "=r"(b), "=r"(c), "=r"(d) : "r"(addr));
}
__device__ __forceinline__ void mma16816(float* d, const uint32_t* a, const uint32_t* b) {
    asm volatile(
        "mma.sync.aligned.m16n8k16.row.col.f32.bf16.bf16.f32 "
        "{%0,%1,%2,%3}, {%4,%5,%6,%7}, {%8,%9}, {%0,%1,%2,%3};"
        : "+f"(d[0]), "+f"(d[1]), "+f"(d[2]), "+f"(d[3])
        : "r"(a[0]), "r"(a[1]), "r"(a[2]), "r"(a[3]), "r"(b[0]), "r"(b[1]));
}
__device__ __forceinline__ void mma16816h(float* d, const uint32_t* a, const uint32_t* b) {
    asm volatile(
        "mma.sync.aligned.m16n8k16.row.col.f32.f16.f16.f32 "
        "{%0,%1,%2,%3}, {%4,%5,%6,%7}, {%8,%9}, {%0,%1,%2,%3};"
        : "+f"(d[0]), "+f"(d[1]), "+f"(d[2]), "+f"(d[3])
        : "r"(a[0]), "r"(a[1]), "r"(a[2]), "r"(a[3]), "r"(b[0]), "r"(b[1]));
}
__device__ __forceinline__ float ex2(float x) {
    float r;
    asm("ex2.approx.f32 %0, %1;" : "=f"(r) : "f"(x));
    return r;
}
__device__ __forceinline__ void split2(float v, __nv_bfloat16& h, __nv_bfloat16& l) {
    h = __float2bfloat16(v);
    l = __float2bfloat16(v - __bfloat162float(h));
}
__device__ __forceinline__ uint32_t cvt2bf(float f0, float f1) {
    uint32_t r;
    asm("cvt.rn.bf16x2.f32 %0, %1, %2;" : "=r"(r) : "f"(f1), "f"(f0));
    return r;
}
__device__ __forceinline__ uint32_t cvt2h(float f0, float f1) {
    uint32_t r;
    asm("cvt.rn.f16x2.f32 %0, %1, %2;" : "=r"(r) : "f"(f1), "f"(f0));
    return r;
}
__device__ __forceinline__ void split_pair(float f0, float f1, uint32_t& hp, uint32_t& lp) {
    hp = cvt2bf(f0, f1);
    float h0 = __uint_as_float(hp << 16);
    float h1 = __uint_as_float(hp & 0xffff0000u);
    lp = cvt2bf(f0 - h0, f1 - h1);
}

// ---------------------------------------------------------------------------
// prep kernels
// ---------------------------------------------------------------------------
__global__ void conv_x(const float* __restrict__ x) {
    __shared__ float t[32][33];
    const int b = blockIdx.z, d0 = blockIdx.y * 32, n0 = blockIdx.x * 32;
    const int txx = threadIdx.x, tyy = threadIdx.y;
    #pragma unroll
    for (int r = 0; r < 4; r++)
        t[tyy + r * 8][txx] = x[((size_t)b * 512 + d0 + tyy + r * 8) * 1024 + n0 + txx];
    __syncthreads();
    #pragma unroll
    for (int r = 0; r < 4; r++) {
        int n = n0 + tyy + r * 8;
        __nv_bfloat16 h, l;
        split2(t[txx][tyy + r * 8], h, l);
        size_t o = ((size_t)b * 1024 + n) * 512 + d0 + txx;
        g_rxh[o] = h; g_rxl[o] = l;
    }
}

// merged weight prep; Q rows scaled by 0.125 * log2(e) (base-2 softmax)
__global__ void prep_w(const float* __restrict__ qp, const float* __restrict__ kp,
                       const float* __restrict__ vp, const float* __restrict__ wout) {
    int idx = blockIdx.x * 256 + threadIdx.x;
    if (idx < 640 * 512) {
        int c = idx >> 9, d = idx & 511;
        float v;
        if (c < 512)      v = qp[c * 512 + d] * (0.125f * 1.4426950408889634f);
        else if (c < 576) v = kp[d * 64 + (c - 512)];
        else              v = vp[d * 64 + (c - 576)];
        split2(v, g_Wqh[idx], g_Wql[idx]);
    } else {
        int j = idx - 640 * 512;
        if (j < 512 * 512) split2(wout[j], g_Woh[j], g_Wol[j]);
    }
}

// ---------------------------------------------------------------------------
// GEMM core (4-warp CTA, 64x128 tile, 2-stage cp.async, 2 CTAs/SM)
// ---------------------------------------------------------------------------
#define GEMM_SMEM (2 * 49152)
#define STAGE_SZ  49152u

struct GemmAcc { float a[2][8][4]; };

template <typename Epi>
__device__ __forceinline__ void gemm_core(
    const __nv_bfloat16* Ahi, const __nv_bfloat16* Alo,
    const __nv_bfloat16* Bhi, const __nv_bfloat16* Blo,
    int K, Epi epi) {
    extern __shared__ char sm[];
    const uint32_t sbase = s2u(sm);
    const uint32_t OFF[4] = {0u, 8192u, 16384u, 32768u};

    const int tid = threadIdx.x, lane = tid & 31, wid = tid >> 5;
    const int wm = (wid >> 1) * 32, wn = (wid & 1) * 64;

    const __nv_bfloat16* gsrc[4] = {Ahi, Alo, Bhi, Blo};

    auto load_chunk = [&](int stage, int kc) {
        const uint32_t stbase = sbase + stage * STAGE_SZ;
        #pragma unroll
        for (int t = 0; t < 2; t++) {
            #pragma unroll
            for (int i = 0; i < 4; i++) {
                int c = tid + i * 128;
                int row = c >> 3, u = c & 7;
                cpasync16(stbase + OFF[t] + SWZ((uint32_t)(row * 128 + u * 16)),
                          gsrc[t] + (size_t)row * K + kc + u * 8);
            }
        }
        #pragma unroll
        for (int t = 2; t < 4; t++) {
            #pragma unroll
            for (int i = 0; i < 8; i++) {
                int c = tid + i * 128;
                int row = c >> 3, u = c & 7;
                cpasync16(stbase + OFF[t] + SWZ((uint32_t)(row * 128 + u * 16)),
                          gsrc[t] + (size_t)row * K + kc + u * 8);
            }
        }
        CP_COMMIT();
    };

    GemmAcc acc;
    #pragma unroll
    for (int i = 0; i < 2; i++)
        #pragma unroll
        for (int j = 0; j < 8; j++)
            #pragma unroll
            for (int e = 0; e < 4; e++) acc.a[i][j][e] = 0.f;

    const int nchunks = K >> 6;
    load_chunk(0, 0);
    for (int c = 0; c < nchunks; c++) {
        if (c + 1 < nchunks) { load_chunk((c + 1) & 1, (c + 1) << 6); CP_WAIT(1); }
        else                 { CP_WAIT(0); }
        __syncthreads();
        const uint32_t stb = sbase + (c & 1) * STAGE_SZ;

        #pragma unroll
        for (int ks = 0; ks < 4; ks++) {
            uint32_t ah[2][4], al[2][4], bh[8][2], bl[8][2];
            #pragma unroll
            for (int mf = 0; mf < 2; mf++) {
                int row = wm + mf * 16 + (lane & 15);
                int cu = ks * 2 + (lane >> 4);
                uint32_t off = SWZ((uint32_t)(row * 128 + cu * 16));
                ldsm4(ah[mf][0], ah[mf][1], ah[mf][2], ah[mf][3], stb + OFF[0] + off);
                ldsm4(al[mf][0], al[mf][1], al[mf][2], al[mf][3], stb + OFF[1] + off);
            }
            #pragma unroll
            for (int nf2 = 0; nf2 < 4; nf2++) {
                int row = wn + nf2 * 16 + (lane & 7) + ((lane >> 4) << 3);
                int cu = ks * 2 + ((lane >> 3) & 1);
                uint32_t off = SWZ((uint32_t)(row * 128 + cu * 16));
                ldsm4(bh[2 * nf2][0], bh[2 * nf2][1], bh[2 * nf2 + 1][0], bh[2 * nf2 + 1][1],
                      stb + OFF[2] + off);
                ldsm4(bl[2 * nf2][0], bl[2 * nf2][1], bl[2 * nf2 + 1][0], bl[2 * nf2 + 1][1],
                      stb + OFF[3] + off);
            }
            #pragma unroll
            for (int mf = 0; mf < 2; mf++)
                #pragma unroll
                for (int nf = 0; nf < 8; nf++) {
                    mma16816(acc.a[mf][nf], ah[mf], bh[nf]);
                    mma16816(acc.a[mf][nf], ah[mf], bl[nf]);
                    mma16816(acc.a[mf][nf], al[mf], bh[nf]);
                }
        }
        __syncthreads();
    }
    epi(acc, wm, wn, lane);
}

// epilogue functor: QKV split + routing (V -> fp16 hi/lo)
struct QkvEpi {
    int b, mt, nt;
    __device__ void operator()(GemmAcc& acc, int wm, int wn, int lane) const {
        #pragma unroll
        for (int mf = 0; mf < 2; mf++) {
            int r0 = mt * 64 + wm + mf * 16 + (lane >> 2);
            #pragma unroll
            for (int nf = 0; nf < 8; nf++) {
                int col = nt * 128 + wn + nf * 8 + 2 * (lane & 3);
                const float* a = acc.a[mf][nf];
                if (nt < 4) {
                    uint32_t hp, lp;
                    split_pair(a[0], a[1], hp, lp);
                    size_t o0 = ((size_t)b * 1024 + r0) * 512 + col;
                    *(uint32_t*)&g_Qh[o0] = hp; *(uint32_t*)&g_Ql[o0] = lp;
                    split_pair(a[2], a[3], hp, lp);
                    size_t o1 = ((size_t)b * 1024 + r0 + 8) * 512 + col;
                    *(uint32_t*)&g_Qh[o1] = hp; *(uint32_t*)&g_Ql[o1] = lp;
                } else if (wn == 0) {
                    int kc = col - 512;
                    uint32_t hp, lp;
                    split_pair(a[0], a[1], hp, lp);
                    size_t o0 = ((size_t)b * 1024 + r0) * 64 + kc;
                    *(uint32_t*)&g_Kh[o0] = hp; *(uint32_t*)&g_Kl[o0] = lp;
                    split_pair(a[2], a[3], hp, lp);
                    size_t o1 = ((size_t)b * 1024 + r0 + 8) * 64 + kc;
                    *(uint32_t*)&g_Kh[o1] = hp; *(uint32_t*)&g_Kl[o1] = lp;
                } else {
                    int v0 = col - 576;
                    #pragma unroll
                    for (int e = 0; e < 4; e++) {
                        int vv = v0 + (e & 1);
                        int mm = r0 + (e >> 1) * 8;
                        __half h = __float2half(a[e]);
                        __half l = __float2half(a[e] - __half2float(h));
                        size_t o = ((size_t)b * 64 + vv) * 1024 + mm;
                        g_Vth[o] = h; g_Vtl[o] = l;
                    }
                }
            }
        }
    }
};

// epilogue functor: float output
struct OutEpi {
    int b, mt, nt;
    float* D;
    __device__ void operator()(GemmAcc& acc, int wm, int wn, int lane) const {
        #pragma unroll
        for (int mf = 0; mf < 2; mf++) {
            int r0 = mt * 64 + wm + mf * 16 + (lane >> 2);
            #pragma unroll
            for (int nf = 0; nf < 8; nf++) {
                int col = nt * 128 + wn + nf * 8 + 2 * (lane & 3);
                *(float2*)(D + ((size_t)b * 512 + r0) * 1024 + col) =
                    make_float2(acc.a[mf][nf][0], acc.a[mf][nf][1]);
                *(float2*)(D + ((size_t)b * 512 + r0 + 8) * 1024 + col) =
                    make_float2(acc.a[mf][nf][2], acc.a[mf][nf][3]);
            }
        }
    }
};

__global__ void __launch_bounds__(128)
gemm_qkv() {
    const int b = blockIdx.z, mt = blockIdx.y, nt = blockIdx.x;
    QkvEpi epi{b, mt, nt};
    gemm_core(
        g_rxh + ((size_t)b * 1024 + mt * 64) * 512,
        g_rxl + ((size_t)b * 1024 + mt * 64) * 512,
        g_Wqh + (size_t)nt * 128 * 512,
        g_Wql + (size_t)nt * 128 * 512,
        512, epi);
}

__global__ void __launch_bounds__(128)
gemm_out(float* __restrict__ D) {
    const int b = blockIdx.z, mt = blockIdx.y, nt = blockIdx.x;
    OutEpi epi{b, mt, nt, D};
    gemm_core(
        g_Woh + (size_t)mt * 64 * 512,
        g_Wol + (size_t)mt * 64 * 512,
        g_Ohi + ((size_t)b * 1024 + nt * 128) * 512,
        g_Olo + ((size_t)b * 1024 + nt * 128) * 512,
        512, epi);
}

// ---------------------------------------------------------------------------
// HMMA flash attention: 4-warp CTA, 128 q-rows, 2-stage KV, 2 CTAs/SM.
// Base-2 softmax (log2e folded into Q weights). KV iteration phase-staggered
// by CTA parity so co-resident CTAs' softmax overlaps the neighbor's MMAs.
// ---------------------------------------------------------------------------
#define ATTN_SMEM 98304

__global__ void __launch_bounds__(128, 2)
attn_mma() {
    extern __shared__ char sm[];
    const uint32_t sbase = s2u(sm);
    const uint32_t QH = 0u, QL = 16384u, STG = 32768u;

    const int tid = threadIdx.x, lane = tid & 31, wid = tid >> 5;
    const int b = blockIdx.z, h = blockIdx.y, n0 = blockIdx.x * 128;
    const int phase = ((blockIdx.x + blockIdx.y) & 1) << 3;   // 0 or 8 chunks

    const __nv_bfloat16* Qhb = g_Qh + ((size_t)b * 1024 + n0) * 512 + h * 64;
    const __nv_bfloat16* Qlb = g_Ql + ((size_t)b * 1024 + n0) * 512 + h * 64;
    const __nv_bfloat16* Khb = g_Kh + (size_t)b * 1024 * 64;
    const __nv_bfloat16* Klb = g_Kl + (size_t)b * 1024 * 64;
    const __half* Vhb = g_Vth + (size_t)b * 64 * 1024;
    const __half* Vlb = g_Vtl + (size_t)b * 64 * 1024;

    // Q load
    #pragma unroll
    for (int i = 0; i < 8; i++) {
        int c = tid + i * 128;
        int row = c >> 3, u = c & 7;
        uint32_t off = SWZ((uint32_t)(row * 128 + u * 16));
        cpasync16(sbase + QH + off, Qhb + (size_t)row * 512 + u * 8);
        cpasync16(sbase + QL + off, Qlb + (size_t)row * 512 + u * 8);
    }
    CP_COMMIT();

    auto load_kv = [&](int stage, int m0) {
        const uint32_t stb = sbase + STG + stage * 32768u;
        #pragma unroll
        for (int i = 0; i < 4; i++) {
            int c = tid + i * 128;
            int row = c >> 3, u = c & 7;
            uint32_t off = SWZ((uint32_t)(row * 128 + u * 16));
            cpasync16(stb + off,          Khb + (size_t)(m0 + row) * 64 + u * 8);
            cpasync16(stb + 8192u + off,  Klb + (size_t)(m0 + row) * 64 + u * 8);
            cpasync16(stb + 16384u + off, Vhb + (size_t)row * 1024 + m0 + u * 8);
            cpasync16(stb + 24576u + off, Vlb + (size_t)row * 1024 + m0 + u * 8);
        }
        CP_COMMIT();
    };

    load_kv(0, phase * 64);

    float m_i[2][2], l_i[2][2], oacc[2][8][4];
    #pragma unroll
    for (int mf = 0; mf < 2; mf++) {
        m_i[mf][0] = m_i[mf][1] = -1e30f;
        l_i[mf][0] = l_i[mf][1] = 0.f;
        #pragma unroll
        for (int nf = 0; nf < 8; nf++)
            #pragma unroll
            for (int e = 0; e < 4; e++) oacc[mf][nf][e] = 0.f;
    }

    for (int ic = 0; ic < 16; ic++) {
        if (ic + 1 < 16) {
            load_kv((ic + 1) & 1, (((ic + 1) + phase) & 15) * 64);
            CP_WAIT(1);
        } else {
            CP_WAIT(0);
        }
        __syncthreads();
        const uint32_t KHs = STG + (uint32_t)(ic & 1) * 32768u;
        const uint32_t KLs = KHs + 8192u, VHs = KHs + 16384u, VLs = KHs + 24576u;

        // ---- S = Q K^T (3-term bf16, base-2 scaled) ----
        float sacc[2][8][4];
        #pragma unroll
        for (int mf = 0; mf < 2; mf++)
            #pragma unroll
            for (int nf = 0; nf < 8; nf++)
                #pragma unroll
                for (int e = 0; e < 4; e++) sacc[mf][nf][e] = 0.f;

        #pragma unroll
        for (int ks = 0; ks < 4; ks++) {
            uint32_t qh[2][4], ql[2][4], bh[8][2], bl[8][2];
            #pragma unroll
            for (int mf = 0; mf < 2; mf++) {
                int row = wid * 32 + mf * 16 + (lane & 15);
                int cu = ks * 2 + (lane >> 4);
                uint32_t off = SWZ((uint32_t)(row * 128 + cu * 16));
                ldsm4(qh[mf][0], qh[mf][1], qh[mf][2], qh[mf][3], sbase + QH + off);
                ldsm4(ql[mf][0], ql[mf][1], ql[mf][2], ql[mf][3], sbase + QL + off);
            }
            #pragma unroll
            for (int nf2 = 0; nf2 < 4; nf2++) {
                int row = nf2 * 16 + (lane & 7) + ((lane >> 4) << 3);
                int cu = ks * 2 + ((lane >> 3) & 1);
                uint32_t off = SWZ((uint32_t)(row * 128 + cu * 16));
                ldsm4(bh[2 * nf2][0], bh[2 * nf2][1], bh[2 * nf2 + 1][0], bh[2 * nf2 + 1][1],
                      sbase + KHs + off);
                ldsm4(bl[2 * nf2][0], bl[2 * nf2][1], bl[2 * nf2 + 1][0], bl[2 * nf2 + 1][1],
                      sbase + KLs + off);
            }
            #pragma unroll
            for (int mf = 0; mf < 2; mf++)
                #pragma unroll
                for (int nf = 0; nf < 8; nf++) {
                    mma16816(sacc[mf][nf], qh[mf], bh[nf]);
                    mma16816(sacc[mf][nf], qh[mf], bl[nf]);
                    mma16816(sacc[mf][nf], ql[mf], bh[nf]);
                }
        }

        // ---- online softmax (base 2) ----
        #pragma unroll
        for (int mf = 0; mf < 2; mf++) {
            float mx0 = -1e30f, mx1 = -1e30f;
            #pragma unroll
            for (int nf = 0; nf < 8; nf++) {
                mx0 = fmaxf(mx0, fmaxf(sacc[mf][nf][0], sacc[mf][nf][1]));
                mx1 = fmaxf(mx1, fmaxf(sacc[mf][nf][2], sacc[mf][nf][3]));
            }
            mx0 = fmaxf(mx0, __shfl_xor_sync(0xffffffffu, mx0, 1));
            mx0 = fmaxf(mx0, __shfl_xor_sync(0xffffffffu, mx0, 2));
            mx1 = fmaxf(mx1, __shfl_xor_sync(0xffffffffu, mx1, 1));
            mx1 = fmaxf(mx1, __shfl_xor_sync(0xffffffffu, mx1, 2));
            float mn0 = fmaxf(m_i[mf][0], mx0), mn1 = fmaxf(m_i[mf][1], mx1);
            float c0 = ex2(m_i[mf][0] - mn0), c1 = ex2(m_i[mf][1] - mn1);
            float sum0 = 0.f, sum1 = 0.f;
            #pragma unroll
            for (int nf = 0; nf < 8; nf++) {
                sacc[mf][nf][0] = ex2(sacc[mf][nf][0] - mn0);
                sacc[mf][nf][1] = ex2(sacc[mf][nf][1] - mn0);
                sacc[mf][nf][2] = ex2(sacc[mf][nf][2] - mn1);
                sacc[mf][nf][3] = ex2(sacc[mf][nf][3] - mn1);
                sum0 += sacc[mf][nf][0] + sacc[mf][nf][1];
                sum1 += sacc[mf][nf][2] + sacc[mf][nf][3];
            }
            sum0 += __shfl_xor_sync(0xffffffffu, sum0, 1);
            sum0 += __shfl_xor_sync(0xffffffffu, sum0, 2);
            sum1 += __shfl_xor_sync(0xffffffffu, sum1, 1);
            sum1 += __shfl_xor_sync(0xffffffffu, sum1, 2);
            l_i[mf][0] = l_i[mf][0] * c0 + sum0;
            l_i[mf][1] = l_i[mf][1] * c1 + sum1;
            m_i[mf][0] = mn0; m_i[mf][1] = mn1;
            #pragma unroll
            for (int nf = 0; nf < 8; nf++) {
                oacc[mf][nf][0] *= c0; oacc[mf][nf][1] *= c0;
                oacc[mf][nf][2] *= c1; oacc[mf][nf][3] *= c1;
            }
        }

        // ---- O += P V  (fp16 P single x fp16 V hi/lo) ----
        #pragma unroll
        for (int ks = 0; ks < 4; ks++) {
            uint32_t pa[2][4];
            #pragma unroll
            for (int mf = 0; mf < 2; mf++) {
                const float* f0 = sacc[mf][2 * ks];
                const float* f1 = sacc[mf][2 * ks + 1];
                pa[mf][0] = cvt2h(f0[0], f0[1]);
                pa[mf][1] = cvt2h(f0[2], f0[3]);
                pa[mf][2] = cvt2h(f1[0], f1[1]);
                pa[mf][3] = cvt2h(f1[2], f1[3]);
            }
            uint32_t vh[8][2], vl[8][2];
            #pragma unroll
            for (int nf2 = 0; nf2 < 4; nf2++) {
                int row = nf2 * 16 + (lane & 7) + ((lane >> 4) << 3);
                int cu = ks * 2 + ((lane >> 3) & 1);
                uint32_t off = SWZ((uint32_t)(row * 128 + cu * 16));
                ldsm4(vh[2 * nf2][0], vh[2 * nf2][1], vh[2 * nf2 + 1][0], vh[2 * nf2 + 1][1],
                      sbase + VHs + off);
                ldsm4(vl[2 * nf2][0], vl[2 * nf2][1], vl[2 * nf2 + 1][0], vl[2 * nf2 + 1][1],
                      sbase + VLs + off);
            }
            #pragma unroll
            for (int mf = 0; mf < 2; mf++)
                #pragma unroll
                for (int nf = 0; nf < 8; nf++) {
                    mma16816h(oacc[mf][nf], pa[mf], vh[nf]);
                    mma16816h(oacc[mf][nf], pa[mf], vl[nf]);
                }
        }
        __syncthreads();
    }

    // ---- epilogue ----
    #pragma unroll
    for (int mf = 0; mf < 2; mf++) {
        float inv0 = 1.0f / l_i[mf][0], inv1 = 1.0f / l_i[mf][1];
        int nr0 = n0 + wid * 32 + mf * 16 + (lane >> 2);
        #pragma unroll
        for (int nf = 0; nf < 8; nf++) {
            int col = h * 64 + nf * 8 + 2 * (lane & 3);
            uint32_t hp, lp;
            split_pair(oacc[mf][nf][0] * inv0, oacc[mf][nf][1] * inv0, hp, lp);
            size_t base0 = ((size_t)b * 1024 + nr0) * 512 + col;
            *(uint32_t*)&g_Ohi[base0] = hp;
            *(uint32_t*)&g_Olo[base0] = lp;
            split_pair(oacc[mf][nf][2] * inv1, oacc[mf][nf][3] * inv1, hp, lp);
            size_t base1 = ((size_t)b * 1024 + nr0 + 8) * 512 + col;
            *(uint32_t*)&g_Ohi[base1] = hp;
            *(uint32_t*)&g_Olo[base1] = lp;
        }
    }
}

// ---------------------------------------------------------------------------
extern "C" void kernel_launch(void* const* d_in, const int* in_sizes, int n_in,
                              void* d_out, int out_size) {
    const float* x    = (const float*)d_in[0];
    const float* qp   = (const float*)d_in[1];
    const float* kp   = (const float*)d_in[2];
    const float* vp   = (const float*)d_in[3];
    const float* wout = (const float*)d_in[4];
    float* out = (float*)d_out;

    cudaFuncSetAttribute(gemm_qkv, cudaFuncAttributeMaxDynamicSharedMemorySize, GEMM_SMEM);
    cudaFuncSetAttribute(gemm_out, cudaFuncAttributeMaxDynamicSharedMemorySize, GEMM_SMEM);
    cudaFuncSetAttribute(attn_mma, cudaFuncAttributeMaxDynamicSharedMemorySize, ATTN_SMEM);

    { dim3 g(32, 16, BSZ); dim3 blk(32, 8); conv_x<<<g, blk>>>(x); }
    prep_w<<<(640 * 512 + 512 * 512 + 255) / 256, 256>>>(qp, kp, vp, wout);

    { dim3 g(5, 16, BSZ); gemm_qkv<<<g, 128, GEMM_SMEM>>>(); }
    { dim3 g(8, NH, BSZ); attn_mma<<<g, 128, ATTN_SMEM>>>(); }
    { dim3 g(8, 8, BSZ); gemm_out<<<g, 128, GEMM_SMEM>>>(out); }
}

// round 13
// speedup vs baseline: 4.4345x; 1.0275x over previous
#include <cuda_runtime.h>
#include <cuda_bf16.h>
#include <cuda_fp16.h>
#include <cstdint>
#include <cstddef>
#include <math.h>

#define BSZ 8
#define NTOK 1024
#define NH 8

// ---------------------------------------------------------------------------
// Device scratch
// ---------------------------------------------------------------------------
__device__ __align__(16) __nv_bfloat16 g_rxh[BSZ * NTOK * 512];   // [b][n][d]
__device__ __align__(16) __nv_bfloat16 g_rxl[BSZ * NTOK * 512];
__device__ __align__(16) __nv_bfloat16 g_Wqh[640 * 512];          // [c][d] (Q pre-scaled 0.125*log2e)
__device__ __align__(16) __nv_bfloat16 g_Wql[640 * 512];
__device__ __align__(16) __nv_bfloat16 g_Woh[512 * 512];          // [dout][c]
__device__ __align__(16) __nv_bfloat16 g_Wol[512 * 512];
__device__ __align__(16) __nv_bfloat16 g_Qh[BSZ * NTOK * 512];    // [b][n][hk] scaled
__device__ __align__(16) __nv_bfloat16 g_Ql[BSZ * NTOK * 512];
__device__ __align__(16) __nv_bfloat16 g_Kh[BSZ * NTOK * 64];     // [b][m][kd]
__device__ __align__(16) __nv_bfloat16 g_Kl[BSZ * NTOK * 64];
__device__ __align__(16) __half g_Vth[BSZ * 64 * NTOK];           // [b][v][m] fp16 hi
__device__ __align__(16) __half g_Vtl[BSZ * 64 * NTOK];           // fp16 lo
__device__ __align__(16) __nv_bfloat16 g_Ohi[BSZ * NTOK * 512];   // [b][n][c]
__device__ __align__(16) __nv_bfloat16 g_Olo[BSZ * NTOK * 512];

// ---------------------------------------------------------------------------
// helpers
// ---------------------------------------------------------------------------
#define SWZ(x) ((x) ^ (((x) >> 3) & 0x70))

__device__ __forceinline__ uint32_t s2u(const void* p) {
    uint32_t a;
    asm("{ .reg .u64 t; cvta.to.shared.u64 t, %1; cvt.u32.u64 %0, t; }" : "=r"(a) : "l"(p));
    return a;
}
__device__ __forceinline__ void cpasync16(uint32_t dst, const void* src) {
    asm volatile("cp.async.cg.shared.global [%0], [%1], 16;" :: "r"(dst), "l"(src));
}
#define CP_COMMIT() asm volatile("cp.async.commit_group;")
#define CP_WAIT(n)  asm volatile("cp.async.wait_group %0;" :: "n"(n))

__device__ __forceinline__ void ldsm4(uint32_t& a, uint32_t& b, uint32_t& c, uint32_t& d,
                                      uint32_t addr) {
    asm volatile("ldmatrix.sync.aligned.m8n8.x4.shared.b16 {%0,%1,%2,%3}, [%4];"
                 : "=r"(a), "=r"(b), "=r"(c), "=r"(d) : "r"(addr));
}
__device__ __forceinline__ void mma16816(float* d, const uint32_t* a, const uint32_t* b) {
    asm volatile(
        "mma.sync.aligned.m16n8k16.row.col.f32.bf16.bf16.f32 "
        "{%0,%1,%2,%3}, {%4,%5,%6,%7}, {%8,%9}, {%0,%1,%2,%3};"
        : "+f"(d[0]), "+f"(d[1]), "+f"(d[2]), "+f"(d[3])
        : "r"(a[0]), "r"(a[1]), "r"(a[2]), "r"(a[3]), "r"(b[0]), "r"(b[1]));
}
__device__ __forceinline__ void mma16816h(float* d, const uint32_t* a, const uint32_t* b) {
    asm volatile(
        "mma.sync.aligned.m16n8k16.row.col.f32.f16.f16.f32 "
        "{%0,%1,%2,%3}, {%4,%5,%6,%7}, {%8,%9}, {%0,%1,%2,%3};"
        : "+f"(d[0]), "+f"(d[1]), "+f"(d[2]), "+f"(d[3])
        : "r"(a[0]), "r"(a[1]), "r"(a[2]), "r"(a[3]), "r"(b[0]), "r"(b[1]));
}
__device__ __forceinline__ float ex2(float x) {
    float r;
    asm("ex2.approx.f32 %0, %1;" : "=f"(r) : "f"(x));
    return r;
}
// packed exp2 of two fp16 values
__device__ __forceinline__ uint32_t h2ex2(uint32_t x) {
    uint32_t r;
    asm("ex2.approx.f16x2 %0, %1;" : "=r"(r) : "r"(x));
    return r;
}
__device__ __forceinline__ void split2(float v, __nv_bfloat16& h, __nv_bfloat16& l) {
    h = __float2bfloat16(v);
    l = __float2bfloat16(v - __bfloat162float(h));
}
__device__ __forceinline__ uint32_t cvt2bf(float f0, float f1) {
    uint32_t r;
    asm("cvt.rn.bf16x2.f32 %0, %1, %2;" : "=r"(r) : "f"(f1), "f"(f0));
    return r;
}
__device__ __forceinline__ uint32_t cvt2h(float f0, float f1) {
    uint32_t r;
    asm("cvt.rn.f16x2.f32 %0, %1, %2;" : "=r"(r) : "f"(f1), "f"(f0));
    return r;
}
__device__ __forceinline__ void split_pair(float f0, float f1, uint32_t& hp, uint32_t& lp) {
    hp = cvt2bf(f0, f1);
    float h0 = __uint_as_float(hp << 16);
    float h1 = __uint_as_float(hp & 0xffff0000u);
    lp = cvt2bf(f0 - h0, f1 - h1);
}

// ---------------------------------------------------------------------------
// prep kernels
// ---------------------------------------------------------------------------
__global__ void conv_x(const float* __restrict__ x) {
    __shared__ float t[32][33];
    const int b = blockIdx.z, d0 = blockIdx.y * 32, n0 = blockIdx.x * 32;
    const int txx = threadIdx.x, tyy = threadIdx.y;
    #pragma unroll
    for (int r = 0; r < 4; r++)
        t[tyy + r * 8][txx] = x[((size_t)b * 512 + d0 + tyy + r * 8) * 1024 + n0 + txx];
    __syncthreads();
    #pragma unroll
    for (int r = 0; r < 4; r++) {
        int n = n0 + tyy + r * 8;
        __nv_bfloat16 h, l;
        split2(t[txx][tyy + r * 8], h, l);
        size_t o = ((size_t)b * 1024 + n) * 512 + d0 + txx;
        g_rxh[o] = h; g_rxl[o] = l;
    }
}

// merged weight prep; Q rows scaled by 0.125 * log2(e)
__global__ void prep_w(const float* __restrict__ qp, const float* __restrict__ kp,
                       const float* __restrict__ vp, const float* __restrict__ wout) {
    int idx = blockIdx.x * 256 + threadIdx.x;
    if (idx < 640 * 512) {
        int c = idx >> 9, d = idx & 511;
        float v;
        if (c < 512)      v = qp[c * 512 + d] * (0.125f * 1.4426950408889634f);
        else if (c < 576) v = kp[d * 64 + (c - 512)];
        else              v = vp[d * 64 + (c - 576)];
        split2(v, g_Wqh[idx], g_Wql[idx]);
    } else {
        int j = idx - 640 * 512;
        if (j < 512 * 512) split2(wout[j], g_Woh[j], g_Wol[j]);
    }
}

// ---------------------------------------------------------------------------
// GEMM core (4-warp CTA, 64x128 tile, 2-stage cp.async, 2 CTAs/SM)
// ---------------------------------------------------------------------------
#define GEMM_SMEM (2 * 49152)
#define STAGE_SZ  49152u

struct GemmAcc { float a[2][8][4]; };

template <typename Epi>
__device__ __forceinline__ void gemm_core(
    const __nv_bfloat16* Ahi, const __nv_bfloat16* Alo,
    const __nv_bfloat16* Bhi, const __nv_bfloat16* Blo,
    int K, Epi epi) {
    extern __shared__ char sm[];
    const uint32_t sbase = s2u(sm);
    const uint32_t OFF[4] = {0u, 8192u, 16384u, 32768u};

    const int tid = threadIdx.x, lane = tid & 31, wid = tid >> 5;
    const int wm = (wid >> 1) * 32, wn = (wid & 1) * 64;

    const __nv_bfloat16* gsrc[4] = {Ahi, Alo, Bhi, Blo};

    auto load_chunk = [&](int stage, int kc) {
        const uint32_t stbase = sbase + stage * STAGE_SZ;
        #pragma unroll
        for (int t = 0; t < 2; t++) {
            #pragma unroll
            for (int i = 0; i < 4; i++) {
                int c = tid + i * 128;
                int row = c >> 3, u = c & 7;
                cpasync16(stbase + OFF[t] + SWZ((uint32_t)(row * 128 + u * 16)),
                          gsrc[t] + (size_t)row * K + kc + u * 8);
            }
        }
        #pragma unroll
        for (int t = 2; t < 4; t++) {
            #pragma unroll
            for (int i = 0; i < 8; i++) {
                int c = tid + i * 128;
                int row = c >> 3, u = c & 7;
                cpasync16(stbase + OFF[t] + SWZ((uint32_t)(row * 128 + u * 16)),
                          gsrc[t] + (size_t)row * K + kc + u * 8);
            }
        }
        CP_COMMIT();
    };

    GemmAcc acc;
    #pragma unroll
    for (int i = 0; i < 2; i++)
        #pragma unroll
        for (int j = 0; j < 8; j++)
            #pragma unroll
            for (int e = 0; e < 4; e++) acc.a[i][j][e] = 0.f;

    const int nchunks = K >> 6;
    load_chunk(0, 0);
    for (int c = 0; c < nchunks; c++) {
        if (c + 1 < nchunks) { load_chunk((c + 1) & 1, (c + 1) << 6); CP_WAIT(1); }
        else                 { CP_WAIT(0); }
        __syncthreads();
        const uint32_t stb = sbase + (c & 1) * STAGE_SZ;

        #pragma unroll
        for (int ks = 0; ks < 4; ks++) {
            uint32_t ah[2][4], al[2][4], bh[8][2], bl[8][2];
            #pragma unroll
            for (int mf = 0; mf < 2; mf++) {
                int row = wm + mf * 16 + (lane & 15);
                int cu = ks * 2 + (lane >> 4);
                uint32_t off = SWZ((uint32_t)(row * 128 + cu * 16));
                ldsm4(ah[mf][0], ah[mf][1], ah[mf][2], ah[mf][3], stb + OFF[0] + off);
                ldsm4(al[mf][0], al[mf][1], al[mf][2], al[mf][3], stb + OFF[1] + off);
            }
            #pragma unroll
            for (int nf2 = 0; nf2 < 4; nf2++) {
                int row = wn + nf2 * 16 + (lane & 7) + ((lane >> 4) << 3);
                int cu = ks * 2 + ((lane >> 3) & 1);
                uint32_t off = SWZ((uint32_t)(row * 128 + cu * 16));
                ldsm4(bh[2 * nf2][0], bh[2 * nf2][1], bh[2 * nf2 + 1][0], bh[2 * nf2 + 1][1],
                      stb + OFF[2] + off);
                ldsm4(bl[2 * nf2][0], bl[2 * nf2][1], bl[2 * nf2 + 1][0], bl[2 * nf2 + 1][1],
                      stb + OFF[3] + off);
            }
            #pragma unroll
            for (int mf = 0; mf < 2; mf++)
                #pragma unroll
                for (int nf = 0; nf < 8; nf++) {
                    mma16816(acc.a[mf][nf], ah[mf], bh[nf]);
                    mma16816(acc.a[mf][nf], ah[mf], bl[nf]);
                    mma16816(acc.a[mf][nf], al[mf], bh[nf]);
                }
        }
        __syncthreads();
    }
    epi(acc, wm, wn, lane);
}

// epilogue functor: QKV split + routing (V -> fp16 hi/lo)
struct QkvEpi {
    int b, mt, nt;
    __device__ void operator()(GemmAcc& acc, int wm, int wn, int lane) const {
        #pragma unroll
        for (int mf = 0; mf < 2; mf++) {
            int r0 = mt * 64 + wm + mf * 16 + (lane >> 2);
            #pragma unroll
            for (int nf = 0; nf < 8; nf++) {
                int col = nt * 128 + wn + nf * 8 + 2 * (lane & 3);
                const float* a = acc.a[mf][nf];
                if (nt < 4) {
                    uint32_t hp, lp;
                    split_pair(a[0], a[1], hp, lp);
                    size_t o0 = ((size_t)b * 1024 + r0) * 512 + col;
                    *(uint32_t*)&g_Qh[o0] = hp; *(uint32_t*)&g_Ql[o0] = lp;
                    split_pair(a[2], a[3], hp, lp);
                    size_t o1 = ((size_t)b * 1024 + r0 + 8) * 512 + col;
                    *(uint32_t*)&g_Qh[o1] = hp; *(uint32_t*)&g_Ql[o1] = lp;
                } else if (wn == 0) {
                    int kc = col - 512;
                    uint32_t hp, lp;
                    split_pair(a[0], a[1], hp, lp);
                    size_t o0 = ((size_t)b * 1024 + r0) * 64 + kc;
                    *(uint32_t*)&g_Kh[o0] = hp; *(uint32_t*)&g_Kl[o0] = lp;
                    split_pair(a[2], a[3], hp, lp);
                    size_t o1 = ((size_t)b * 1024 + r0 + 8) * 64 + kc;
                    *(uint32_t*)&g_Kh[o1] = hp; *(uint32_t*)&g_Kl[o1] = lp;
                } else {
                    int v0 = col - 576;
                    #pragma unroll
                    for (int e = 0; e < 4; e++) {
                        int vv = v0 + (e & 1);
                        int mm = r0 + (e >> 1) * 8;
                        __half h = __float2half(a[e]);
                        __half l = __float2half(a[e] - __half2float(h));
                        size_t o = ((size_t)b * 64 + vv) * 1024 + mm;
                        g_Vth[o] = h; g_Vtl[o] = l;
                    }
                }
            }
        }
    }
};

// epilogue functor: float output
struct OutEpi {
    int b, mt, nt;
    float* D;
    __device__ void operator()(GemmAcc& acc, int wm, int wn, int lane) const {
        #pragma unroll
        for (int mf = 0; mf < 2; mf++) {
            int r0 = mt * 64 + wm + mf * 16 + (lane >> 2);
            #pragma unroll
            for (int nf = 0; nf < 8; nf++) {
                int col = nt * 128 + wn + nf * 8 + 2 * (lane & 3);
                *(float2*)(D + ((size_t)b * 512 + r0) * 1024 + col) =
                    make_float2(acc.a[mf][nf][0], acc.a[mf][nf][1]);
                *(float2*)(D + ((size_t)b * 512 + r0 + 8) * 1024 + col) =
                    make_float2(acc.a[mf][nf][2], acc.a[mf][nf][3]);
            }
        }
    }
};

__global__ void __launch_bounds__(128)
gemm_qkv() {
    const int b = blockIdx.z, mt = blockIdx.y, nt = blockIdx.x;
    QkvEpi epi{b, mt, nt};
    gemm_core(
        g_rxh + ((size_t)b * 1024 + mt * 64) * 512,
        g_rxl + ((size_t)b * 1024 + mt * 64) * 512,
        g_Wqh + (size_t)nt * 128 * 512,
        g_Wql + (size_t)nt * 128 * 512,
        512, epi);
}

__global__ void __launch_bounds__(128)
gemm_out(float* __restrict__ D) {
    const int b = blockIdx.z, mt = blockIdx.y, nt = blockIdx.x;
    OutEpi epi{b, mt, nt, D};
    gemm_core(
        g_Woh + (size_t)mt * 64 * 512,
        g_Wol + (size_t)mt * 64 * 512,
        g_Ohi + ((size_t)b * 1024 + nt * 128) * 512,
        g_Olo + ((size_t)b * 1024 + nt * 128) * 512,
        512, epi);
}

// ---------------------------------------------------------------------------
// HMMA flash attention: 4-warp CTA, 128 q-rows, 2-stage KV, 2 CTAs/SM.
// Base-2 softmax; P computed as fp16 via packed ex2.approx.f16x2.
// Row sum l computed by a ones-column PV MMA (9th V fragment) — no FMA/shfl
// sum chain, and l is consistent with the fp16 P used in PV.
// ---------------------------------------------------------------------------
#define ATTN_SMEM 98304

__global__ void __launch_bounds__(128, 2)
attn_mma() {
    extern __shared__ char sm[];
    const uint32_t sbase = s2u(sm);
    const uint32_t QH = 0u, QL = 16384u, STG = 32768u;

    const int tid = threadIdx.x, lane = tid & 31, wid = tid >> 5;
    const int b = blockIdx.z, h = blockIdx.y, n0 = blockIdx.x * 128;
    const int phase = ((blockIdx.x + blockIdx.y) & 1) << 3;

    const __nv_bfloat16* Qhb = g_Qh + ((size_t)b * 1024 + n0) * 512 + h * 64;
    const __nv_bfloat16* Qlb = g_Ql + ((size_t)b * 1024 + n0) * 512 + h * 64;
    const __nv_bfloat16* Khb = g_Kh + (size_t)b * 1024 * 64;
    const __nv_bfloat16* Klb = g_Kl + (size_t)b * 1024 * 64;
    const __half* Vhb = g_Vth + (size_t)b * 64 * 1024;
    const __half* Vlb = g_Vtl + (size_t)b * 64 * 1024;

    // ones B-fragment: col n=0 (global col 64) = 1.0, cols 65..71 = 0
    uint32_t b_ones[2];
    b_ones[0] = b_ones[1] = ((lane >> 2) == 0) ? 0x3C003C00u : 0u;

    // Q load
    #pragma unroll
    for (int i = 0; i < 8; i++) {
        int c = tid + i * 128;
        int row = c >> 3, u = c & 7;
        uint32_t off = SWZ((uint32_t)(row * 128 + u * 16));
        cpasync16(sbase + QH + off, Qhb + (size_t)row * 512 + u * 8);
        cpasync16(sbase + QL + off, Qlb + (size_t)row * 512 + u * 8);
    }
    CP_COMMIT();

    auto load_kv = [&](int stage, int m0) {
        const uint32_t stb = sbase + STG + stage * 32768u;
        #pragma unroll
        for (int i = 0; i < 4; i++) {
            int c = tid + i * 128;
            int row = c >> 3, u = c & 7;
            uint32_t off = SWZ((uint32_t)(row * 128 + u * 16));
            cpasync16(stb + off,          Khb + (size_t)(m0 + row) * 64 + u * 8);
            cpasync16(stb + 8192u + off,  Klb + (size_t)(m0 + row) * 64 + u * 8);
            cpasync16(stb + 16384u + off, Vhb + (size_t)row * 1024 + m0 + u * 8);
            cpasync16(stb + 24576u + off, Vlb + (size_t)row * 1024 + m0 + u * 8);
        }
        CP_COMMIT();
    };

    load_kv(0, phase * 64);

    float m_i[2][2], oacc[2][8][4], oacc_s[2][4];
    #pragma unroll
    for (int mf = 0; mf < 2; mf++) {
        m_i[mf][0] = m_i[mf][1] = -1e30f;
        #pragma unroll
        for (int e = 0; e < 4; e++) oacc_s[mf][e] = 0.f;
        #pragma unroll
        for (int nf = 0; nf < 8; nf++)
            #pragma unroll
            for (int e = 0; e < 4; e++) oacc[mf][nf][e] = 0.f;
    }

    for (int ic = 0; ic < 16; ic++) {
        if (ic + 1 < 16) {
            load_kv((ic + 1) & 1, (((ic + 1) + phase) & 15) * 64);
            CP_WAIT(1);
        } else {
            CP_WAIT(0);
        }
        __syncthreads();
        const uint32_t KHs = STG + (uint32_t)(ic & 1) * 32768u;
        const uint32_t KLs = KHs + 8192u, VHs = KHs + 16384u, VLs = KHs + 24576u;

        // ---- S = Q K^T (3-term bf16, base-2 scaled) ----
        float sacc[2][8][4];
        #pragma unroll
        for (int mf = 0; mf < 2; mf++)
            #pragma unroll
            for (int nf = 0; nf < 8; nf++)
                #pragma unroll
                for (int e = 0; e < 4; e++) sacc[mf][nf][e] = 0.f;

        #pragma unroll
        for (int ks = 0; ks < 4; ks++) {
            uint32_t qh[2][4], ql[2][4], bh[8][2], bl[8][2];
            #pragma unroll
            for (int mf = 0; mf < 2; mf++) {
                int row = wid * 32 + mf * 16 + (lane & 15);
                int cu = ks * 2 + (lane >> 4);
                uint32_t off = SWZ((uint32_t)(row * 128 + cu * 16));
                ldsm4(qh[mf][0], qh[mf][1], qh[mf][2], qh[mf][3], sbase + QH + off);
                ldsm4(ql[mf][0], ql[mf][1], ql[mf][2], ql[mf][3], sbase + QL + off);
            }
            #pragma unroll
            for (int nf2 = 0; nf2 < 4; nf2++) {
                int row = nf2 * 16 + (lane & 7) + ((lane >> 4) << 3);
                int cu = ks * 2 + ((lane >> 3) & 1);
                uint32_t off = SWZ((uint32_t)(row * 128 + cu * 16));
                ldsm4(bh[2 * nf2][0], bh[2 * nf2][1], bh[2 * nf2 + 1][0], bh[2 * nf2 + 1][1],
                      sbase + KHs + off);
                ldsm4(bl[2 * nf2][0], bl[2 * nf2][1], bl[2 * nf2 + 1][0], bl[2 * nf2 + 1][1],
                      sbase + KLs + off);
            }
            #pragma unroll
            for (int mf = 0; mf < 2; mf++)
                #pragma unroll
                for (int nf = 0; nf < 8; nf++) {
                    mma16816(sacc[mf][nf], qh[mf], bh[nf]);
                    mma16816(sacc[mf][nf], qh[mf], bl[nf]);
                    mma16816(sacc[mf][nf], ql[mf], bh[nf]);
                }
        }

        // ---- online softmax (base 2); P built as packed fp16 ----
        uint32_t pp[2][8][2];
        #pragma unroll
        for (int mf = 0; mf < 2; mf++) {
            float mx0 = -1e30f, mx1 = -1e30f;
            #pragma unroll
            for (int nf = 0; nf < 8; nf++) {
                mx0 = fmaxf(mx0, fmaxf(sacc[mf][nf][0], sacc[mf][nf][1]));
                mx1 = fmaxf(mx1, fmaxf(sacc[mf][nf][2], sacc[mf][nf][3]));
            }
            mx0 = fmaxf(mx0, __shfl_xor_sync(0xffffffffu, mx0, 1));
            mx0 = fmaxf(mx0, __shfl_xor_sync(0xffffffffu, mx0, 2));
            mx1 = fmaxf(mx1, __shfl_xor_sync(0xffffffffu, mx1, 1));
            mx1 = fmaxf(mx1, __shfl_xor_sync(0xffffffffu, mx1, 2));
            float mn0 = fmaxf(m_i[mf][0], mx0), mn1 = fmaxf(m_i[mf][1], mx1);
            float c0 = ex2(m_i[mf][0] - mn0), c1 = ex2(m_i[mf][1] - mn1);
            m_i[mf][0] = mn0; m_i[mf][1] = mn1;
            #pragma unroll
            for (int nf = 0; nf < 8; nf++) {
                pp[mf][nf][0] = h2ex2(cvt2h(sacc[mf][nf][0] - mn0, sacc[mf][nf][1] - mn0));
                pp[mf][nf][1] = h2ex2(cvt2h(sacc[mf][nf][2] - mn1, sacc[mf][nf][3] - mn1));
                oacc[mf][nf][0] *= c0; oacc[mf][nf][1] *= c0;
                oacc[mf][nf][2] *= c1; oacc[mf][nf][3] *= c1;
            }
            oacc_s[mf][0] *= c0; oacc_s[mf][1] *= c0;
            oacc_s[mf][2] *= c1; oacc_s[mf][3] *= c1;
        }

        // ---- O += P V  (fp16 P x fp16 V hi/lo) + ones-column row sum ----
        #pragma unroll
        for (int ks = 0; ks < 4; ks++) {
            uint32_t pa[2][4];
            #pragma unroll
            for (int mf = 0; mf < 2; mf++) {
                pa[mf][0] = pp[mf][2 * ks][0];
                pa[mf][1] = pp[mf][2 * ks][1];
                pa[mf][2] = pp[mf][2 * ks + 1][0];
                pa[mf][3] = pp[mf][2 * ks + 1][1];
            }
            uint32_t vh[8][2], vl[8][2];
            #pragma unroll
            for (int nf2 = 0; nf2 < 4; nf2++) {
                int row = nf2 * 16 + (lane & 7) + ((lane >> 4) << 3);
                int cu = ks * 2 + ((lane >> 3) & 1);
                uint32_t off = SWZ((uint32_t)(row * 128 + cu * 16));
                ldsm4(vh[2 * nf2][0], vh[2 * nf2][1], vh[2 * nf2 + 1][0], vh[2 * nf2 + 1][1],
                      sbase + VHs + off);
                ldsm4(vl[2 * nf2][0], vl[2 * nf2][1], vl[2 * nf2 + 1][0], vl[2 * nf2 + 1][1],
                      sbase + VLs + off);
            }
            #pragma unroll
            for (int mf = 0; mf < 2; mf++) {
                #pragma unroll
                for (int nf = 0; nf < 8; nf++) {
                    mma16816h(oacc[mf][nf], pa[mf], vh[nf]);
                    mma16816h(oacc[mf][nf], pa[mf], vl[nf]);
                }
                mma16816h(oacc_s[mf], pa[mf], b_ones);
            }
        }
        __syncthreads();
    }

    // ---- epilogue: l lives in quad-leader lanes (col 64), broadcast ----
    #pragma unroll
    for (int mf = 0; mf < 2; mf++) {
        float l0 = __shfl_sync(0xffffffffu, oacc_s[mf][0], lane & 28);
        float l1 = __shfl_sync(0xffffffffu, oacc_s[mf][2], lane & 28);
        float inv0 = 1.0f / l0, inv1 = 1.0f / l1;
        int nr0 = n0 + wid * 32 + mf * 16 + (lane >> 2);
        #pragma unroll
        for (int nf = 0; nf < 8; nf++) {
            int col = h * 64 + nf * 8 + 2 * (lane & 3);
            uint32_t hp, lp;
            split_pair(oacc[mf][nf][0] * inv0, oacc[mf][nf][1] * inv0, hp, lp);
            size_t base0 = ((size_t)b * 1024 + nr0) * 512 + col;
            *(uint32_t*)&g_Ohi[base0] = hp;
            *(uint32_t*)&g_Olo[base0] = lp;
            split_pair(oacc[mf][nf][2] * inv1, oacc[mf][nf][3] * inv1, hp, lp);
            size_t base1 = ((size_t)b * 1024 + nr0 + 8) * 512 + col;
            *(uint32_t*)&g_Ohi[base1] = hp;
            *(uint32_t*)&g_Olo[base1] = lp;
        }
    }
}

// ---------------------------------------------------------------------------
extern "C" void kernel_launch(void* const* d_in, const int* in_sizes, int n_in,
                              void* d_out, int out_size) {
    const float* x    = (const float*)d_in[0];
    const float* qp   = (const float*)d_in[1];
    const float* kp   = (const float*)d_in[2];
    const float* vp   = (const float*)d_in[3];
    const float* wout = (const float*)d_in[4];
    float* out = (float*)d_out;

    cudaFuncSetAttribute(gemm_qkv, cudaFuncAttributeMaxDynamicSharedMemorySize, GEMM_SMEM);
    cudaFuncSetAttribute(gemm_out, cudaFuncAttributeMaxDynamicSharedMemorySize, GEMM_SMEM);
    cudaFuncSetAttribute(attn_mma, cudaFuncAttributeMaxDynamicSharedMemorySize, ATTN_SMEM);

    { dim3 g(32, 16, BSZ); dim3 blk(32, 8); conv_x<<<g, blk>>>(x); }
    prep_w<<<(640 * 512 + 512 * 512 + 255) / 256, 256>>>(qp, kp, vp, wout);

    { dim3 g(5, 16, BSZ); gemm_qkv<<<g, 128, GEMM_SMEM>>>(); }
    { dim3 g(8, NH, BSZ); attn_mma<<<g, 128, ATTN_SMEM>>>(); }
    { dim3 g(8, 8, BSZ); gemm_out<<<g, 128, GEMM_SMEM>>>(out); }
}

// round 15
// speedup vs baseline: 4.9203x; 1.1095x over previous
#include <cuda_runtime.h>
#include <cuda_bf16.h>
#include <cuda_fp16.h>
#include <cstdint>
#include <cstddef>
#include <math.h>

#define BSZ 8
#define NTOK 1024
#define NH 8

// ---------------------------------------------------------------------------
// Device scratch
// ---------------------------------------------------------------------------
__device__ __align__(16) __nv_bfloat16 g_rxh[BSZ * NTOK * 512];   // [b][n][d]
__device__ __align__(16) __nv_bfloat16 g_rxl[BSZ * NTOK * 512];
__device__ __align__(16) __nv_bfloat16 g_Wqh[640 * 512];          // [c][d] (Q pre-scaled 0.125*log2e)
__device__ __align__(16) __nv_bfloat16 g_Wql[640 * 512];
__device__ __align__(16) __nv_bfloat16 g_Woh[512 * 512];          // [dout][c]
__device__ __align__(16) __nv_bfloat16 g_Wol[512 * 512];
__device__ __align__(16) __nv_bfloat16 g_Qh[BSZ * NTOK * 512];    // [b][n][hk] scaled
__device__ __align__(16) __nv_bfloat16 g_Ql[BSZ * NTOK * 512];
__device__ __align__(16) __nv_bfloat16 g_Kh[BSZ * NTOK * 64];     // [b][m][kd]
__device__ __align__(16) __nv_bfloat16 g_Kl[BSZ * NTOK * 64];
__device__ __align__(16) __half g_Vt[BSZ * 64 * NTOK];            // [b][v][m] fp16 (single)
__device__ __align__(16) __nv_bfloat16 g_Ohi[BSZ * NTOK * 512];   // [b][n][c]
__device__ __align__(16) __nv_bfloat16 g_Olo[BSZ * NTOK * 512];

// ---------------------------------------------------------------------------
// helpers
// ---------------------------------------------------------------------------
#define SWZ(x) ((x) ^ (((x) >> 3) & 0x70))

__device__ __forceinline__ uint32_t s2u(const void* p) {
    uint32_t a;
    asm("{ .reg .u64 t; cvta.to.shared.u64 t, %1; cvt.u32.u64 %0, t; }" : "=r"(a) : "l"(p));
    return a;
}
__device__ __forceinline__ void cpasync16(uint32_t dst, const void* src) {
    asm volatile("cp.async.cg.shared.global [%0], [%1], 16;" :: "r"(dst), "l"(src));
}
#define CP_COMMIT() asm volatile("cp.async.commit_group;")
#define CP_WAIT(n)  asm volatile("cp.async.wait_group %0;" :: "n"(n))

__device__ __forceinline__ void ldsm4(uint32_t& a, uint32_t& b, uint32_t& c, uint32_t& d,
                                      uint32_t addr) {
    asm volatile("ldmatrix.sync.aligned.m8n8.x4.shared.b16 {%0,%1,%2,%3}, [%4];"
                 : "=r"(a), "=r"(b), "=r"(c), "=r"(d) : "r"(addr));
}
__device__ __forceinline__ void mma16816(float* d, const uint32_t* a, const uint32_t* b) {
    asm volatile(
        "mma.sync.aligned.m16n8k16.row.col.f32.bf16.bf16.f32 "
        "{%0,%1,%2,%3}, {%4,%5,%6,%7}, {%8,%9}, {%0,%1,%2,%3};"
        : "+f"(d[0]), "+f"(d[1]), "+f"(d[2]), "+f"(d[3])
        : "r"(a[0]), "r"(a[1]), "r"(a[2]), "r"(a[3]), "r"(b[0]), "r"(b[1]));
}
__device__ __forceinline__ void mma16816h(float* d, const uint32_t* a, const uint32_t* b) {
    asm volatile(
        "mma.sync.aligned.m16n8k16.row.col.f32.f16.f16.f32 "
        "{%0,%1,%2,%3}, {%4,%5,%6,%7}, {%8,%9}, {%0,%1,%2,%3};"
        : "+f"(d[0]), "+f"(d[1]), "+f"(d[2]), "+f"(d[3])
        : "r"(a[0]), "r"(a[1]), "r"(a[2]), "r"(a[3]), "r"(b[0]), "r"(b[1]));
}
__device__ __forceinline__ float ex2(float x) {
    float r;
    asm("ex2.approx.f32 %0, %1;" : "=f"(r) : "f"(x));
    return r;
}
__device__ __forceinline__ uint32_t h2ex2(uint32_t x) {
    uint32_t r;
    asm("ex2.approx.f16x2 %0, %1;" : "=r"(r) : "r"(x));
    return r;
}
__device__ __forceinline__ void split2(float v, __nv_bfloat16& h, __nv_bfloat16& l) {
    h = __float2bfloat16(v);
    l = __float2bfloat16(v - __bfloat162float(h));
}
__device__ __forceinline__ uint32_t cvt2bf(float f0, float f1) {
    uint32_t r;
    asm("cvt.rn.bf16x2.f32 %0, %1, %2;" : "=r"(r) : "f"(f1), "f"(f0));
    return r;
}
__device__ __forceinline__ uint32_t cvt2h(float f0, float f1) {
    uint32_t r;
    asm("cvt.rn.f16x2.f32 %0, %1, %2;" : "=r"(r) : "f"(f1), "f"(f0));
    return r;
}
__device__ __forceinline__ void split_pair(float f0, float f1, uint32_t& hp, uint32_t& lp) {
    hp = cvt2bf(f0, f1);
    float h0 = __uint_as_float(hp << 16);
    float h1 = __uint_as_float(hp & 0xffff0000u);
    lp = cvt2bf(f0 - h0, f1 - h1);
}

// ---------------------------------------------------------------------------
// prep kernels
// ---------------------------------------------------------------------------
__global__ void conv_x(const float* __restrict__ x) {
    __shared__ float t[32][33];
    const int b = blockIdx.z, d0 = blockIdx.y * 32, n0 = blockIdx.x * 32;
    const int txx = threadIdx.x, tyy = threadIdx.y;
    #pragma unroll
    for (int r = 0; r < 4; r++)
        t[tyy + r * 8][txx] = x[((size_t)b * 512 + d0 + tyy + r * 8) * 1024 + n0 + txx];
    __syncthreads();
    #pragma unroll
    for (int r = 0; r < 4; r++) {
        int n = n0 + tyy + r * 8;
        __nv_bfloat16 h, l;
        split2(t[txx][tyy + r * 8], h, l);
        size_t o = ((size_t)b * 1024 + n) * 512 + d0 + txx;
        g_rxh[o] = h; g_rxl[o] = l;
    }
}

// merged weight prep; Q rows scaled by 0.125 * log2(e)
__global__ void prep_w(const float* __restrict__ qp, const float* __restrict__ kp,
                       const float* __restrict__ vp, const float* __restrict__ wout) {
    int idx = blockIdx.x * 256 + threadIdx.x;
    if (idx < 640 * 512) {
        int c = idx >> 9, d = idx & 511;
        float v;
        if (c < 512)      v = qp[c * 512 + d] * (0.125f * 1.4426950408889634f);
        else if (c < 576) v = kp[d * 64 + (c - 512)];
        else              v = vp[d * 64 + (c - 576)];
        split2(v, g_Wqh[idx], g_Wql[idx]);
    } else {
        int j = idx - 640 * 512;
        if (j < 512 * 512) split2(wout[j], g_Woh[j], g_Wol[j]);
    }
}

// ---------------------------------------------------------------------------
// GEMM core (4-warp CTA, 64x128 tile, 2-stage cp.async, 2 CTAs/SM)
// ---------------------------------------------------------------------------
#define GEMM_SMEM (2 * 49152)
#define STAGE_SZ  49152u

struct GemmAcc { float a[2][8][4]; };

template <typename Epi>
__device__ __forceinline__ void gemm_core(
    const __nv_bfloat16* Ahi, const __nv_bfloat16* Alo,
    const __nv_bfloat16* Bhi, const __nv_bfloat16* Blo,
    int K, Epi epi) {
    extern __shared__ char sm[];
    const uint32_t sbase = s2u(sm);
    const uint32_t OFF[4] = {0u, 8192u, 16384u, 32768u};

    const int tid = threadIdx.x, lane = tid & 31, wid = tid >> 5;
    const int wm = (wid >> 1) * 32, wn = (wid & 1) * 64;

    const __nv_bfloat16* gsrc[4] = {Ahi, Alo, Bhi, Blo};

    auto load_chunk = [&](int stage, int kc) {
        const uint32_t stbase = sbase + stage * STAGE_SZ;
        #pragma unroll
        for (int t = 0; t < 2; t++) {
            #pragma unroll
            for (int i = 0; i < 4; i++) {
                int c = tid + i * 128;
                int row = c >> 3, u = c & 7;
                cpasync16(stbase + OFF[t] + SWZ((uint32_t)(row * 128 + u * 16)),
                          gsrc[t] + (size_t)row * K + kc + u * 8);
            }
        }
        #pragma unroll
        for (int t = 2; t < 4; t++) {
            #pragma unroll
            for (int i = 0; i < 8; i++) {
                int c = tid + i * 128;
                int row = c >> 3, u = c & 7;
                cpasync16(stbase + OFF[t] + SWZ((uint32_t)(row * 128 + u * 16)),
                          gsrc[t] + (size_t)row * K + kc + u * 8);
            }
        }
        CP_COMMIT();
    };

    GemmAcc acc;
    #pragma unroll
    for (int i = 0; i < 2; i++)
        #pragma unroll
        for (int j = 0; j < 8; j++)
            #pragma unroll
            for (int e = 0; e < 4; e++) acc.a[i][j][e] = 0.f;

    const int nchunks = K >> 6;
    load_chunk(0, 0);
    for (int c = 0; c < nchunks; c++) {
        if (c + 1 < nchunks) { load_chunk((c + 1) & 1, (c + 1) << 6); CP_WAIT(1); }
        else                 { CP_WAIT(0); }
        __syncthreads();
        const uint32_t stb = sbase + (c & 1) * STAGE_SZ;

        #pragma unroll
        for (int ks = 0; ks < 4; ks++) {
            uint32_t ah[2][4], al[2][4], bh[8][2], bl[8][2];
            #pragma unroll
            for (int mf = 0; mf < 2; mf++) {
                int row = wm + mf * 16 + (lane & 15);
                int cu = ks * 2 + (lane >> 4);
                uint32_t off = SWZ((uint32_t)(row * 128 + cu * 16));
                ldsm4(ah[mf][0], ah[mf][1], ah[mf][2], ah[mf][3], stb + OFF[0] + off);
                ldsm4(al[mf][0], al[mf][1], al[mf][2], al[mf][3], stb + OFF[1] + off);
            }
            #pragma unroll
            for (int nf2 = 0; nf2 < 4; nf2++) {
                int row = wn + nf2 * 16 + (lane & 7) + ((lane >> 4) << 3);
                int cu = ks * 2 + ((lane >> 3) & 1);
                uint32_t off = SWZ((uint32_t)(row * 128 + cu * 16));
                ldsm4(bh[2 * nf2][0], bh[2 * nf2][1], bh[2 * nf2 + 1][0], bh[2 * nf2 + 1][1],
                      stb + OFF[2] + off);
                ldsm4(bl[2 * nf2][0], bl[2 * nf2][1], bl[2 * nf2 + 1][0], bl[2 * nf2 + 1][1],
                      stb + OFF[3] + off);
            }
            #pragma unroll
            for (int mf = 0; mf < 2; mf++)
                #pragma unroll
                for (int nf = 0; nf < 8; nf++) {
                    mma16816(acc.a[mf][nf], ah[mf], bh[nf]);
                    mma16816(acc.a[mf][nf], ah[mf], bl[nf]);
                    mma16816(acc.a[mf][nf], al[mf], bh[nf]);
                }
        }
        __syncthreads();
    }
    epi(acc, wm, wn, lane);
}

// epilogue functor: QKV split + routing (V -> single fp16, rounded)
struct QkvEpi {
    int b, mt, nt;
    __device__ void operator()(GemmAcc& acc, int wm, int wn, int lane) const {
        #pragma unroll
        for (int mf = 0; mf < 2; mf++) {
            int r0 = mt * 64 + wm + mf * 16 + (lane >> 2);
            #pragma unroll
            for (int nf = 0; nf < 8; nf++) {
                int col = nt * 128 + wn + nf * 8 + 2 * (lane & 3);
                const float* a = acc.a[mf][nf];
                if (nt < 4) {
                    uint32_t hp, lp;
                    split_pair(a[0], a[1], hp, lp);
                    size_t o0 = ((size_t)b * 1024 + r0) * 512 + col;
                    *(uint32_t*)&g_Qh[o0] = hp; *(uint32_t*)&g_Ql[o0] = lp;
                    split_pair(a[2], a[3], hp, lp);
                    size_t o1 = ((size_t)b * 1024 + r0 + 8) * 512 + col;
                    *(uint32_t*)&g_Qh[o1] = hp; *(uint32_t*)&g_Ql[o1] = lp;
                } else if (wn == 0) {
                    int kc = col - 512;
                    uint32_t hp, lp;
                    split_pair(a[0], a[1], hp, lp);
                    size_t o0 = ((size_t)b * 1024 + r0) * 64 + kc;
                    *(uint32_t*)&g_Kh[o0] = hp; *(uint32_t*)&g_Kl[o0] = lp;
                    split_pair(a[2], a[3], hp, lp);
                    size_t o1 = ((size_t)b * 1024 + r0 + 8) * 64 + kc;
                    *(uint32_t*)&g_Kh[o1] = hp; *(uint32_t*)&g_Kl[o1] = lp;
                } else {
                    int v0 = col - 576;
                    #pragma unroll
                    for (int e = 0; e < 4; e++) {
                        int vv = v0 + (e & 1);
                        int mm = r0 + (e >> 1) * 8;
                        size_t o = ((size_t)b * 64 + vv) * 1024 + mm;
                        g_Vt[o] = __float2half_rn(a[e]);
                    }
                }
            }
        }
    }
};

// epilogue functor: float output
struct OutEpi {
    int b, mt, nt;
    float* D;
    __device__ void operator()(GemmAcc& acc, int wm, int wn, int lane) const {
        #pragma unroll
        for (int mf = 0; mf < 2; mf++) {
            int r0 = mt * 64 + wm + mf * 16 + (lane >> 2);
            #pragma unroll
            for (int nf = 0; nf < 8; nf++) {
                int col = nt * 128 + wn + nf * 8 + 2 * (lane & 3);
                *(float2*)(D + ((size_t)b * 512 + r0) * 1024 + col) =
                    make_float2(acc.a[mf][nf][0], acc.a[mf][nf][1]);
                *(float2*)(D + ((size_t)b * 512 + r0 + 8) * 1024 + col) =
                    make_float2(acc.a[mf][nf][2], acc.a[mf][nf][3]);
            }
        }
    }
};

__global__ void __launch_bounds__(128)
gemm_qkv() {
    const int b = blockIdx.z, mt = blockIdx.y, nt = blockIdx.x;
    QkvEpi epi{b, mt, nt};
    gemm_core(
        g_rxh + ((size_t)b * 1024 + mt * 64) * 512,
        g_rxl + ((size_t)b * 1024 + mt * 64) * 512,
        g_Wqh + (size_t)nt * 128 * 512,
        g_Wql + (size_t)nt * 128 * 512,
        512, epi);
}

__global__ void __launch_bounds__(128)
gemm_out(float* __restrict__ D) {
    const int b = blockIdx.z, mt = blockIdx.y, nt = blockIdx.x;
    OutEpi epi{b, mt, nt, D};
    gemm_core(
        g_Woh + (size_t)mt * 64 * 512,
        g_Wol + (size_t)mt * 64 * 512,
        g_Ohi + ((size_t)b * 1024 + nt * 128) * 512,
        g_Olo + ((size_t)b * 1024 + nt * 128) * 512,
        512, epi);
}

// ---------------------------------------------------------------------------
// HMMA flash attention: 4-warp CTA, 128 q-rows, 2-stage KV, 2 CTAs/SM.
// Base-2 softmax; P fp16 via packed ex2; V single fp16; ones-column row sum.
// smem: Qh 0 | Ql 16K | stages 32K + s*24K: {Kh 0 | Kl 8K | Vh 16K}  -> 80K
// ---------------------------------------------------------------------------
#define ATTN_SMEM 81920
#define KV_STAGE 24576u

__global__ void __launch_bounds__(128, 2)
attn_mma() {
    extern __shared__ char sm[];
    const uint32_t sbase = s2u(sm);
    const uint32_t QH = 0u, QL = 16384u, STG = 32768u;

    const int tid = threadIdx.x, lane = tid & 31, wid = tid >> 5;
    const int b = blockIdx.z, h = blockIdx.y, n0 = blockIdx.x * 128;
    const int phase = ((blockIdx.x + blockIdx.y) & 1) << 3;

    const __nv_bfloat16* Qhb = g_Qh + ((size_t)b * 1024 + n0) * 512 + h * 64;
    const __nv_bfloat16* Qlb = g_Ql + ((size_t)b * 1024 + n0) * 512 + h * 64;
    const __nv_bfloat16* Khb = g_Kh + (size_t)b * 1024 * 64;
    const __nv_bfloat16* Klb = g_Kl + (size_t)b * 1024 * 64;
    const __half* Vb = g_Vt + (size_t)b * 64 * 1024;

    // ones B-fragment: col n=0 (global col 64) = 1.0
    uint32_t b_ones[2];
    b_ones[0] = b_ones[1] = ((lane >> 2) == 0) ? 0x3C003C00u : 0u;

    // Q load
    #pragma unroll
    for (int i = 0; i < 8; i++) {
        int c = tid + i * 128;
        int row = c >> 3, u = c & 7;
        uint32_t off = SWZ((uint32_t)(row * 128 + u * 16));
        cpasync16(sbase + QH + off, Qhb + (size_t)row * 512 + u * 8);
        cpasync16(sbase + QL + off, Qlb + (size_t)row * 512 + u * 8);
    }
    CP_COMMIT();

    auto load_kv = [&](int stage, int m0) {
        const uint32_t stb = sbase + STG + stage * KV_STAGE;
        #pragma unroll
        for (int i = 0; i < 4; i++) {
            int c = tid + i * 128;
            int row = c >> 3, u = c & 7;
            uint32_t off = SWZ((uint32_t)(row * 128 + u * 16));
            cpasync16(stb + off,          Khb + (size_t)(m0 + row) * 64 + u * 8);
            cpasync16(stb + 8192u + off,  Klb + (size_t)(m0 + row) * 64 + u * 8);
            cpasync16(stb + 16384u + off, Vb + (size_t)row * 1024 + m0 + u * 8);
        }
        CP_COMMIT();
    };

    load_kv(0, phase * 64);

    float m_i[2][2], oacc[2][8][4], oacc_s[2][4];
    #pragma unroll
    for (int mf = 0; mf < 2; mf++) {
        m_i[mf][0] = m_i[mf][1] = -1e30f;
        #pragma unroll
        for (int e = 0; e < 4; e++) oacc_s[mf][e] = 0.f;
        #pragma unroll
        for (int nf = 0; nf < 8; nf++)
            #pragma unroll
            for (int e = 0; e < 4; e++) oacc[mf][nf][e] = 0.f;
    }

    for (int ic = 0; ic < 16; ic++) {
        if (ic + 1 < 16) {
            load_kv((ic + 1) & 1, (((ic + 1) + phase) & 15) * 64);
            CP_WAIT(1);
        } else {
            CP_WAIT(0);
        }
        __syncthreads();
        const uint32_t KHs = STG + (uint32_t)(ic & 1) * KV_STAGE;
        const uint32_t KLs = KHs + 8192u, VHs = KHs + 16384u;

        // ---- S = Q K^T (3-term bf16, base-2 scaled) ----
        float sacc[2][8][4];
        #pragma unroll
        for (int mf = 0; mf < 2; mf++)
            #pragma unroll
            for (int nf = 0; nf < 8; nf++)
                #pragma unroll
                for (int e = 0; e < 4; e++) sacc[mf][nf][e] = 0.f;

        #pragma unroll
        for (int ks = 0; ks < 4; ks++) {
            uint32_t qh[2][4], ql[2][4], bh[8][2], bl[8][2];
            #pragma unroll
            for (int mf = 0; mf < 2; mf++) {
                int row = wid * 32 + mf * 16 + (lane & 15);
                int cu = ks * 2 + (lane >> 4);
                uint32_t off = SWZ((uint32_t)(row * 128 + cu * 16));
                ldsm4(qh[mf][0], qh[mf][1], qh[mf][2], qh[mf][3], sbase + QH + off);
                ldsm4(ql[mf][0], ql[mf][1], ql[mf][2], ql[mf][3], sbase + QL + off);
            }
            #pragma unroll
            for (int nf2 = 0; nf2 < 4; nf2++) {
                int row = nf2 * 16 + (lane & 7) + ((lane >> 4) << 3);
                int cu = ks * 2 + ((lane >> 3) & 1);
                uint32_t off = SWZ((uint32_t)(row * 128 + cu * 16));
                ldsm4(bh[2 * nf2][0], bh[2 * nf2][1], bh[2 * nf2 + 1][0], bh[2 * nf2 + 1][1],
                      sbase + KHs + off);
                ldsm4(bl[2 * nf2][0], bl[2 * nf2][1], bl[2 * nf2 + 1][0], bl[2 * nf2 + 1][1],
                      sbase + KLs + off);
            }
            #pragma unroll
            for (int mf = 0; mf < 2; mf++)
                #pragma unroll
                for (int nf = 0; nf < 8; nf++) {
                    mma16816(sacc[mf][nf], qh[mf], bh[nf]);
                    mma16816(sacc[mf][nf], qh[mf], bl[nf]);
                    mma16816(sacc[mf][nf], ql[mf], bh[nf]);
                }
        }

        // ---- online softmax (base 2); P as packed fp16 ----
        uint32_t pp[2][8][2];
        #pragma unroll
        for (int mf = 0; mf < 2; mf++) {
            float mx0 = -1e30f, mx1 = -1e30f;
            #pragma unroll
            for (int nf = 0; nf < 8; nf++) {
                mx0 = fmaxf(mx0, fmaxf(sacc[mf][nf][0], sacc[mf][nf][1]));
                mx1 = fmaxf(mx1, fmaxf(sacc[mf][nf][2], sacc[mf][nf][3]));
            }
            mx0 = fmaxf(mx0, __shfl_xor_sync(0xffffffffu, mx0, 1));
            mx0 = fmaxf(mx0, __shfl_xor_sync(0xffffffffu, mx0, 2));
            mx1 = fmaxf(mx1, __shfl_xor_sync(0xffffffffu, mx1, 1));
            mx1 = fmaxf(mx1, __shfl_xor_sync(0xffffffffu, mx1, 2));
            float mn0 = fmaxf(m_i[mf][0], mx0), mn1 = fmaxf(m_i[mf][1], mx1);
            float c0 = ex2(m_i[mf][0] - mn0), c1 = ex2(m_i[mf][1] - mn1);
            m_i[mf][0] = mn0; m_i[mf][1] = mn1;
            #pragma unroll
            for (int nf = 0; nf < 8; nf++) {
                pp[mf][nf][0] = h2ex2(cvt2h(sacc[mf][nf][0] - mn0, sacc[mf][nf][1] - mn0));
                pp[mf][nf][1] = h2ex2(cvt2h(sacc[mf][nf][2] - mn1, sacc[mf][nf][3] - mn1));
                oacc[mf][nf][0] *= c0; oacc[mf][nf][1] *= c0;
                oacc[mf][nf][2] *= c1; oacc[mf][nf][3] *= c1;
            }
            oacc_s[mf][0] *= c0; oacc_s[mf][1] *= c0;
            oacc_s[mf][2] *= c1; oacc_s[mf][3] *= c1;
        }

        // ---- O += P V  (fp16 P x fp16 V single) + ones-column row sum ----
        #pragma unroll
        for (int ks = 0; ks < 4; ks++) {
            uint32_t pa[2][4];
            #pragma unroll
            for (int mf = 0; mf < 2; mf++) {
                pa[mf][0] = pp[mf][2 * ks][0];
                pa[mf][1] = pp[mf][2 * ks][1];
                pa[mf][2] = pp[mf][2 * ks + 1][0];
                pa[mf][3] = pp[mf][2 * ks + 1][1];
            }
            uint32_t vh[8][2];
            #pragma unroll
            for (int nf2 = 0; nf2 < 4; nf2++) {
                int row = nf2 * 16 + (lane & 7) + ((lane >> 4) << 3);
                int cu = ks * 2 + ((lane >> 3) & 1);
                uint32_t off = SWZ((uint32_t)(row * 128 + cu * 16));
                ldsm4(vh[2 * nf2][0], vh[2 * nf2][1], vh[2 * nf2 + 1][0], vh[2 * nf2 + 1][1],
                      sbase + VHs + off);
            }
            #pragma unroll
            for (int mf = 0; mf < 2; mf++) {
                #pragma unroll
                for (int nf = 0; nf < 8; nf++)
                    mma16816h(oacc[mf][nf], pa[mf], vh[nf]);
                mma16816h(oacc_s[mf], pa[mf], b_ones);
            }
        }
        __syncthreads();
    }

    // ---- epilogue: l from quad-leader lanes (col 64) ----
    #pragma unroll
    for (int mf = 0; mf < 2; mf++) {
        float l0 = __shfl_sync(0xffffffffu, oacc_s[mf][0], lane & 28);
        float l1 = __shfl_sync(0xffffffffu, oacc_s[mf][2], lane & 28);
        float inv0 = 1.0f / l0, inv1 = 1.0f / l1;
        int nr0 = n0 + wid * 32 + mf * 16 + (lane >> 2);
        #pragma unroll
        for (int nf = 0; nf < 8; nf++) {
            int col = h * 64 + nf * 8 + 2 * (lane & 3);
            uint32_t hp, lp;
            split_pair(oacc[mf][nf][0] * inv0, oacc[mf][nf][1] * inv0, hp, lp);
            size_t base0 = ((size_t)b * 1024 + nr0) * 512 + col;
            *(uint32_t*)&g_Ohi[base0] = hp;
            *(uint32_t*)&g_Olo[base0] = lp;
            split_pair(oacc[mf][nf][2] * inv1, oacc[mf][nf][3] * inv1, hp, lp);
            size_t base1 = ((size_t)b * 1024 + nr0 + 8) * 512 + col;
            *(uint32_t*)&g_Ohi[base1] = hp;
            *(uint32_t*)&g_Olo[base1] = lp;
        }
    }
}

// ---------------------------------------------------------------------------
extern "C" void kernel_launch(void* const* d_in, const int* in_sizes, int n_in,
                              void* d_out, int out_size) {
    const float* x    = (const float*)d_in[0];
    const float* qp   = (const float*)d_in[1];
    const float* kp   = (const float*)d_in[2];
    const float* vp   = (const float*)d_in[3];
    const float* wout = (const float*)d_in[4];
    float* out = (float*)d_out;

    cudaFuncSetAttribute(gemm_qkv, cudaFuncAttributeMaxDynamicSharedMemorySize, GEMM_SMEM);
    cudaFuncSetAttribute(gemm_out, cudaFuncAttributeMaxDynamicSharedMemorySize, GEMM_SMEM);
    cudaFuncSetAttribute(attn_mma, cudaFuncAttributeMaxDynamicSharedMemorySize, ATTN_SMEM);

    { dim3 g(32, 16, BSZ); dim3 blk(32, 8); conv_x<<<g, blk>>>(x); }
    prep_w<<<(640 * 512 + 512 * 512 + 255) / 256, 256>>>(qp, kp, vp, wout);

    { dim3 g(5, 16, BSZ); gemm_qkv<<<g, 128, GEMM_SMEM>>>(); }
    { dim3 g(8, NH, BSZ); attn_mma<<<g, 128, ATTN_SMEM>>>(); }
    { dim3 g(8, 8, BSZ); gemm_out<<<g, 128, GEMM_SMEM>>>(out); }
}

// round 16
// speedup vs baseline: 5.1927x; 1.0554x over previous
#include <cuda_runtime.h>
#include <cuda_bf16.h>
#include <cuda_fp16.h>
#include <cstdint>
#include <cstddef>
#include <math.h>

#define BSZ 8
#define NTOK 1024
#define NH 8

// ---------------------------------------------------------------------------
// Device scratch
// ---------------------------------------------------------------------------
__device__ __align__(16) __nv_bfloat16 g_rxh[BSZ * NTOK * 512];   // [b][n][d]
__device__ __align__(16) __nv_bfloat16 g_rxl[BSZ * NTOK * 512];
__device__ __align__(16) __nv_bfloat16 g_Wqh[640 * 512];          // [c][d] (Q pre-scaled 0.125*log2e)
__device__ __align__(16) __nv_bfloat16 g_Wql[640 * 512];
__device__ __align__(16) __half g_Ws16[512 * 512];                // [dout][c] fp16 single
__device__ __align__(16) __nv_bfloat16 g_Qh[BSZ * NTOK * 512];    // [b][n][hk] scaled
__device__ __align__(16) __nv_bfloat16 g_Ql[BSZ * NTOK * 512];
__device__ __align__(16) __nv_bfloat16 g_Kh[BSZ * NTOK * 64];     // [b][m][kd]
__device__ __align__(16) __nv_bfloat16 g_Kl[BSZ * NTOK * 64];
__device__ __align__(16) __half g_Vt[BSZ * 64 * NTOK];            // [b][v][m] fp16 single
__device__ __align__(16) __half g_Ohf[BSZ * NTOK * 512];          // [b][n][c] fp16 hi
__device__ __align__(16) __half g_Olf[BSZ * NTOK * 512];          // fp16 lo

// ---------------------------------------------------------------------------
// helpers
// ---------------------------------------------------------------------------
#define SWZ(x) ((x) ^ (((x) >> 3) & 0x70))

__device__ __forceinline__ uint32_t s2u(const void* p) {
    uint32_t a;
    asm("{ .reg .u64 t; cvta.to.shared.u64 t, %1; cvt.u32.u64 %0, t; }" : "=r"(a) : "l"(p));
    return a;
}
__device__ __forceinline__ void cpasync16(uint32_t dst, const void* src) {
    asm volatile("cp.async.cg.shared.global [%0], [%1], 16;" :: "r"(dst), "l"(src));
}
#define CP_COMMIT() asm volatile("cp.async.commit_group;")
#define CP_WAIT(n)  asm volatile("cp.async.wait_group %0;" :: "n"(n))

__device__ __forceinline__ void ldsm4(uint32_t& a, uint32_t& b, uint32_t& c, uint32_t& d,
                                      uint32_t addr) {
    asm volatile("ldmatrix.sync.aligned.m8n8.x4.shared.b16 {%0,%1,%2,%3}, [%4];"
                 : "=r"(a), "=r"(b), "=r"(c), "=r"(d) : "r"(addr));
}
__device__ __forceinline__ void mma16816(float* d, const uint32_t* a, const uint32_t* b) {
    asm volatile(
        "mma.sync.aligned.m16n8k16.row.col.f32.bf16.bf16.f32 "
        "{%0,%1,%2,%3}, {%4,%5,%6,%7}, {%8,%9}, {%0,%1,%2,%3};"
        : "+f"(d[0]), "+f"(d[1]), "+f"(d[2]), "+f"(d[3])
        : "r"(a[0]), "r"(a[1]), "r"(a[2]), "r"(a[3]), "r"(b[0]), "r"(b[1]));
}
__device__ __forceinline__ void mma16816h(float* d, const uint32_t* a, const uint32_t* b) {
    asm volatile(
        "mma.sync.aligned.m16n8k16.row.col.f32.f16.f16.f32 "
        "{%0,%1,%2,%3}, {%4,%5,%6,%7}, {%8,%9}, {%0,%1,%2,%3};"
        : "+f"(d[0]), "+f"(d[1]), "+f"(d[2]), "+f"(d[3])
        : "r"(a[0]), "r"(a[1]), "r"(a[2]), "r"(a[3]), "r"(b[0]), "r"(b[1]));
}
__device__ __forceinline__ float ex2(float x) {
    float r;
    asm("ex2.approx.f32 %0, %1;" : "=f"(r) : "f"(x));
    return r;
}
__device__ __forceinline__ uint32_t h2ex2(uint32_t x) {
    uint32_t r;
    asm("ex2.approx.f16x2 %0, %1;" : "=r"(r) : "r"(x));
    return r;
}
__device__ __forceinline__ void split2(float v, __nv_bfloat16& h, __nv_bfloat16& l) {
    h = __float2bfloat16(v);
    l = __float2bfloat16(v - __bfloat162float(h));
}
__device__ __forceinline__ uint32_t cvt2bf(float f0, float f1) {
    uint32_t r;
    asm("cvt.rn.bf16x2.f32 %0, %1, %2;" : "=r"(r) : "f"(f1), "f"(f0));
    return r;
}
__device__ __forceinline__ uint32_t cvt2h(float f0, float f1) {
    uint32_t r;
    asm("cvt.rn.f16x2.f32 %0, %1, %2;" : "=r"(r) : "f"(f1), "f"(f0));
    return r;
}
__device__ __forceinline__ void split_pair(float f0, float f1, uint32_t& hp, uint32_t& lp) {
    hp = cvt2bf(f0, f1);
    float h0 = __uint_as_float(hp << 16);
    float h1 = __uint_as_float(hp & 0xffff0000u);
    lp = cvt2bf(f0 - h0, f1 - h1);
}
// fp16 hi/lo split of a float pair (packed)
__device__ __forceinline__ void split_pair_h(float f0, float f1, uint32_t& hp, uint32_t& lp) {
    hp = cvt2h(f0, f1);
    __half2 hh = *reinterpret_cast<__half2*>(&hp);
    lp = cvt2h(f0 - __half2float(__low2half(hh)), f1 - __half2float(__high2half(hh)));
}

// ---------------------------------------------------------------------------
// prep kernels
// ---------------------------------------------------------------------------
__global__ void conv_x(const float* __restrict__ x) {
    __shared__ float t[32][33];
    const int b = blockIdx.z, d0 = blockIdx.y * 32, n0 = blockIdx.x * 32;
    const int txx = threadIdx.x, tyy = threadIdx.y;
    #pragma unroll
    for (int r = 0; r < 4; r++)
        t[tyy + r * 8][txx] = x[((size_t)b * 512 + d0 + tyy + r * 8) * 1024 + n0 + txx];
    __syncthreads();
    #pragma unroll
    for (int r = 0; r < 4; r++) {
        int n = n0 + tyy + r * 8;
        __nv_bfloat16 h, l;
        split2(t[txx][tyy + r * 8], h, l);
        size_t o = ((size_t)b * 1024 + n) * 512 + d0 + txx;
        g_rxh[o] = h; g_rxl[o] = l;
    }
}

// merged weight prep; Q rows scaled by 0.125 * log2(e); Wout -> single fp16
__global__ void prep_w(const float* __restrict__ qp, const float* __restrict__ kp,
                       const float* __restrict__ vp, const float* __restrict__ wout) {
    int idx = blockIdx.x * 256 + threadIdx.x;
    if (idx < 640 * 512) {
        int c = idx >> 9, d = idx & 511;
        float v;
        if (c < 512)      v = qp[c * 512 + d] * (0.125f * 1.4426950408889634f);
        else if (c < 576) v = kp[d * 64 + (c - 512)];
        else              v = vp[d * 64 + (c - 576)];
        split2(v, g_Wqh[idx], g_Wql[idx]);
    } else {
        int j = idx - 640 * 512;
        if (j < 512 * 512) g_Ws16[j] = __float2half_rn(wout[j]);
    }
}

// ---------------------------------------------------------------------------
// GEMM core (4-warp CTA, 64x128 tile, 2-stage cp.async, 2 CTAs/SM) — bf16 x3
// ---------------------------------------------------------------------------
#define GEMM_SMEM (2 * 49152)
#define STAGE_SZ  49152u

struct GemmAcc { float a[2][8][4]; };

template <typename Epi>
__device__ __forceinline__ void gemm_core(
    const __nv_bfloat16* Ahi, const __nv_bfloat16* Alo,
    const __nv_bfloat16* Bhi, const __nv_bfloat16* Blo,
    int K, Epi epi) {
    extern __shared__ char sm[];
    const uint32_t sbase = s2u(sm);
    const uint32_t OFF[4] = {0u, 8192u, 16384u, 32768u};

    const int tid = threadIdx.x, lane = tid & 31, wid = tid >> 5;
    const int wm = (wid >> 1) * 32, wn = (wid & 1) * 64;

    const __nv_bfloat16* gsrc[4] = {Ahi, Alo, Bhi, Blo};

    auto load_chunk = [&](int stage, int kc) {
        const uint32_t stbase = sbase + stage * STAGE_SZ;
        #pragma unroll
        for (int t = 0; t < 2; t++) {
            #pragma unroll
            for (int i = 0; i < 4; i++) {
                int c = tid + i * 128;
                int row = c >> 3, u = c & 7;
                cpasync16(stbase + OFF[t] + SWZ((uint32_t)(row * 128 + u * 16)),
                          gsrc[t] + (size_t)row * K + kc + u * 8);
            }
        }
        #pragma unroll
        for (int t = 2; t < 4; t++) {
            #pragma unroll
            for (int i = 0; i < 8; i++) {
                int c = tid + i * 128;
                int row = c >> 3, u = c & 7;
                cpasync16(stbase + OFF[t] + SWZ((uint32_t)(row * 128 + u * 16)),
                          gsrc[t] + (size_t)row * K + kc + u * 8);
            }
        }
        CP_COMMIT();
    };

    GemmAcc acc;
    #pragma unroll
    for (int i = 0; i < 2; i++)
        #pragma unroll
        for (int j = 0; j < 8; j++)
            #pragma unroll
            for (int e = 0; e < 4; e++) acc.a[i][j][e] = 0.f;

    const int nchunks = K >> 6;
    load_chunk(0, 0);
    for (int c = 0; c < nchunks; c++) {
        if (c + 1 < nchunks) { load_chunk((c + 1) & 1, (c + 1) << 6); CP_WAIT(1); }
        else                 { CP_WAIT(0); }
        __syncthreads();
        const uint32_t stb = sbase + (c & 1) * STAGE_SZ;

        #pragma unroll
        for (int ks = 0; ks < 4; ks++) {
            uint32_t ah[2][4], al[2][4], bh[8][2], bl[8][2];
            #pragma unroll
            for (int mf = 0; mf < 2; mf++) {
                int row = wm + mf * 16 + (lane & 15);
                int cu = ks * 2 + (lane >> 4);
                uint32_t off = SWZ((uint32_t)(row * 128 + cu * 16));
                ldsm4(ah[mf][0], ah[mf][1], ah[mf][2], ah[mf][3], stb + OFF[0] + off);
                ldsm4(al[mf][0], al[mf][1], al[mf][2], al[mf][3], stb + OFF[1] + off);
            }
            #pragma unroll
            for (int nf2 = 0; nf2 < 4; nf2++) {
                int row = wn + nf2 * 16 + (lane & 7) + ((lane >> 4) << 3);
                int cu = ks * 2 + ((lane >> 3) & 1);
                uint32_t off = SWZ((uint32_t)(row * 128 + cu * 16));
                ldsm4(bh[2 * nf2][0], bh[2 * nf2][1], bh[2 * nf2 + 1][0], bh[2 * nf2 + 1][1],
                      stb + OFF[2] + off);
                ldsm4(bl[2 * nf2][0], bl[2 * nf2][1], bl[2 * nf2 + 1][0], bl[2 * nf2 + 1][1],
                      stb + OFF[3] + off);
            }
            #pragma unroll
            for (int mf = 0; mf < 2; mf++)
                #pragma unroll
                for (int nf = 0; nf < 8; nf++) {
                    mma16816(acc.a[mf][nf], ah[mf], bh[nf]);
                    mma16816(acc.a[mf][nf], ah[mf], bl[nf]);
                    mma16816(acc.a[mf][nf], al[mf], bh[nf]);
                }
        }
        __syncthreads();
    }
    epi(acc, wm, wn, lane);
}

// epilogue functor: QKV split + routing (V -> single fp16)
struct QkvEpi {
    int b, mt, nt;
    __device__ void operator()(GemmAcc& acc, int wm, int wn, int lane) const {
        #pragma unroll
        for (int mf = 0; mf < 2; mf++) {
            int r0 = mt * 64 + wm + mf * 16 + (lane >> 2);
            #pragma unroll
            for (int nf = 0; nf < 8; nf++) {
                int col = nt * 128 + wn + nf * 8 + 2 * (lane & 3);
                const float* a = acc.a[mf][nf];
                if (nt < 4) {
                    uint32_t hp, lp;
                    split_pair(a[0], a[1], hp, lp);
                    size_t o0 = ((size_t)b * 1024 + r0) * 512 + col;
                    *(uint32_t*)&g_Qh[o0] = hp; *(uint32_t*)&g_Ql[o0] = lp;
                    split_pair(a[2], a[3], hp, lp);
                    size_t o1 = ((size_t)b * 1024 + r0 + 8) * 512 + col;
                    *(uint32_t*)&g_Qh[o1] = hp; *(uint32_t*)&g_Ql[o1] = lp;
                } else if (wn == 0) {
                    int kc = col - 512;
                    uint32_t hp, lp;
                    split_pair(a[0], a[1], hp, lp);
                    size_t o0 = ((size_t)b * 1024 + r0) * 64 + kc;
                    *(uint32_t*)&g_Kh[o0] = hp; *(uint32_t*)&g_Kl[o0] = lp;
                    split_pair(a[2], a[3], hp, lp);
                    size_t o1 = ((size_t)b * 1024 + r0 + 8) * 64 + kc;
                    *(uint32_t*)&g_Kh[o1] = hp; *(uint32_t*)&g_Kl[o1] = lp;
                } else {
                    int v0 = col - 576;
                    #pragma unroll
                    for (int e = 0; e < 4; e++) {
                        int vv = v0 + (e & 1);
                        int mm = r0 + (e >> 1) * 8;
                        size_t o = ((size_t)b * 64 + vv) * 1024 + mm;
                        g_Vt[o] = __float2half_rn(a[e]);
                    }
                }
            }
        }
    }
};

__global__ void __launch_bounds__(128)
gemm_qkv() {
    const int b = blockIdx.z, mt = blockIdx.y, nt = blockIdx.x;
    QkvEpi epi{b, mt, nt};
    gemm_core(
        g_rxh + ((size_t)b * 1024 + mt * 64) * 512,
        g_rxl + ((size_t)b * 1024 + mt * 64) * 512,
        g_Wqh + (size_t)nt * 128 * 512,
        g_Wql + (size_t)nt * 128 * 512,
        512, epi);
}

// ---------------------------------------------------------------------------
// gemm_out_f16: out[dout][n] = Ws16 (single fp16) x O (fp16 hi/lo), 2 terms.
// CTA 64(dout) x 128(n), 4 warps, 2-stage cp.async.
// stage: A 0 (8K) | Bh 8K (16K) | Bl 24K (16K) = 40K; 2 stages = 80K
// ---------------------------------------------------------------------------
#define OUT_SMEM (2 * 40960)
#define OUT_STAGE 40960u

__global__ void __launch_bounds__(128)
gemm_out_f16(float* __restrict__ D) {
    extern __shared__ char sm[];
    const uint32_t sbase = s2u(sm);
    const uint32_t OA = 0u, OBH = 8192u, OBL = 24576u;

    const int tid = threadIdx.x, lane = tid & 31, wid = tid >> 5;
    const int b = blockIdx.z, mt = blockIdx.y, nt = blockIdx.x;
    const int wm = (wid >> 1) * 32, wn = (wid & 1) * 64;

    const __half* Asrc = g_Ws16 + (size_t)mt * 64 * 512;
    const __half* Bh   = g_Ohf + ((size_t)b * 1024 + nt * 128) * 512;
    const __half* Bl   = g_Olf + ((size_t)b * 1024 + nt * 128) * 512;

    auto load_chunk = [&](int stage, int kc) {
        const uint32_t stb = sbase + stage * OUT_STAGE;
        #pragma unroll
        for (int i = 0; i < 4; i++) {
            int c = tid + i * 128;
            int row = c >> 3, u = c & 7;
            cpasync16(stb + OA + SWZ((uint32_t)(row * 128 + u * 16)),
                      Asrc + (size_t)row * 512 + kc + u * 8);
        }
        #pragma unroll
        for (int i = 0; i < 8; i++) {
            int c = tid + i * 128;
            int row = c >> 3, u = c & 7;
            uint32_t off = SWZ((uint32_t)(row * 128 + u * 16));
            cpasync16(stb + OBH + off, Bh + (size_t)row * 512 + kc + u * 8);
            cpasync16(stb + OBL + off, Bl + (size_t)row * 512 + kc + u * 8);
        }
        CP_COMMIT();
    };

    float acc[2][8][4];
    #pragma unroll
    for (int i = 0; i < 2; i++)
        #pragma unroll
        for (int j = 0; j < 8; j++)
            #pragma unroll
            for (int e = 0; e < 4; e++) acc[i][j][e] = 0.f;

    load_chunk(0, 0);
    for (int c = 0; c < 8; c++) {
        if (c + 1 < 8) { load_chunk((c + 1) & 1, (c + 1) << 6); CP_WAIT(1); }
        else           { CP_WAIT(0); }
        __syncthreads();
        const uint32_t stb = sbase + (c & 1) * OUT_STAGE;

        #pragma unroll
        for (int ks = 0; ks < 4; ks++) {
            uint32_t aa[2][4], bh16[8][2], bl16[8][2];
            #pragma unroll
            for (int mf = 0; mf < 2; mf++) {
                int row = wm + mf * 16 + (lane & 15);
                int cu = ks * 2 + (lane >> 4);
                uint32_t off = SWZ((uint32_t)(row * 128 + cu * 16));
                ldsm4(aa[mf][0], aa[mf][1], aa[mf][2], aa[mf][3], stb + OA + off);
            }
            #pragma unroll
            for (int nf2 = 0; nf2 < 4; nf2++) {
                int row = wn + nf2 * 16 + (lane & 7) + ((lane >> 4) << 3);
                int cu = ks * 2 + ((lane >> 3) & 1);
                uint32_t off = SWZ((uint32_t)(row * 128 + cu * 16));
                ldsm4(bh16[2 * nf2][0], bh16[2 * nf2][1], bh16[2 * nf2 + 1][0],
                      bh16[2 * nf2 + 1][1], stb + OBH + off);
                ldsm4(bl16[2 * nf2][0], bl16[2 * nf2][1], bl16[2 * nf2 + 1][0],
                      bl16[2 * nf2 + 1][1], stb + OBL + off);
            }
            #pragma unroll
            for (int mf = 0; mf < 2; mf++)
                #pragma unroll
                for (int nf = 0; nf < 8; nf++) {
                    mma16816h(acc[mf][nf], aa[mf], bh16[nf]);
                    mma16816h(acc[mf][nf], aa[mf], bl16[nf]);
                }
        }
        __syncthreads();
    }

    #pragma unroll
    for (int mf = 0; mf < 2; mf++) {
        int r0 = mt * 64 + wm + mf * 16 + (lane >> 2);
        #pragma unroll
        for (int nf = 0; nf < 8; nf++) {
            int col = nt * 128 + wn + nf * 8 + 2 * (lane & 3);
            *(float2*)(D + ((size_t)b * 512 + r0) * 1024 + col) =
                make_float2(acc[mf][nf][0], acc[mf][nf][1]);
            *(float2*)(D + ((size_t)b * 512 + r0 + 8) * 1024 + col) =
                make_float2(acc[mf][nf][2], acc[mf][nf][3]);
        }
    }
}

// ---------------------------------------------------------------------------
// HMMA flash attention (unchanged from R15 except O epilogue -> fp16 hi/lo)
// smem: Qh 0 | Ql 16K | stages 32K + s*24K: {Kh 0 | Kl 8K | Vh 16K} -> 80K
// ---------------------------------------------------------------------------
#define ATTN_SMEM 81920
#define KV_STAGE 24576u

__global__ void __launch_bounds__(128, 2)
attn_mma() {
    extern __shared__ char sm[];
    const uint32_t sbase = s2u(sm);
    const uint32_t QH = 0u, QL = 16384u, STG = 32768u;

    const int tid = threadIdx.x, lane = tid & 31, wid = tid >> 5;
    const int b = blockIdx.z, h = blockIdx.y, n0 = blockIdx.x * 128;
    const int phase = ((blockIdx.x + blockIdx.y) & 1) << 3;

    const __nv_bfloat16* Qhb = g_Qh + ((size_t)b * 1024 + n0) * 512 + h * 64;
    const __nv_bfloat16* Qlb = g_Ql + ((size_t)b * 1024 + n0) * 512 + h * 64;
    const __nv_bfloat16* Khb = g_Kh + (size_t)b * 1024 * 64;
    const __nv_bfloat16* Klb = g_Kl + (size_t)b * 1024 * 64;
    const __half* Vb = g_Vt + (size_t)b * 64 * 1024;

    uint32_t b_ones[2];
    b_ones[0] = b_ones[1] = ((lane >> 2) == 0) ? 0x3C003C00u : 0u;

    #pragma unroll
    for (int i = 0; i < 8; i++) {
        int c = tid + i * 128;
        int row = c >> 3, u = c & 7;
        uint32_t off = SWZ((uint32_t)(row * 128 + u * 16));
        cpasync16(sbase + QH + off, Qhb + (size_t)row * 512 + u * 8);
        cpasync16(sbase + QL + off, Qlb + (size_t)row * 512 + u * 8);
    }
    CP_COMMIT();

    auto load_kv = [&](int stage, int m0) {
        const uint32_t stb = sbase + STG + stage * KV_STAGE;
        #pragma unroll
        for (int i = 0; i < 4; i++) {
            int c = tid + i * 128;
            int row = c >> 3, u = c & 7;
            uint32_t off = SWZ((uint32_t)(row * 128 + u * 16));
            cpasync16(stb + off,          Khb + (size_t)(m0 + row) * 64 + u * 8);
            cpasync16(stb + 8192u + off,  Klb + (size_t)(m0 + row) * 64 + u * 8);
            cpasync16(stb + 16384u + off, Vb + (size_t)row * 1024 + m0 + u * 8);
        }
        CP_COMMIT();
    };

    load_kv(0, phase * 64);

    float m_i[2][2], oacc[2][8][4], oacc_s[2][4];
    #pragma unroll
    for (int mf = 0; mf < 2; mf++) {
        m_i[mf][0] = m_i[mf][1] = -1e30f;
        #pragma unroll
        for (int e = 0; e < 4; e++) oacc_s[mf][e] = 0.f;
        #pragma unroll
        for (int nf = 0; nf < 8; nf++)
            #pragma unroll
            for (int e = 0; e < 4; e++) oacc[mf][nf][e] = 0.f;
    }

    for (int ic = 0; ic < 16; ic++) {
        if (ic + 1 < 16) {
            load_kv((ic + 1) & 1, (((ic + 1) + phase) & 15) * 64);
            CP_WAIT(1);
        } else {
            CP_WAIT(0);
        }
        __syncthreads();
        const uint32_t KHs = STG + (uint32_t)(ic & 1) * KV_STAGE;
        const uint32_t KLs = KHs + 8192u, VHs = KHs + 16384u;

        float sacc[2][8][4];
        #pragma unroll
        for (int mf = 0; mf < 2; mf++)
            #pragma unroll
            for (int nf = 0; nf < 8; nf++)
                #pragma unroll
                for (int e = 0; e < 4; e++) sacc[mf][nf][e] = 0.f;

        #pragma unroll
        for (int ks = 0; ks < 4; ks++) {
            uint32_t qh[2][4], ql[2][4], bh[8][2], bl[8][2];
            #pragma unroll
            for (int mf = 0; mf < 2; mf++) {
                int row = wid * 32 + mf * 16 + (lane & 15);
                int cu = ks * 2 + (lane >> 4);
                uint32_t off = SWZ((uint32_t)(row * 128 + cu * 16));
                ldsm4(qh[mf][0], qh[mf][1], qh[mf][2], qh[mf][3], sbase + QH + off);
                ldsm4(ql[mf][0], ql[mf][1], ql[mf][2], ql[mf][3], sbase + QL + off);
            }
            #pragma unroll
            for (int nf2 = 0; nf2 < 4; nf2++) {
                int row = nf2 * 16 + (lane & 7) + ((lane >> 4) << 3);
                int cu = ks * 2 + ((lane >> 3) & 1);
                uint32_t off = SWZ((uint32_t)(row * 128 + cu * 16));
                ldsm4(bh[2 * nf2][0], bh[2 * nf2][1], bh[2 * nf2 + 1][0], bh[2 * nf2 + 1][1],
                      sbase + KHs + off);
                ldsm4(bl[2 * nf2][0], bl[2 * nf2][1], bl[2 * nf2 + 1][0], bl[2 * nf2 + 1][1],
                      sbase + KLs + off);
            }
            #pragma unroll
            for (int mf = 0; mf < 2; mf++)
                #pragma unroll
                for (int nf = 0; nf < 8; nf++) {
                    mma16816(sacc[mf][nf], qh[mf], bh[nf]);
                    mma16816(sacc[mf][nf], qh[mf], bl[nf]);
                    mma16816(sacc[mf][nf], ql[mf], bh[nf]);
                }
        }

        uint32_t pp[2][8][2];
        #pragma unroll
        for (int mf = 0; mf < 2; mf++) {
            float mx0 = -1e30f, mx1 = -1e30f;
            #pragma unroll
            for (int nf = 0; nf < 8; nf++) {
                mx0 = fmaxf(mx0, fmaxf(sacc[mf][nf][0], sacc[mf][nf][1]));
                mx1 = fmaxf(mx1, fmaxf(sacc[mf][nf][2], sacc[mf][nf][3]));
            }
            mx0 = fmaxf(mx0, __shfl_xor_sync(0xffffffffu, mx0, 1));
            mx0 = fmaxf(mx0, __shfl_xor_sync(0xffffffffu, mx0, 2));
            mx1 = fmaxf(mx1, __shfl_xor_sync(0xffffffffu, mx1, 1));
            mx1 = fmaxf(mx1, __shfl_xor_sync(0xffffffffu, mx1, 2));
            float mn0 = fmaxf(m_i[mf][0], mx0), mn1 = fmaxf(m_i[mf][1], mx1);
            float c0 = ex2(m_i[mf][0] - mn0), c1 = ex2(m_i[mf][1] - mn1);
            m_i[mf][0] = mn0; m_i[mf][1] = mn1;
            #pragma unroll
            for (int nf = 0; nf < 8; nf++) {
                pp[mf][nf][0] = h2ex2(cvt2h(sacc[mf][nf][0] - mn0, sacc[mf][nf][1] - mn0));
                pp[mf][nf][1] = h2ex2(cvt2h(sacc[mf][nf][2] - mn1, sacc[mf][nf][3] - mn1));
                oacc[mf][nf][0] *= c0; oacc[mf][nf][1] *= c0;
                oacc[mf][nf][2] *= c1; oacc[mf][nf][3] *= c1;
            }
            oacc_s[mf][0] *= c0; oacc_s[mf][1] *= c0;
            oacc_s[mf][2] *= c1; oacc_s[mf][3] *= c1;
        }

        #pragma unroll
        for (int ks = 0; ks < 4; ks++) {
            uint32_t pa[2][4];
            #pragma unroll
            for (int mf = 0; mf < 2; mf++) {
                pa[mf][0] = pp[mf][2 * ks][0];
                pa[mf][1] = pp[mf][2 * ks][1];
                pa[mf][2] = pp[mf][2 * ks + 1][0];
                pa[mf][3] = pp[mf][2 * ks + 1][1];
            }
            uint32_t vh[8][2];
            #pragma unroll
            for (int nf2 = 0; nf2 < 4; nf2++) {
                int row = nf2 * 16 + (lane & 7) + ((lane >> 4) << 3);
                int cu = ks * 2 + ((lane >> 3) & 1);
                uint32_t off = SWZ((uint32_t)(row * 128 + cu * 16));
                ldsm4(vh[2 * nf2][0], vh[2 * nf2][1], vh[2 * nf2 + 1][0], vh[2 * nf2 + 1][1],
                      sbase + VHs + off);
            }
            #pragma unroll
            for (int mf = 0; mf < 2; mf++) {
                #pragma unroll
                for (int nf = 0; nf < 8; nf++)
                    mma16816h(oacc[mf][nf], pa[mf], vh[nf]);
                mma16816h(oacc_s[mf], pa[mf], b_ones);
            }
        }
        __syncthreads();
    }

    // ---- epilogue: normalize, split fp16 hi/lo ----
    #pragma unroll
    for (int mf = 0; mf < 2; mf++) {
        float l0 = __shfl_sync(0xffffffffu, oacc_s[mf][0], lane & 28);
        float l1 = __shfl_sync(0xffffffffu, oacc_s[mf][2], lane & 28);
        float inv0 = 1.0f / l0, inv1 = 1.0f / l1;
        int nr0 = n0 + wid * 32 + mf * 16 + (lane >> 2);
        #pragma unroll
        for (int nf = 0; nf < 8; nf++) {
            int col = h * 64 + nf * 8 + 2 * (lane & 3);
            uint32_t hp, lp;
            split_pair_h(oacc[mf][nf][0] * inv0, oacc[mf][nf][1] * inv0, hp, lp);
            size_t base0 = ((size_t)b * 1024 + nr0) * 512 + col;
            *(uint32_t*)&g_Ohf[base0] = hp;
            *(uint32_t*)&g_Olf[base0] = lp;
            split_pair_h(oacc[mf][nf][2] * inv1, oacc[mf][nf][3] * inv1, hp, lp);
            size_t base1 = ((size_t)b * 1024 + nr0 + 8) * 512 + col;
            *(uint32_t*)&g_Ohf[base1] = hp;
            *(uint32_t*)&g_Olf[base1] = lp;
        }
    }
}

// ---------------------------------------------------------------------------
extern "C" void kernel_launch(void* const* d_in, const int* in_sizes, int n_in,
                              void* d_out, int out_size) {
    const float* x    = (const float*)d_in[0];
    const float* qp   = (const float*)d_in[1];
    const float* kp   = (const float*)d_in[2];
    const float* vp   = (const float*)d_in[3];
    const float* wout = (const float*)d_in[4];
    float* out = (float*)d_out;

    cudaFuncSetAttribute(gemm_qkv, cudaFuncAttributeMaxDynamicSharedMemorySize, GEMM_SMEM);
    cudaFuncSetAttribute(gemm_out_f16, cudaFuncAttributeMaxDynamicSharedMemorySize, OUT_SMEM);
    cudaFuncSetAttribute(attn_mma, cudaFuncAttributeMaxDynamicSharedMemorySize, ATTN_SMEM);

    { dim3 g(32, 16, BSZ); dim3 blk(32, 8); conv_x<<<g, blk>>>(x); }
    prep_w<<<(640 * 512 + 512 * 512 + 255) / 256, 256>>>(qp, kp, vp, wout);

    { dim3 g(5, 16, BSZ); gemm_qkv<<<g, 128, GEMM_SMEM>>>(); }
    { dim3 g(8, NH, BSZ); attn_mma<<<g, 128, ATTN_SMEM>>>(); }
    { dim3 g(8, 8, BSZ); gemm_out_f16<<<g, 128, OUT_SMEM>>>(out); }
}